// round 4
// baseline (speedup 1.0000x reference)
#include <cuda_runtime.h>
#include <math.h>

#define BN 2
#define CI_T 8

// ---------------- static scratch (no allocations allowed) ----------------
// batched over 6 = 3 streams x BN; largest stage 6*64*512*512 floats
__device__ float g_bufA[6 * 64 * 512 * 512];
__device__ float g_bufB[6 * 64 * 512 * 512];
__device__ float g_comp[BN * 3 * 512 * 512];
__device__ float g_wT[1734336];   // transposed weights, all 7 layers

#define SZ1 (BN * 64 * 256 * 256)
#define SZ2 (BN * 128 * 128 * 128)
#define SZ3 (BN * 256 * 64 * 64)
__device__ float g_p1[3][SZ1];   // [gt, out, comp]
__device__ float g_p2[3][SZ2];
__device__ float g_p3[3][SZ3];

// 0: hole, 1: valid, 2: perc (raw), 3: style_out (scaled), 4: style_comp (scaled)
__device__ double g_acc[8];

// ---------------- f32x2 helpers ----------------
__device__ __forceinline__ unsigned long long pk2(float a, float b) {
    unsigned long long r;
    asm("mov.b64 %0, {%1, %2};" : "=l"(r) : "f"(a), "f"(b));
    return r;
}
__device__ __forceinline__ unsigned long long fma_x2(unsigned long long a,
                                                     unsigned long long b,
                                                     unsigned long long c) {
    unsigned long long d;
    asm("fma.rn.f32x2 %0, %1, %2, %3;" : "=l"(d) : "l"(a), "l"(b), "l"(c));
    return d;
}
__device__ __forceinline__ void upk(unsigned long long v, float& lo, float& hi) {
    asm("mov.b64 {%0, %1}, %2;" : "=f"(lo), "=f"(hi) : "l"(v));
}

__device__ __forceinline__ void warp_atomic(double* dst, float v) {
    #pragma unroll
    for (int o = 16; o > 0; o >>= 1) v += __shfl_down_sync(0xffffffffu, v, o);
    if ((threadIdx.x & 31) == 0) atomicAdd(dst, (double)v);
}

// ---------------- kernels ----------------
__global__ void zero_acc_k() {
    if (threadIdx.x < 8) g_acc[threadIdx.x] = 0.0;
}

// weight transpose: wT[(ci*9+k)*Cout + co] = w[((co*Cin)+ci)*9 + k]
__global__ void wtrans_k(const float* __restrict__ w, float* __restrict__ wT,
                         int Cin, int Cout) {
    int n = Cin * Cout * 9;
    for (int i = blockIdx.x * blockDim.x + threadIdx.x; i < n;
         i += gridDim.x * blockDim.x) {
        int co = i % Cout;
        int t = i / Cout;
        int k = t % 9;
        int ci = t / 9;
        wT[i] = w[((size_t)co * Cin + ci) * 9 + k];
    }
}

// icomp + hole/valid L1 partial sums
__global__ void comp_l1_k(const float* __restrict__ igt,
                          const float* __restrict__ iout,
                          const float* __restrict__ mask) {
    const int n = BN * 3 * 512 * 512;
    const int hw = 512 * 512;
    float h = 0.f, v = 0.f;
    for (int i = blockIdx.x * blockDim.x + threadIdx.x; i < n;
         i += gridDim.x * blockDim.x) {
        int pix = i % hw;
        int b = (i / hw) / 3;
        float m = (mask[b * hw + pix] != 0.0f) ? 1.0f : 0.0f;
        float gt = igt[i], ot = iout[i];
        float d = ot - gt;
        h += fabsf((1.0f - m) * d);
        v += fabsf(m * d);
        g_comp[i] = (m == 1.0f) ? gt : ot;
    }
    warp_atomic(&g_acc[0], h);
    warp_atomic(&g_acc[1], v);
}

// 3x3 SAME conv + bias + relu, FFMA2 (packed co-pairs), 8-ci staging rounds.
// block 256: 64 pixel-threads (2x2 px each) x 4 channel groups (8 co each).
// grid: (W/16, H/16, 6 * Cout/32). be = blockIdx.z / nCoT in 0..5:
// stream s = be>>1 (0 gt, 1 out, 2 comp), batch b = be&1.
__global__ __launch_bounds__(256, 3) void conv3x3_relu_k(
    const float* __restrict__ in0, const float* __restrict__ in1,
    const float* __restrict__ in2, int multisrc,
    const float* __restrict__ wT, const float* __restrict__ bias,
    float* __restrict__ out, int Cin, int Cout, int Hh, int Ww) {
    __shared__ __align__(16) float s_in[CI_T][18][20];
    __shared__ __align__(16) float s_w[CI_T][9][32];

    const int nCoT = Cout >> 5;
    const int coT = blockIdx.z % nCoT;
    const int be = blockIdx.z / nCoT;
    const int x0 = blockIdx.x * 16, y0 = blockIdx.y * 16;
    const int tid = threadIdx.x;
    const int p = tid & 63;
    const int g = tid >> 6;
    const int px = (p & 7) * 2, py = (p >> 3) * 2;
    const int g8 = g * 8;
    const size_t HW = (size_t)Hh * Ww;

    const float* inB;
    if (multisrc) {
        int s = be >> 1;
        const float* sp = (s == 0) ? in0 : ((s == 1) ? in1 : in2);
        inB = sp + (size_t)(be & 1) * Cin * HW;
    } else {
        inB = in0 + (size_t)be * Cin * HW;
    }

    unsigned long long acc[4][4];   // [co-pair][pixel]
    #pragma unroll
    for (int c = 0; c < 4; c++)
        #pragma unroll
        for (int q = 0; q < 4; q++) acc[c][q] = 0ull;

    const int rounds = (Cin + CI_T - 1) / CI_T;
    for (int r = 0; r < rounds; r++) {
        const int c0 = r * CI_T;
        // stage input tile (zero-padded at image border and ci >= Cin)
        for (int idx = tid; idx < CI_T * 324; idx += 256) {
            int q = idx / 324, rr = idx - q * 324;
            int iy = rr / 18, ix = rr - iy * 18;
            int ci = c0 + q;
            int gy = y0 + iy - 1, gx = x0 + ix - 1;
            float v = 0.f;
            if (ci < Cin && gy >= 0 && gy < Hh && gx >= 0 && gx < Ww)
                v = inB[(size_t)ci * HW + gy * Ww + gx];
            s_in[q][iy][ix] = v;
        }
        // stage weights (coalesced from transposed layout)
        for (int idx = tid; idx < CI_T * 288; idx += 256) {
            int co = idx & 31;
            int t = idx >> 5;
            int k = t % 9, q = t / 9;
            int ci = c0 + q;
            float v = 0.f;
            if (ci < Cin) v = wT[((size_t)ci * 9 + k) * Cout + coT * 32 + co];
            s_w[q][k][co] = v;
        }
        __syncthreads();

        #pragma unroll 2
        for (int q = 0; q < CI_T; q++) {
            unsigned long long xx[4][4];
            #pragma unroll
            for (int dy = 0; dy < 4; dy++) {
                float2 a = *(const float2*)&s_in[q][py + dy][px];
                float2 b = *(const float2*)&s_in[q][py + dy][px + 2];
                xx[dy][0] = pk2(a.x, a.x);
                xx[dy][1] = pk2(a.y, a.y);
                xx[dy][2] = pk2(b.x, b.x);
                xx[dy][3] = pk2(b.y, b.y);
            }
            #pragma unroll
            for (int ky = 0; ky < 3; ky++)
                #pragma unroll
                for (int kx = 0; kx < 3; kx++) {
                    const int k = ky * 3 + kx;
                    float2 wa = *(const float2*)&s_w[q][k][g8];
                    float2 wb = *(const float2*)&s_w[q][k][g8 + 2];
                    float2 wc = *(const float2*)&s_w[q][k][g8 + 4];
                    float2 wd = *(const float2*)&s_w[q][k][g8 + 6];
                    unsigned long long w0 = pk2(wa.x, wa.y);
                    unsigned long long w1 = pk2(wb.x, wb.y);
                    unsigned long long w2 = pk2(wc.x, wc.y);
                    unsigned long long w3 = pk2(wd.x, wd.y);
                    #pragma unroll
                    for (int sy = 0; sy < 2; sy++)
                        #pragma unroll
                        for (int sx = 0; sx < 2; sx++) {
                            unsigned long long xf = xx[sy + ky][sx + kx];
                            const int pid = sy * 2 + sx;
                            acc[0][pid] = fma_x2(xf, w0, acc[0][pid]);
                            acc[1][pid] = fma_x2(xf, w1, acc[1][pid]);
                            acc[2][pid] = fma_x2(xf, w2, acc[2][pid]);
                            acc[3][pid] = fma_x2(xf, w3, acc[3][pid]);
                        }
                }
        }
        __syncthreads();
    }

    #pragma unroll
    for (int cp = 0; cp < 4; cp++) {
        int co = coT * 32 + g8 + cp * 2;
        float b0 = bias[co], b1 = bias[co + 1];
        float* o0 = out + ((size_t)be * Cout + co) * HW;
        float* o1 = o0 + HW;
        #pragma unroll
        for (int sy = 0; sy < 2; sy++)
            #pragma unroll
            for (int sx = 0; sx < 2; sx++) {
                float lo, hi;
                upk(acc[cp][sy * 2 + sx], lo, hi);
                int ofs = (y0 + py + sy) * Ww + (x0 + px + sx);
                o0[ofs] = fmaxf(lo + b0, 0.f);
                o1[ofs] = fmaxf(hi + b1, 0.f);
            }
    }
}

// 2x2 maxpool, stride 2, batched over all (stream,b,c) planes.
__global__ void maxpool2_k(const float* __restrict__ in, float* __restrict__ out,
                           int total, int Ho, int Wo) {
    for (int i = blockIdx.x * blockDim.x + threadIdx.x; i < total;
         i += gridDim.x * blockDim.x) {
        int x = i % Wo;
        int t = i / Wo;
        int y = t % Ho;
        int bc = t / Ho;
        const float* pin = in + ((size_t)bc * 2 * Ho + 2 * y) * (2 * Wo) + 2 * x;
        float v = fmaxf(fmaxf(pin[0], pin[1]),
                        fmaxf(pin[2 * Wo], pin[2 * Wo + 1]));
        out[i] = v;
    }
}

// perceptual: sum |out-gt| + |comp-gt| -> g_acc[2]
__global__ void perc_sum_k(const float* __restrict__ aout,
                           const float* __restrict__ agt,
                           const float* __restrict__ acomp, int n) {
    float s = 0.f;
    for (int i = blockIdx.x * blockDim.x + threadIdx.x; i < n;
         i += gridDim.x * blockDim.x) {
        float g = agt[i];
        s += fabsf(aout[i] - g) + fabsf(acomp[i] - g);
    }
    warp_atomic(&g_acc[2], s);
}

// style Gram-difference, 32x32 Gram tile per block, 3 streams fused.
__global__ __launch_bounds__(256) void style_k(
    const float* __restrict__ Xout, const float* __restrict__ Xgt,
    const float* __restrict__ Xcomp, int HHs, int WWs, double scale) {
    __shared__ float sh[6][32][33];
    const int bc = blockIdx.z;
    const size_t off = (size_t)bc * HHs * WWs;
    const float* p0 = Xout + off;
    const float* p1 = Xgt + off;
    const float* p2 = Xcomp + off;
    const int v0 = blockIdx.x * 32, w0 = blockIdx.y * 32;
    const int tx = threadIdx.x & 31, ty = threadIdx.x >> 5;

    float aO[4] = {0, 0, 0, 0}, aG[4] = {0, 0, 0, 0}, aC[4] = {0, 0, 0, 0};

    for (int h0 = 0; h0 < HHs; h0 += 32) {
        for (int e = threadIdx.x; e < 1024; e += 256) {
            int hh = e >> 5, cc = e & 31;
            int rw = (h0 + hh) * WWs;
            sh[0][hh][cc] = p0[rw + w0 + cc];
            sh[1][hh][cc] = p0[rw + v0 + cc];
            sh[2][hh][cc] = p1[rw + w0 + cc];
            sh[3][hh][cc] = p1[rw + v0 + cc];
            sh[4][hh][cc] = p2[rw + w0 + cc];
            sh[5][hh][cc] = p2[rw + v0 + cc];
        }
        __syncthreads();
        #pragma unroll 4
        for (int hh = 0; hh < 32; hh++) {
            float vO = sh[1][hh][tx], vG = sh[3][hh][tx], vC = sh[5][hh][tx];
            #pragma unroll
            for (int j = 0; j < 4; j++) {
                int wl = ty + j * 8;
                aO[j] += sh[0][hh][wl] * vO;
                aG[j] += sh[2][hh][wl] * vG;
                aC[j] += sh[4][hh][wl] * vC;
            }
        }
        __syncthreads();
    }

    float sO = 0.f, sC = 0.f;
    #pragma unroll
    for (int j = 0; j < 4; j++) {
        sO += fabsf(aO[j] - aG[j]);
        sC += fabsf(aC[j] - aG[j]);
    }
    #pragma unroll
    for (int o = 16; o > 0; o >>= 1) {
        sO += __shfl_down_sync(0xffffffffu, sO, o);
        sC += __shfl_down_sync(0xffffffffu, sC, o);
    }
    if ((threadIdx.x & 31) == 0) {
        atomicAdd(&g_acc[3], scale * (double)sO);
        atomicAdd(&g_acc[4], scale * (double)sC);
    }
}

__global__ void finalize_k(float* out) {
    if (threadIdx.x == 0 && blockIdx.x == 0) {
        const double N = 3.0 * 512.0 * 512.0 * (double)BN;   // 1572864
        const double Nigt = (double)SZ1;                     // 8388608
        double l = (double)BN * g_acc[0] / N   // l_hole (faithful factor B)
                 + g_acc[1] / N                // l_valid
                 + g_acc[2] / Nigt             // l_perc (always /prod(p1 shape))
                 + g_acc[3]                    // l_style_out (pre-scaled)
                 + g_acc[4];                   // l_style_comp (pre-scaled)
        out[0] = (float)l;
    }
}

// ---------------- host launcher ----------------
extern "C" void kernel_launch(void* const* d_in, const int* in_sizes, int n_in,
                              void* d_out, int out_size) {
    (void)in_sizes; (void)n_in; (void)out_size;
    const float* igt  = (const float*)d_in[0];
    const float* iout = (const float*)d_in[1];
    const float* mask = (const float*)d_in[2];
    const float* w[7];
    const float* bb[7];
    for (int i = 0; i < 7; i++) {
        w[i]  = (const float*)d_in[3 + 2 * i];
        bb[i] = (const float*)d_in[4 + 2 * i];
    }

    float *bufA, *bufB, *comp, *p1b, *p2b, *p3b, *wTb;
    cudaGetSymbolAddress((void**)&bufA, g_bufA);
    cudaGetSymbolAddress((void**)&bufB, g_bufB);
    cudaGetSymbolAddress((void**)&comp, g_comp);
    cudaGetSymbolAddress((void**)&p1b, g_p1);
    cudaGetSymbolAddress((void**)&p2b, g_p2);
    cudaGetSymbolAddress((void**)&p3b, g_p3);
    cudaGetSymbolAddress((void**)&wTb, g_wT);

    // weight transpose offsets
    const int cins[7]  = {3, 64, 64, 128, 128, 256, 256};
    const int couts[7] = {64, 64, 128, 128, 256, 256, 256};
    float* wT[7];
    size_t ofs = 0;
    for (int i = 0; i < 7; i++) {
        wT[i] = wTb + ofs;
        ofs += (size_t)cins[i] * couts[i] * 9;
    }

    float* P1[3] = {p1b, p1b + SZ1, p1b + 2 * (size_t)SZ1};
    float* P2[3] = {p2b, p2b + SZ2, p2b + 2 * (size_t)SZ2};
    float* P3[3] = {p3b, p3b + SZ3, p3b + 2 * (size_t)SZ3};

    zero_acc_k<<<1, 32>>>();
    for (int i = 0; i < 7; i++)
        wtrans_k<<<256, 256>>>(w[i], wT[i], cins[i], couts[i]);
    comp_l1_k<<<1024, 256>>>(igt, iout, mask);

    // batched convs over 6 = 3 streams x BN
    conv3x3_relu_k<<<dim3(32, 32, 6 * 2), 256>>>(igt, iout, comp, 1, wT[0], bb[0],
                                                 bufA, 3, 64, 512, 512);
    conv3x3_relu_k<<<dim3(32, 32, 6 * 2), 256>>>(bufA, 0, 0, 0, wT[1], bb[1],
                                                 bufB, 64, 64, 512, 512);
    maxpool2_k<<<8192, 256>>>(bufB, p1b, 3 * SZ1, 256, 256);
    conv3x3_relu_k<<<dim3(16, 16, 6 * 4), 256>>>(p1b, 0, 0, 0, wT[2], bb[2],
                                                 bufA, 64, 128, 256, 256);
    conv3x3_relu_k<<<dim3(16, 16, 6 * 4), 256>>>(bufA, 0, 0, 0, wT[3], bb[3],
                                                 bufB, 128, 128, 256, 256);
    maxpool2_k<<<4096, 256>>>(bufB, p2b, 3 * SZ2, 128, 128);
    conv3x3_relu_k<<<dim3(8, 8, 6 * 8), 256>>>(p2b, 0, 0, 0, wT[4], bb[4],
                                               bufA, 128, 256, 128, 128);
    conv3x3_relu_k<<<dim3(8, 8, 6 * 8), 256>>>(bufA, 0, 0, 0, wT[5], bb[5],
                                               bufB, 256, 256, 128, 128);
    conv3x3_relu_k<<<dim3(8, 8, 6 * 8), 256>>>(bufB, 0, 0, 0, wT[6], bb[6],
                                               bufA, 256, 256, 128, 128);
    maxpool2_k<<<2048, 256>>>(bufA, p3b, 3 * SZ3, 64, 64);

    perc_sum_k<<<4096, 256>>>(P1[1], P1[0], P1[2], SZ1);
    perc_sum_k<<<2048, 256>>>(P2[1], P2[0], P2[2], SZ2);
    perc_sum_k<<<1024, 256>>>(P3[1], P3[0], P3[2], SZ3);

    // scale = Kp / C^2 = 1/(C*H*W) / C^2
    style_k<<<dim3(8, 8, BN * 64), 256>>>(P1[1], P1[0], P1[2], 256, 256,
                                          1.0 / (4194304.0 * 4096.0));
    style_k<<<dim3(4, 4, BN * 128), 256>>>(P2[1], P2[0], P2[2], 128, 128,
                                           1.0 / (2097152.0 * 16384.0));
    style_k<<<dim3(2, 2, BN * 256), 256>>>(P3[1], P3[0], P3[2], 64, 64,
                                           1.0 / (1048576.0 * 65536.0));

    finalize_k<<<1, 32>>>((float*)d_out);
}

// round 5
// speedup vs baseline: 1.2990x; 1.2990x over previous
#include <cuda_runtime.h>
#include <math.h>
#include <stdint.h>

#define BN 2
#define CI_T 8

// ---------------- static scratch (no allocations allowed) ----------------
__device__ float g_bufA[6 * 64 * 512 * 512];
__device__ float g_bufB[6 * 64 * 512 * 512];
__device__ float g_comp[BN * 3 * 512 * 512];
__device__ float g_wT[1734336];   // transposed weights, all 7 layers

#define SZ1 (BN * 64 * 256 * 256)
#define SZ2 (BN * 128 * 128 * 128)
#define SZ3 (BN * 256 * 64 * 64)
__device__ float g_p1[3][SZ1];
__device__ float g_p2[3][SZ2];
__device__ float g_p3[3][SZ3];

__device__ double g_acc[8];

// ---------------- helpers ----------------
__device__ __forceinline__ unsigned long long pk2(float a, float b) {
    unsigned long long r;
    asm("mov.b64 %0, {%1, %2};" : "=l"(r) : "f"(a), "f"(b));
    return r;
}
__device__ __forceinline__ unsigned long long fma_x2(unsigned long long a,
                                                     unsigned long long b,
                                                     unsigned long long c) {
    unsigned long long d;
    asm("fma.rn.f32x2 %0, %1, %2, %3;" : "=l"(d) : "l"(a), "l"(b), "l"(c));
    return d;
}
__device__ __forceinline__ void upk(unsigned long long v, float& lo, float& hi) {
    asm("mov.b64 {%0, %1}, %2;" : "=f"(lo), "=f"(hi) : "l"(v));
}
__device__ __forceinline__ float to_tf32(float x) {
    uint32_t u;
    asm("cvt.rna.tf32.f32 %0, %1;" : "=r"(u) : "f"(x));
    return __uint_as_float(u);
}
__device__ __forceinline__ void mma_tf32(float* c, const uint32_t* a,
                                         uint32_t b0, uint32_t b1) {
    asm volatile(
        "mma.sync.aligned.m16n8k8.row.col.f32.tf32.tf32.f32 "
        "{%0,%1,%2,%3}, {%4,%5,%6,%7}, {%8,%9}, {%0,%1,%2,%3};"
        : "+f"(c[0]), "+f"(c[1]), "+f"(c[2]), "+f"(c[3])
        : "r"(a[0]), "r"(a[1]), "r"(a[2]), "r"(a[3]), "r"(b0), "r"(b1));
}

__device__ __forceinline__ void warp_atomic(double* dst, float v) {
    #pragma unroll
    for (int o = 16; o > 0; o >>= 1) v += __shfl_down_sync(0xffffffffu, v, o);
    if ((threadIdx.x & 31) == 0) atomicAdd(dst, (double)v);
}

// ---------------- kernels ----------------
__global__ void zero_acc_k() {
    if (threadIdx.x < 8) g_acc[threadIdx.x] = 0.0;
}

// weight transpose (+ optional tf32 pre-round):
// wT[(ci*9+k)*Cout + co] = w[((co*Cin)+ci)*9 + k]
__global__ void wtrans_k(const float* __restrict__ w, float* __restrict__ wT,
                         int Cin, int Cout, int do_round) {
    int n = Cin * Cout * 9;
    for (int i = blockIdx.x * blockDim.x + threadIdx.x; i < n;
         i += gridDim.x * blockDim.x) {
        int co = i % Cout;
        int t = i / Cout;
        int k = t % 9;
        int ci = t / 9;
        float v = w[((size_t)co * Cin + ci) * 9 + k];
        wT[i] = do_round ? to_tf32(v) : v;
    }
}

// icomp + hole/valid L1 partial sums
__global__ void comp_l1_k(const float* __restrict__ igt,
                          const float* __restrict__ iout,
                          const float* __restrict__ mask) {
    const int n = BN * 3 * 512 * 512;
    const int hw = 512 * 512;
    float h = 0.f, v = 0.f;
    for (int i = blockIdx.x * blockDim.x + threadIdx.x; i < n;
         i += gridDim.x * blockDim.x) {
        int pix = i % hw;
        int b = (i / hw) / 3;
        float m = (mask[b * hw + pix] != 0.0f) ? 1.0f : 0.0f;
        float gt = igt[i], ot = iout[i];
        float d = ot - gt;
        h += fabsf((1.0f - m) * d);
        v += fabsf(m * d);
        g_comp[i] = (m == 1.0f) ? gt : ot;
    }
    warp_atomic(&g_acc[0], h);
    warp_atomic(&g_acc[1], v);
}

// ---------- FFMA2 conv (layer 1 only: Cin=3, multisrc) ----------
__global__ __launch_bounds__(256, 3) void conv3x3_relu_k(
    const float* __restrict__ in0, const float* __restrict__ in1,
    const float* __restrict__ in2, int multisrc,
    const float* __restrict__ wT, const float* __restrict__ bias,
    float* __restrict__ out, int Cin, int Cout, int Hh, int Ww) {
    __shared__ __align__(16) float s_in[CI_T][18][20];
    __shared__ __align__(16) float s_w[CI_T][9][32];

    const int nCoT = Cout >> 5;
    const int coT = blockIdx.z % nCoT;
    const int be = blockIdx.z / nCoT;
    const int x0 = blockIdx.x * 16, y0 = blockIdx.y * 16;
    const int tid = threadIdx.x;
    const int p = tid & 63;
    const int g = tid >> 6;
    const int px = (p & 7) * 2, py = (p >> 3) * 2;
    const int g8 = g * 8;
    const size_t HW = (size_t)Hh * Ww;

    const float* inB;
    if (multisrc) {
        int s = be >> 1;
        const float* sp = (s == 0) ? in0 : ((s == 1) ? in1 : in2);
        inB = sp + (size_t)(be & 1) * Cin * HW;
    } else {
        inB = in0 + (size_t)be * Cin * HW;
    }

    unsigned long long acc[4][4];
    #pragma unroll
    for (int c = 0; c < 4; c++)
        #pragma unroll
        for (int q = 0; q < 4; q++) acc[c][q] = 0ull;

    const int rounds = (Cin + CI_T - 1) / CI_T;
    for (int r = 0; r < rounds; r++) {
        const int c0 = r * CI_T;
        for (int idx = tid; idx < CI_T * 324; idx += 256) {
            int q = idx / 324, rr = idx - q * 324;
            int iy = rr / 18, ix = rr - iy * 18;
            int ci = c0 + q;
            int gy = y0 + iy - 1, gx = x0 + ix - 1;
            float v = 0.f;
            if (ci < Cin && gy >= 0 && gy < Hh && gx >= 0 && gx < Ww)
                v = inB[(size_t)ci * HW + gy * Ww + gx];
            s_in[q][iy][ix] = v;
        }
        for (int idx = tid; idx < CI_T * 288; idx += 256) {
            int co = idx & 31;
            int t = idx >> 5;
            int k = t % 9, q = t / 9;
            int ci = c0 + q;
            float v = 0.f;
            if (ci < Cin) v = wT[((size_t)ci * 9 + k) * Cout + coT * 32 + co];
            s_w[q][k][co] = v;
        }
        __syncthreads();

        #pragma unroll 2
        for (int q = 0; q < CI_T; q++) {
            unsigned long long xx[4][4];
            #pragma unroll
            for (int dy = 0; dy < 4; dy++) {
                float2 a = *(const float2*)&s_in[q][py + dy][px];
                float2 b = *(const float2*)&s_in[q][py + dy][px + 2];
                xx[dy][0] = pk2(a.x, a.x);
                xx[dy][1] = pk2(a.y, a.y);
                xx[dy][2] = pk2(b.x, b.x);
                xx[dy][3] = pk2(b.y, b.y);
            }
            #pragma unroll
            for (int ky = 0; ky < 3; ky++)
                #pragma unroll
                for (int kx = 0; kx < 3; kx++) {
                    const int k = ky * 3 + kx;
                    float2 wa = *(const float2*)&s_w[q][k][g8];
                    float2 wb = *(const float2*)&s_w[q][k][g8 + 2];
                    float2 wc = *(const float2*)&s_w[q][k][g8 + 4];
                    float2 wd = *(const float2*)&s_w[q][k][g8 + 6];
                    unsigned long long w0 = pk2(wa.x, wa.y);
                    unsigned long long w1 = pk2(wb.x, wb.y);
                    unsigned long long w2 = pk2(wc.x, wc.y);
                    unsigned long long w3 = pk2(wd.x, wd.y);
                    #pragma unroll
                    for (int sy = 0; sy < 2; sy++)
                        #pragma unroll
                        for (int sx = 0; sx < 2; sx++) {
                            unsigned long long xf = xx[sy + ky][sx + kx];
                            const int pid = sy * 2 + sx;
                            acc[0][pid] = fma_x2(xf, w0, acc[0][pid]);
                            acc[1][pid] = fma_x2(xf, w1, acc[1][pid]);
                            acc[2][pid] = fma_x2(xf, w2, acc[2][pid]);
                            acc[3][pid] = fma_x2(xf, w3, acc[3][pid]);
                        }
                }
        }
        __syncthreads();
    }

    #pragma unroll
    for (int cp = 0; cp < 4; cp++) {
        int co = coT * 32 + g8 + cp * 2;
        float b0 = bias[co], b1 = bias[co + 1];
        float* o0 = out + ((size_t)be * Cout + co) * HW;
        float* o1 = o0 + HW;
        #pragma unroll
        for (int sy = 0; sy < 2; sy++)
            #pragma unroll
            for (int sx = 0; sx < 2; sx++) {
                float lo, hi;
                upk(acc[cp][sy * 2 + sx], lo, hi);
                int ofs = (y0 + py + sy) * Ww + (x0 + px + sx);
                o0[ofs] = fmaxf(lo + b0, 0.f);
                o1[ofs] = fmaxf(hi + b1, 0.f);
            }
    }
}

// ---------- tf32 mma.sync implicit-GEMM conv (layers 2-7; Cin % 8 == 0) ----------
// block: 256 thr = 8 warps; tile 64 co x (8 rows x 16 cols) px.
// warp: 32 co x 32 px (2 rows of 16). K order: (tap, ci) with ci-pair interleave
// so each mma k-pair (j, j+4) maps to adjacent ci (2j, 2j+1) -> LDS.64.
// grid: (W/16, H/8, 6 * Cout/64)
__global__ __launch_bounds__(256, 2) void conv_mma_k(
    const float* __restrict__ in, const float* __restrict__ wT,
    const float* __restrict__ bias, float* __restrict__ out,
    int Cin, int Cout, int Hh, int Ww) {
    __shared__ __align__(16) float s_x[10][18][10];   // [yy][xx][ci pad 10]
    __shared__ __align__(16) float s_w[9][64][10];    // [tap][co][ci pad 10]

    const int nCoT = Cout >> 6;
    const int coT = blockIdx.z % nCoT;
    const int be = blockIdx.z / nCoT;
    const int x0 = blockIdx.x * 16, y0 = blockIdx.y * 8;
    const int tid = threadIdx.x;
    const int wid = tid >> 5, lane = tid & 31;
    const int warp_m = wid >> 2, warp_n = wid & 3;
    const int g = lane >> 2, tg = lane & 3;
    const size_t HW = (size_t)Hh * Ww;

    const float* inB = in + (size_t)be * Cin * HW;

    float acc[2][4][4];
    #pragma unroll
    for (int mf = 0; mf < 2; mf++)
        #pragma unroll
        for (int nf = 0; nf < 4; nf++)
            #pragma unroll
            for (int q = 0; q < 4; q++) acc[mf][nf][q] = 0.f;

    const int rounds = Cin >> 3;
    for (int r = 0; r < rounds; r++) {
        const int ci0 = r * 8;
        // stage input 8ci x 10x18 (transposed to ci-innermost), tf32-rounded
        for (int idx = tid; idx < 1440; idx += 256) {
            int ci = idx / 180, e = idx - ci * 180;
            int yy = e / 18, xx = e - yy * 18;
            int gy = y0 + yy - 1, gx = x0 + xx - 1;
            float v = 0.f;
            if (gy >= 0 && gy < Hh && gx >= 0 && gx < Ww)
                v = inB[(size_t)(ci0 + ci) * HW + gy * Ww + gx];
            s_x[yy][xx][ci] = to_tf32(v);
        }
        // stage weights 9 taps x 64 co x 8 ci (pre-rounded in wtrans)
        for (int idx = tid; idx < 4608; idx += 256) {
            int co = idx & 63;
            int t2 = idx >> 6;           // 0..71
            int t = t2 >> 3, ci = t2 & 7;
            s_w[t][co][ci] =
                wT[((size_t)(ci0 + ci) * 9 + t) * Cout + coT * 64 + co];
        }
        __syncthreads();

        #pragma unroll
        for (int t = 0; t < 9; t++) {
            const int dy = t / 3, dx = t - dy * 3;
            uint32_t a[2][4];
            #pragma unroll
            for (int mf = 0; mf < 2; mf++) {
                int row = warp_m * 32 + mf * 16 + g;
                float2 lo = *(const float2*)&s_w[t][row][2 * tg];
                float2 hi = *(const float2*)&s_w[t][row + 8][2 * tg];
                a[mf][0] = __float_as_uint(lo.x);
                a[mf][2] = __float_as_uint(lo.y);
                a[mf][1] = __float_as_uint(hi.x);
                a[mf][3] = __float_as_uint(hi.y);
            }
            #pragma unroll
            for (int nf = 0; nf < 4; nf++) {
                int yy = 2 * warp_n + (nf >> 1) + dy;
                int xx = (nf & 1) * 8 + g + dx;
                float2 bv = *(const float2*)&s_x[yy][xx][2 * tg];
                uint32_t b0 = __float_as_uint(bv.x);
                uint32_t b1 = __float_as_uint(bv.y);
                mma_tf32(acc[0][nf], a[0], b0, b1);
                mma_tf32(acc[1][nf], a[1], b0, b1);
            }
        }
        __syncthreads();
    }

    // epilogue: bias + relu, float2 stores (cols 2tg, 2tg+1 adjacent)
    #pragma unroll
    for (int mf = 0; mf < 2; mf++) {
        int r0 = coT * 64 + warp_m * 32 + mf * 16 + g;
        int r1 = r0 + 8;
        float b0 = bias[r0], b1 = bias[r1];
        float* o0 = out + ((size_t)be * Cout + r0) * HW;
        float* o1 = out + ((size_t)be * Cout + r1) * HW;
        #pragma unroll
        for (int nf = 0; nf < 4; nf++) {
            int y = y0 + 2 * warp_n + (nf >> 1);
            int x = x0 + (nf & 1) * 8 + 2 * tg;
            float2 v0, v1;
            v0.x = fmaxf(acc[mf][nf][0] + b0, 0.f);
            v0.y = fmaxf(acc[mf][nf][1] + b0, 0.f);
            v1.x = fmaxf(acc[mf][nf][2] + b1, 0.f);
            v1.y = fmaxf(acc[mf][nf][3] + b1, 0.f);
            *(float2*)&o0[(size_t)y * Ww + x] = v0;
            *(float2*)&o1[(size_t)y * Ww + x] = v1;
        }
    }
}

// 2x2 maxpool, stride 2
__global__ void maxpool2_k(const float* __restrict__ in, float* __restrict__ out,
                           int total, int Ho, int Wo) {
    for (int i = blockIdx.x * blockDim.x + threadIdx.x; i < total;
         i += gridDim.x * blockDim.x) {
        int x = i % Wo;
        int t = i / Wo;
        int y = t % Ho;
        int bc = t / Ho;
        const float* pin = in + ((size_t)bc * 2 * Ho + 2 * y) * (2 * Wo) + 2 * x;
        float v = fmaxf(fmaxf(pin[0], pin[1]),
                        fmaxf(pin[2 * Wo], pin[2 * Wo + 1]));
        out[i] = v;
    }
}

// perceptual: sum |out-gt| + |comp-gt| -> g_acc[2]
__global__ void perc_sum_k(const float* __restrict__ aout,
                           const float* __restrict__ agt,
                           const float* __restrict__ acomp, int n) {
    float s = 0.f;
    for (int i = blockIdx.x * blockDim.x + threadIdx.x; i < n;
         i += gridDim.x * blockDim.x) {
        float g = agt[i];
        s += fabsf(aout[i] - g) + fabsf(acomp[i] - g);
    }
    warp_atomic(&g_acc[2], s);
}

// style Gram-difference, 32x32 Gram tile per block, 3 streams fused
__global__ __launch_bounds__(256) void style_k(
    const float* __restrict__ Xout, const float* __restrict__ Xgt,
    const float* __restrict__ Xcomp, int HHs, int WWs, double scale) {
    __shared__ float sh[6][32][33];
    const int bc = blockIdx.z;
    const size_t off = (size_t)bc * HHs * WWs;
    const float* p0 = Xout + off;
    const float* p1 = Xgt + off;
    const float* p2 = Xcomp + off;
    const int v0 = blockIdx.x * 32, w0 = blockIdx.y * 32;
    const int tx = threadIdx.x & 31, ty = threadIdx.x >> 5;

    float aO[4] = {0, 0, 0, 0}, aG[4] = {0, 0, 0, 0}, aC[4] = {0, 0, 0, 0};

    for (int h0 = 0; h0 < HHs; h0 += 32) {
        for (int e = threadIdx.x; e < 1024; e += 256) {
            int hh = e >> 5, cc = e & 31;
            int rw = (h0 + hh) * WWs;
            sh[0][hh][cc] = p0[rw + w0 + cc];
            sh[1][hh][cc] = p0[rw + v0 + cc];
            sh[2][hh][cc] = p1[rw + w0 + cc];
            sh[3][hh][cc] = p1[rw + v0 + cc];
            sh[4][hh][cc] = p2[rw + w0 + cc];
            sh[5][hh][cc] = p2[rw + v0 + cc];
        }
        __syncthreads();
        #pragma unroll 4
        for (int hh = 0; hh < 32; hh++) {
            float vO = sh[1][hh][tx], vG = sh[3][hh][tx], vC = sh[5][hh][tx];
            #pragma unroll
            for (int j = 0; j < 4; j++) {
                int wl = ty + j * 8;
                aO[j] += sh[0][hh][wl] * vO;
                aG[j] += sh[2][hh][wl] * vG;
                aC[j] += sh[4][hh][wl] * vC;
            }
        }
        __syncthreads();
    }

    float sO = 0.f, sC = 0.f;
    #pragma unroll
    for (int j = 0; j < 4; j++) {
        sO += fabsf(aO[j] - aG[j]);
        sC += fabsf(aC[j] - aG[j]);
    }
    #pragma unroll
    for (int o = 16; o > 0; o >>= 1) {
        sO += __shfl_down_sync(0xffffffffu, sO, o);
        sC += __shfl_down_sync(0xffffffffu, sC, o);
    }
    if ((threadIdx.x & 31) == 0) {
        atomicAdd(&g_acc[3], scale * (double)sO);
        atomicAdd(&g_acc[4], scale * (double)sC);
    }
}

__global__ void finalize_k(float* out) {
    if (threadIdx.x == 0 && blockIdx.x == 0) {
        const double N = 3.0 * 512.0 * 512.0 * (double)BN;
        const double Nigt = (double)SZ1;
        double l = (double)BN * g_acc[0] / N
                 + g_acc[1] / N
                 + g_acc[2] / Nigt
                 + g_acc[3]
                 + g_acc[4];
        out[0] = (float)l;
    }
}

// ---------------- host launcher ----------------
extern "C" void kernel_launch(void* const* d_in, const int* in_sizes, int n_in,
                              void* d_out, int out_size) {
    (void)in_sizes; (void)n_in; (void)out_size;
    const float* igt  = (const float*)d_in[0];
    const float* iout = (const float*)d_in[1];
    const float* mask = (const float*)d_in[2];
    const float* w[7];
    const float* bb[7];
    for (int i = 0; i < 7; i++) {
        w[i]  = (const float*)d_in[3 + 2 * i];
        bb[i] = (const float*)d_in[4 + 2 * i];
    }

    float *bufA, *bufB, *comp, *p1b, *p2b, *p3b, *wTb;
    cudaGetSymbolAddress((void**)&bufA, g_bufA);
    cudaGetSymbolAddress((void**)&bufB, g_bufB);
    cudaGetSymbolAddress((void**)&comp, g_comp);
    cudaGetSymbolAddress((void**)&p1b, g_p1);
    cudaGetSymbolAddress((void**)&p2b, g_p2);
    cudaGetSymbolAddress((void**)&p3b, g_p3);
    cudaGetSymbolAddress((void**)&wTb, g_wT);

    const int cins[7]  = {3, 64, 64, 128, 128, 256, 256};
    const int couts[7] = {64, 64, 128, 128, 256, 256, 256};
    float* wT[7];
    size_t ofs = 0;
    for (int i = 0; i < 7; i++) {
        wT[i] = wTb + ofs;
        ofs += (size_t)cins[i] * couts[i] * 9;
    }

    float* P1[3] = {p1b, p1b + SZ1, p1b + 2 * (size_t)SZ1};
    float* P2[3] = {p2b, p2b + SZ2, p2b + 2 * (size_t)SZ2};
    float* P3[3] = {p3b, p3b + SZ3, p3b + 2 * (size_t)SZ3};

    zero_acc_k<<<1, 32>>>();
    // layer 0 stays fp32 (FFMA2); layers 1-6 pre-rounded to tf32
    for (int i = 0; i < 7; i++)
        wtrans_k<<<256, 256>>>(w[i], wT[i], cins[i], couts[i], i > 0 ? 1 : 0);
    comp_l1_k<<<1024, 256>>>(igt, iout, mask);

    // layer 1: FFMA2 (Cin=3, multisrc)
    conv3x3_relu_k<<<dim3(32, 32, 6 * 2), 256>>>(igt, iout, comp, 1, wT[0], bb[0],
                                                 bufA, 3, 64, 512, 512);
    // layers 2-7: tf32 mma implicit GEMM
    conv_mma_k<<<dim3(32, 64, 6 * 1), 256>>>(bufA, wT[1], bb[1], bufB, 64, 64, 512, 512);
    maxpool2_k<<<8192, 256>>>(bufB, p1b, 3 * SZ1, 256, 256);
    conv_mma_k<<<dim3(16, 32, 6 * 2), 256>>>(p1b, wT[2], bb[2], bufA, 64, 128, 256, 256);
    conv_mma_k<<<dim3(16, 32, 6 * 2), 256>>>(bufA, wT[3], bb[3], bufB, 128, 128, 256, 256);
    maxpool2_k<<<4096, 256>>>(bufB, p2b, 3 * SZ2, 128, 128);
    conv_mma_k<<<dim3(8, 16, 6 * 4), 256>>>(p2b, wT[4], bb[4], bufA, 128, 256, 128, 128);
    conv_mma_k<<<dim3(8, 16, 6 * 4), 256>>>(bufA, wT[5], bb[5], bufB, 256, 256, 128, 128);
    conv_mma_k<<<dim3(8, 16, 6 * 4), 256>>>(bufB, wT[6], bb[6], bufA, 256, 256, 128, 128);
    maxpool2_k<<<2048, 256>>>(bufA, p3b, 3 * SZ3, 64, 64);

    perc_sum_k<<<4096, 256>>>(P1[1], P1[0], P1[2], SZ1);
    perc_sum_k<<<2048, 256>>>(P2[1], P2[0], P2[2], SZ2);
    perc_sum_k<<<1024, 256>>>(P3[1], P3[0], P3[2], SZ3);

    style_k<<<dim3(8, 8, BN * 64), 256>>>(P1[1], P1[0], P1[2], 256, 256,
                                          1.0 / (4194304.0 * 4096.0));
    style_k<<<dim3(4, 4, BN * 128), 256>>>(P2[1], P2[0], P2[2], 128, 128,
                                           1.0 / (2097152.0 * 16384.0));
    style_k<<<dim3(2, 2, BN * 256), 256>>>(P3[1], P3[0], P3[2], 64, 64,
                                           1.0 / (1048576.0 * 65536.0));

    finalize_k<<<1, 32>>>((float*)d_out);
}

// round 7
// speedup vs baseline: 3.1166x; 2.3992x over previous
#include <cuda_runtime.h>
#include <cuda_fp16.h>
#include <math.h>
#include <stdint.h>

#define BN 2
#define CI_T 8

// ---------------- static scratch (no allocations allowed) ----------------
__device__ __half g_hA[6 * 64 * 512 * 512];      // NHWC fp16 ping
__device__ __half g_hB[6 * 64 * 512 * 512];      // NHWC fp16 pong
__device__ __half g_hp[6 * 64 * 256 * 256];      // NHWC fp16 pooled
__device__ float  g_comp[BN * 3 * 512 * 512];
__device__ float  g_wT1[1728];                   // layer-1 weights (fp32)
__device__ __half g_w16[1732608];                // layers 2-7 weights fp16 [t][co][ci]

#define SZ1 (BN * 64 * 256 * 256)
#define SZ2 (BN * 128 * 128 * 128)
#define SZ3 (BN * 256 * 64 * 64)
__device__ float g_p1[3][SZ1];   // [gt, out, comp] fp32 NCHW pools
__device__ float g_p2[3][SZ2];
__device__ float g_p3[3][SZ3];

__device__ double g_acc[8];

// ---------------- helpers ----------------
__device__ __forceinline__ unsigned long long pk2(float a, float b) {
    unsigned long long r;
    asm("mov.b64 %0, {%1, %2};" : "=l"(r) : "f"(a), "f"(b));
    return r;
}
__device__ __forceinline__ unsigned long long fma_x2(unsigned long long a,
                                                     unsigned long long b,
                                                     unsigned long long c) {
    unsigned long long d;
    asm("fma.rn.f32x2 %0, %1, %2, %3;" : "=l"(d) : "l"(a), "l"(b), "l"(c));
    return d;
}
__device__ __forceinline__ void upk(unsigned long long v, float& lo, float& hi) {
    asm("mov.b64 {%0, %1}, %2;" : "=f"(lo), "=f"(hi) : "l"(v));
}
__device__ __forceinline__ uint32_t smem_u32(const void* p) {
    return (uint32_t)__cvta_generic_to_shared(p);
}
__device__ __forceinline__ void ldm4(uint32_t* r, uint32_t addr) {
    asm volatile("ldmatrix.sync.aligned.m8n8.x4.shared.b16 {%0,%1,%2,%3}, [%4];"
                 : "=r"(r[0]), "=r"(r[1]), "=r"(r[2]), "=r"(r[3]) : "r"(addr));
}
__device__ __forceinline__ void mma16(float* c, const uint32_t* a,
                                      uint32_t b0, uint32_t b1) {
    asm volatile(
        "mma.sync.aligned.m16n8k16.row.col.f32.f16.f16.f32 "
        "{%0,%1,%2,%3}, {%4,%5,%6,%7}, {%8,%9}, {%0,%1,%2,%3};"
        : "+f"(c[0]), "+f"(c[1]), "+f"(c[2]), "+f"(c[3])
        : "r"(a[0]), "r"(a[1]), "r"(a[2]), "r"(a[3]), "r"(b0), "r"(b1));
}
__device__ __forceinline__ void warp_atomic(double* dst, float v) {
    #pragma unroll
    for (int o = 16; o > 0; o >>= 1) v += __shfl_down_sync(0xffffffffu, v, o);
    if ((threadIdx.x & 31) == 0) atomicAdd(dst, (double)v);
}

// ---------------- kernels ----------------
__global__ void zero_acc_k() {
    if (threadIdx.x < 8) g_acc[threadIdx.x] = 0.0;
}

// layer-1 weight transpose (fp32): wT[(ci*9+k)*Cout + co]
__global__ void wtrans1_k(const float* __restrict__ w, float* __restrict__ wT,
                          int Cin, int Cout) {
    int n = Cin * Cout * 9;
    for (int i = blockIdx.x * blockDim.x + threadIdx.x; i < n;
         i += gridDim.x * blockDim.x) {
        int co = i % Cout;
        int t = i / Cout;
        int k = t % 9;
        int ci = t / 9;
        wT[i] = w[((size_t)co * Cin + ci) * 9 + k];
    }
}

// layers 2-7 weight repack to fp16: w16[((t*Cout)+co)*Cin + ci]
__global__ void wtrans16_k(const float* __restrict__ w, __half* __restrict__ w16,
                           int Cin, int Cout) {
    int n = 9 * Cin * Cout;
    for (int i = blockIdx.x * blockDim.x + threadIdx.x; i < n;
         i += gridDim.x * blockDim.x) {
        int ci = i % Cin;
        int row = i / Cin;
        int co = row % Cout;
        int t = row / Cout;
        w16[i] = __float2half_rn(w[((size_t)co * Cin + ci) * 9 + t]);
    }
}

// icomp + hole/valid L1 partial sums
__global__ void comp_l1_k(const float* __restrict__ igt,
                          const float* __restrict__ iout,
                          const float* __restrict__ mask) {
    const int n = BN * 3 * 512 * 512;
    const int hw = 512 * 512;
    float h = 0.f, v = 0.f;
    for (int i = blockIdx.x * blockDim.x + threadIdx.x; i < n;
         i += gridDim.x * blockDim.x) {
        int pix = i % hw;
        int b = (i / hw) / 3;
        float m = (mask[b * hw + pix] != 0.0f) ? 1.0f : 0.0f;
        float gt = igt[i], ot = iout[i];
        float d = ot - gt;
        h += fabsf((1.0f - m) * d);
        v += fabsf(m * d);
        g_comp[i] = (m == 1.0f) ? gt : ot;
    }
    warp_atomic(&g_acc[0], h);
    warp_atomic(&g_acc[1], v);
}

// ---------- FFMA2 conv layer 1 (Cin=3, fp32 NCHW in, fp16 NHWC out) ----------
__global__ __launch_bounds__(256, 3) void conv1_k(
    const float* __restrict__ in0, const float* __restrict__ in1,
    const float* __restrict__ in2,
    const float* __restrict__ wT, const float* __restrict__ bias,
    __half* __restrict__ out, int Cin, int Cout, int Hh, int Ww) {
    __shared__ __align__(16) float s_in[CI_T][18][20];
    __shared__ __align__(16) float s_w[CI_T][9][32];

    const int nCoT = Cout >> 5;
    const int coT = blockIdx.z % nCoT;
    const int be = blockIdx.z / nCoT;
    const int x0 = blockIdx.x * 16, y0 = blockIdx.y * 16;
    const int tid = threadIdx.x;
    const int p = tid & 63;
    const int g = tid >> 6;
    const int px = (p & 7) * 2, py = (p >> 3) * 2;
    const int g8 = g * 8;
    const size_t HW = (size_t)Hh * Ww;

    int s = be >> 1;
    const float* sp = (s == 0) ? in0 : ((s == 1) ? in1 : in2);
    const float* inB = sp + (size_t)(be & 1) * Cin * HW;

    unsigned long long acc[4][4];
    #pragma unroll
    for (int c = 0; c < 4; c++)
        #pragma unroll
        for (int q = 0; q < 4; q++) acc[c][q] = 0ull;

    const int rounds = (Cin + CI_T - 1) / CI_T;
    for (int r = 0; r < rounds; r++) {
        const int c0 = r * CI_T;
        for (int idx = tid; idx < CI_T * 324; idx += 256) {
            int q = idx / 324, rr = idx - q * 324;
            int iy = rr / 18, ix = rr - iy * 18;
            int ci = c0 + q;
            int gy = y0 + iy - 1, gx = x0 + ix - 1;
            float v = 0.f;
            if (ci < Cin && gy >= 0 && gy < Hh && gx >= 0 && gx < Ww)
                v = inB[(size_t)ci * HW + gy * Ww + gx];
            s_in[q][iy][ix] = v;
        }
        for (int idx = tid; idx < CI_T * 288; idx += 256) {
            int co = idx & 31;
            int t = idx >> 5;
            int k = t % 9, q = t / 9;
            int ci = c0 + q;
            float v = 0.f;
            if (ci < Cin) v = wT[((size_t)ci * 9 + k) * Cout + coT * 32 + co];
            s_w[q][k][co] = v;
        }
        __syncthreads();

        #pragma unroll 2
        for (int q = 0; q < CI_T; q++) {
            unsigned long long xx[4][4];
            #pragma unroll
            for (int dy = 0; dy < 4; dy++) {
                float2 a = *(const float2*)&s_in[q][py + dy][px];
                float2 b = *(const float2*)&s_in[q][py + dy][px + 2];
                xx[dy][0] = pk2(a.x, a.x);
                xx[dy][1] = pk2(a.y, a.y);
                xx[dy][2] = pk2(b.x, b.x);
                xx[dy][3] = pk2(b.y, b.y);
            }
            #pragma unroll
            for (int ky = 0; ky < 3; ky++)
                #pragma unroll
                for (int kx = 0; kx < 3; kx++) {
                    const int k = ky * 3 + kx;
                    float2 wa = *(const float2*)&s_w[q][k][g8];
                    float2 wb = *(const float2*)&s_w[q][k][g8 + 2];
                    float2 wc = *(const float2*)&s_w[q][k][g8 + 4];
                    float2 wd = *(const float2*)&s_w[q][k][g8 + 6];
                    unsigned long long w0 = pk2(wa.x, wa.y);
                    unsigned long long w1 = pk2(wb.x, wb.y);
                    unsigned long long w2 = pk2(wc.x, wc.y);
                    unsigned long long w3 = pk2(wd.x, wd.y);
                    #pragma unroll
                    for (int sy = 0; sy < 2; sy++)
                        #pragma unroll
                        for (int sx = 0; sx < 2; sx++) {
                            unsigned long long xf = xx[sy + ky][sx + kx];
                            const int pid = sy * 2 + sx;
                            acc[0][pid] = fma_x2(xf, w0, acc[0][pid]);
                            acc[1][pid] = fma_x2(xf, w1, acc[1][pid]);
                            acc[2][pid] = fma_x2(xf, w2, acc[2][pid]);
                            acc[3][pid] = fma_x2(xf, w3, acc[3][pid]);
                        }
                }
        }
        __syncthreads();
    }

    // epilogue: NHWC fp16, 8 consecutive co per thread -> one STG.128 per pixel
    const int coBase = coT * 32 + g8;
    float bb[8];
    #pragma unroll
    for (int j = 0; j < 8; j++) bb[j] = bias[coBase + j];
    #pragma unroll
    for (int sy = 0; sy < 2; sy++)
        #pragma unroll
        for (int sx = 0; sx < 2; sx++) {
            int y = y0 + py + sy, x = x0 + px + sx;
            const int pid = sy * 2 + sx;
            union { uint4 u; __half2 h[4]; } pk;
            #pragma unroll
            for (int cp = 0; cp < 4; cp++) {
                float lo, hi;
                upk(acc[cp][pid], lo, hi);
                pk.h[cp] = __floats2half2_rn(fmaxf(lo + bb[2 * cp], 0.f),
                                             fmaxf(hi + bb[2 * cp + 1], 0.f));
            }
            *(uint4*)&out[((size_t)(be * Hh + y) * Ww + x) * Cout + coBase] = pk.u;
        }
}

// ---------- fp16 mma implicit-GEMM conv (layers 2-7, NHWC fp16) ----------
// block 256 = 8 warps (2 warp_m x 4 warp_n); tile 64co x (8y x 16x) px.
// k16 per mma = 16 input channels of one tap; rounds over Cin/16, 9 taps.
#define SW_H (9 * 64 * 24)    // 13824 halves
#define SX_H (10 * 18 * 24)   // 4320 halves
__global__ __launch_bounds__(256, 2) void conv_mma16_k(
    const __half* __restrict__ in, const __half* __restrict__ w16,
    const float* __restrict__ bias, __half* __restrict__ out,
    int Cin, int Cout, int Hh, int Ww) {
    __shared__ __align__(16) __half sh[SW_H + SX_H];
    __half* s_w = sh;           // [t*64+co][24]
    __half* s_x = sh + SW_H;    // [yy*18+xx][24]

    const int nCoT = Cout >> 6;
    const int coT = blockIdx.z % nCoT;
    const int be = blockIdx.z / nCoT;
    const int x0 = blockIdx.x * 16, y0 = blockIdx.y * 8;
    const int tid = threadIdx.x, wid = tid >> 5, lane = tid & 31;
    const int warp_m = wid >> 2, warp_n = wid & 3;
    const int g = lane >> 2, tg = lane & 3;

    float acc[2][4][4];
    #pragma unroll
    for (int mf = 0; mf < 2; mf++)
        #pragma unroll
        for (int nf = 0; nf < 4; nf++)
            #pragma unroll
            for (int q = 0; q < 4; q++) acc[mf][nf][q] = 0.f;

    // ldmatrix per-lane addresses (byte offsets)
    const int l7 = lane & 7, qd = lane >> 3;
    const int a_r = l7 + (qd & 1) * 8;
    const int a_k = (qd >> 1) * 8;
    const uint32_t swb = smem_u32(s_w), sxb = smem_u32(s_x);
    uint32_t aAddr[2];
    #pragma unroll
    for (int mf = 0; mf < 2; mf++)
        aAddr[mf] = swb + (uint32_t)(((warp_m * 32 + mf * 16 + a_r) * 24 + a_k) * 2);
    const int b_xx = ((qd >> 1) & 1) * 8 + l7;
    const int b_k = (qd & 1) * 8;
    const uint32_t bAddr0 =
        sxb + (uint32_t)((((2 * warp_n) * 18 + b_xx) * 24 + b_k) * 2);
    const uint32_t bAddr1 = bAddr0 + 18 * 24 * 2;

    const int rounds = Cin >> 4;
    for (int r = 0; r < rounds; r++) {
        const int ci0 = r << 4;
        // stage activations: 180 cells x 32B (zero halo)
        for (int idx = tid; idx < 360; idx += 256) {
            int cell = idx >> 1, hh = idx & 1;
            int yy = cell / 18, xx = cell - yy * 18;
            int gy = y0 + yy - 1, gx = x0 + xx - 1;
            uint4 v = make_uint4(0, 0, 0, 0);
            if (gy >= 0 && gy < Hh && gx >= 0 && gx < Ww)
                v = *(const uint4*)&in[((size_t)(be * Hh + gy) * Ww + gx) * Cin +
                                       ci0 + hh * 8];
            *(uint4*)&s_x[cell * 24 + hh * 8] = v;
        }
        // stage weights: 576 rows x 32B
        for (int idx = tid; idx < 1152; idx += 256) {
            int row = idx >> 1, hh = idx & 1;
            int t = row >> 6, co = row & 63;
            uint4 v = *(const uint4*)&w16[((size_t)t * Cout + coT * 64 + co) * Cin +
                                          ci0 + hh * 8];
            *(uint4*)&s_w[row * 24 + hh * 8] = v;
        }
        __syncthreads();

        #pragma unroll
        for (int t = 0; t < 9; t++) {
            const int dy = t / 3, dx = t - dy * 3;
            const uint32_t toff = (uint32_t)((dy * 18 + dx) * 48);
            uint32_t a0[4], a1[4], b0[4], b1[4];
            ldm4(a0, aAddr[0] + (uint32_t)(t * 3072));
            ldm4(a1, aAddr[1] + (uint32_t)(t * 3072));
            ldm4(b0, bAddr0 + toff);
            ldm4(b1, bAddr1 + toff);
            mma16(acc[0][0], a0, b0[0], b0[1]);
            mma16(acc[1][0], a1, b0[0], b0[1]);
            mma16(acc[0][1], a0, b0[2], b0[3]);
            mma16(acc[1][1], a1, b0[2], b0[3]);
            mma16(acc[0][2], a0, b1[0], b1[1]);
            mma16(acc[1][2], a1, b1[0], b1[1]);
            mma16(acc[0][3], a0, b1[2], b1[3]);
            mma16(acc[1][3], a1, b1[2], b1[3]);
        }
        __syncthreads();
    }

    // epilogue: bias+relu -> smem [co][130] -> NHWC fp16 stores
    __half* s_out = sh;
    #pragma unroll
    for (int mf = 0; mf < 2; mf++) {
        int r0 = warp_m * 32 + mf * 16 + g;
        int r1 = r0 + 8;
        float bb0 = bias[coT * 64 + r0];
        float bb1 = bias[coT * 64 + r1];
        #pragma unroll
        for (int nf = 0; nf < 4; nf++) {
            int px0 = (2 * warp_n + (nf >> 1)) * 16 + (nf & 1) * 8 + 2 * tg;
            __half2 v0 = __floats2half2_rn(fmaxf(acc[mf][nf][0] + bb0, 0.f),
                                           fmaxf(acc[mf][nf][1] + bb0, 0.f));
            __half2 v1 = __floats2half2_rn(fmaxf(acc[mf][nf][2] + bb1, 0.f),
                                           fmaxf(acc[mf][nf][3] + bb1, 0.f));
            *(__half2*)&s_out[r0 * 130 + px0] = v0;
            *(__half2*)&s_out[r1 * 130 + px0] = v1;
        }
    }
    __syncthreads();
    {
        int px = tid >> 1, ch = (tid & 1) * 32;
        int yy = px >> 4, xx = px & 15;
        __half* base = out + ((size_t)(be * Hh + y0 + yy) * Ww + (x0 + xx)) * Cout +
                       coT * 64 + ch;
        #pragma unroll
        for (int k = 0; k < 4; k++) {
            union { uint4 u; __half2 h[4]; } pk;
            #pragma unroll
            for (int j = 0; j < 4; j++)
                pk.h[j] = __halves2half2(s_out[(ch + 8 * k + 2 * j) * 130 + px],
                                         s_out[(ch + 8 * k + 2 * j + 1) * 130 + px]);
            *(uint4*)&base[8 * k] = pk.u;
        }
    }
}

// 2x2 maxpool fp16 NHWC -> fp16 NHWC; i enumerates (be,y,x,c8) c8-fastest
__global__ void pool16_k(const __half* __restrict__ in, __half* __restrict__ out,
                         int total8, int Ho, int Wo, int C) {
    const int C8 = C >> 3;
    for (int i = blockIdx.x * blockDim.x + threadIdx.x; i < total8;
         i += gridDim.x * blockDim.x) {
        int c8 = i % C8;
        int t = i / C8;
        int x = t % Wo;
        t /= Wo;
        int y = t % Ho;
        int be = t / Ho;
        const __half* p =
            in + ((size_t)(be * 2 * Ho + 2 * y) * (2 * Wo) + 2 * x) * C + c8 * 8;
        union { uint4 u; __half2 h[4]; } a, b, c, d, rr;
        a.u = *(const uint4*)p;
        b.u = *(const uint4*)(p + C);
        c.u = *(const uint4*)(p + (size_t)2 * Wo * C);
        d.u = *(const uint4*)(p + (size_t)2 * Wo * C + C);
        #pragma unroll
        for (int j = 0; j < 4; j++)
            rr.h[j] = __hmax2(__hmax2(a.h[j], b.h[j]), __hmax2(c.h[j], d.h[j]));
        *(uint4*)&out[(size_t)i * 8] = rr.u;
    }
}

// NHWC fp16 -> NCHW fp32 (pool planes for perc/style)
__global__ void nhwc2nchw_k(const __half* __restrict__ in, float* __restrict__ out,
                            int HWp, int C, int SZlevel) {
    __shared__ float tl[32][33];
    const int px0 = blockIdx.x * 32, c0 = blockIdx.y * 32, be = blockIdx.z;
    const int tx = threadIdx.x, ty = threadIdx.y;
    for (int r = ty; r < 32; r += 8)
        tl[r][tx] = __half2float(in[((size_t)be * HWp + px0 + r) * C + c0 + tx]);
    __syncthreads();
    const int s = be >> 1, b = be & 1;
    float* ob = out + (size_t)s * SZlevel + (size_t)b * C * HWp;
    for (int r = ty; r < 32; r += 8)
        ob[(size_t)(c0 + r) * HWp + px0 + tx] = tl[tx][r];
}

// perceptual: sum |out-gt| + |comp-gt| -> g_acc[2]
__global__ void perc_sum_k(const float* __restrict__ aout,
                           const float* __restrict__ agt,
                           const float* __restrict__ acomp, int n) {
    float s = 0.f;
    for (int i = blockIdx.x * blockDim.x + threadIdx.x; i < n;
         i += gridDim.x * blockDim.x) {
        float g = agt[i];
        s += fabsf(aout[i] - g) + fabsf(acomp[i] - g);
    }
    warp_atomic(&g_acc[2], s);
}

// style Gram-difference, 32x32 Gram tile per block, 3 streams fused
__global__ __launch_bounds__(256) void style_k(
    const float* __restrict__ Xout, const float* __restrict__ Xgt,
    const float* __restrict__ Xcomp, int HHs, int WWs, double scale) {
    __shared__ float sh[6][32][33];
    const int bc = blockIdx.z;
    const size_t off = (size_t)bc * HHs * WWs;
    const float* p0 = Xout + off;
    const float* p1 = Xgt + off;
    const float* p2 = Xcomp + off;
    const int v0 = blockIdx.x * 32, w0 = blockIdx.y * 32;
    const int tx = threadIdx.x & 31, ty = threadIdx.x >> 5;

    float aO[4] = {0, 0, 0, 0}, aG[4] = {0, 0, 0, 0}, aC[4] = {0, 0, 0, 0};

    for (int h0 = 0; h0 < HHs; h0 += 32) {
        for (int e = threadIdx.x; e < 1024; e += 256) {
            int hh = e >> 5, cc = e & 31;
            int rw = (h0 + hh) * WWs;
            sh[0][hh][cc] = p0[rw + w0 + cc];
            sh[1][hh][cc] = p0[rw + v0 + cc];
            sh[2][hh][cc] = p1[rw + w0 + cc];
            sh[3][hh][cc] = p1[rw + v0 + cc];
            sh[4][hh][cc] = p2[rw + w0 + cc];
            sh[5][hh][cc] = p2[rw + v0 + cc];
        }
        __syncthreads();
        #pragma unroll 4
        for (int hh = 0; hh < 32; hh++) {
            float vO = sh[1][hh][tx], vG = sh[3][hh][tx], vC = sh[5][hh][tx];
            #pragma unroll
            for (int j = 0; j < 4; j++) {
                int wl = ty + j * 8;
                aO[j] += sh[0][hh][wl] * vO;
                aG[j] += sh[2][hh][wl] * vG;
                aC[j] += sh[4][hh][wl] * vC;
            }
        }
        __syncthreads();
    }

    float sO = 0.f, sC = 0.f;
    #pragma unroll
    for (int j = 0; j < 4; j++) {
        sO += fabsf(aO[j] - aG[j]);
        sC += fabsf(aC[j] - aG[j]);
    }
    #pragma unroll
    for (int o = 16; o > 0; o >>= 1) {
        sO += __shfl_down_sync(0xffffffffu, sO, o);
        sC += __shfl_down_sync(0xffffffffu, sC, o);
    }
    if ((threadIdx.x & 31) == 0) {
        atomicAdd(&g_acc[3], scale * (double)sO);
        atomicAdd(&g_acc[4], scale * (double)sC);
    }
}

__global__ void finalize_k(float* out) {
    if (threadIdx.x == 0 && blockIdx.x == 0) {
        const double N = 3.0 * 512.0 * 512.0 * (double)BN;
        const double Nigt = (double)SZ1;
        double l = (double)BN * g_acc[0] / N
                 + g_acc[1] / N
                 + g_acc[2] / Nigt
                 + g_acc[3]
                 + g_acc[4];
        out[0] = (float)l;
    }
}

// ---------------- host launcher ----------------
extern "C" void kernel_launch(void* const* d_in, const int* in_sizes, int n_in,
                              void* d_out, int out_size) {
    (void)in_sizes; (void)n_in; (void)out_size;
    const float* igt  = (const float*)d_in[0];
    const float* iout = (const float*)d_in[1];
    const float* mask = (const float*)d_in[2];
    const float* w[7];
    const float* bb[7];
    for (int i = 0; i < 7; i++) {
        w[i]  = (const float*)d_in[3 + 2 * i];
        bb[i] = (const float*)d_in[4 + 2 * i];
    }

    __half *hA, *hB, *hp, *w16b;
    float *comp, *p1b, *p2b, *p3b, *wT1;
    cudaGetSymbolAddress((void**)&hA, g_hA);
    cudaGetSymbolAddress((void**)&hB, g_hB);
    cudaGetSymbolAddress((void**)&hp, g_hp);
    cudaGetSymbolAddress((void**)&comp, g_comp);
    cudaGetSymbolAddress((void**)&p1b, g_p1);
    cudaGetSymbolAddress((void**)&p2b, g_p2);
    cudaGetSymbolAddress((void**)&p3b, g_p3);
    cudaGetSymbolAddress((void**)&wT1, g_wT1);
    cudaGetSymbolAddress((void**)&w16b, g_w16);

    const int cins[7]  = {3, 64, 64, 128, 128, 256, 256};
    const int couts[7] = {64, 64, 128, 128, 256, 256, 256};
    __half* w16[7];
    size_t ofs = 0;
    for (int i = 1; i < 7; i++) {
        w16[i] = w16b + ofs;
        ofs += (size_t)cins[i] * couts[i] * 9;
    }

    float* P1[3] = {p1b, p1b + SZ1, p1b + 2 * (size_t)SZ1};
    float* P2[3] = {p2b, p2b + SZ2, p2b + 2 * (size_t)SZ2};
    float* P3[3] = {p3b, p3b + SZ3, p3b + 2 * (size_t)SZ3};

    zero_acc_k<<<1, 32>>>();
    wtrans1_k<<<32, 256>>>(w[0], wT1, 3, 64);
    for (int i = 1; i < 7; i++)
        wtrans16_k<<<256, 256>>>(w[i], w16[i], cins[i], couts[i]);
    comp_l1_k<<<1024, 256>>>(igt, iout, mask);

    // layer 1: FFMA2, fp32 NCHW in -> fp16 NHWC out
    conv1_k<<<dim3(32, 32, 6 * 2), 256>>>(igt, iout, comp, wT1, bb[0],
                                          hA, 3, 64, 512, 512);
    // layers 2-7: fp16 mma implicit GEMM, NHWC
    conv_mma16_k<<<dim3(32, 64, 6 * 1), 256>>>(hA, w16[1], bb[1], hB, 64, 64, 512, 512);
    pool16_k<<<8192, 256>>>(hB, hp, 6 * 256 * 256 * 8, 256, 256, 64);
    nhwc2nchw_k<<<dim3(2048, 2, 6), dim3(32, 8)>>>(hp, p1b, 65536, 64, SZ1);
    conv_mma16_k<<<dim3(16, 32, 6 * 2), 256>>>(hp, w16[2], bb[2], hA, 64, 128, 256, 256);
    conv_mma16_k<<<dim3(16, 32, 6 * 2), 256>>>(hA, w16[3], bb[3], hB, 128, 128, 256, 256);
    pool16_k<<<4096, 256>>>(hB, hp, 6 * 128 * 128 * 16, 128, 128, 128);
    nhwc2nchw_k<<<dim3(512, 4, 6), dim3(32, 8)>>>(hp, p2b, 16384, 128, SZ2);
    conv_mma16_k<<<dim3(8, 16, 6 * 4), 256>>>(hp, w16[4], bb[4], hA, 128, 256, 128, 128);
    conv_mma16_k<<<dim3(8, 16, 6 * 4), 256>>>(hA, w16[5], bb[5], hB, 256, 256, 128, 128);
    conv_mma16_k<<<dim3(8, 16, 6 * 4), 256>>>(hB, w16[6], bb[6], hA, 256, 256, 128, 128);
    pool16_k<<<2048, 256>>>(hA, hp, 6 * 64 * 64 * 32, 64, 64, 256);
    nhwc2nchw_k<<<dim3(128, 8, 6), dim3(32, 8)>>>(hp, p3b, 4096, 256, SZ3);

    perc_sum_k<<<4096, 256>>>(P1[1], P1[0], P1[2], SZ1);
    perc_sum_k<<<2048, 256>>>(P2[1], P2[0], P2[2], SZ2);
    perc_sum_k<<<1024, 256>>>(P3[1], P3[0], P3[2], SZ3);

    style_k<<<dim3(8, 8, BN * 64), 256>>>(P1[1], P1[0], P1[2], 256, 256,
                                          1.0 / (4194304.0 * 4096.0));
    style_k<<<dim3(4, 4, BN * 128), 256>>>(P2[1], P2[0], P2[2], 128, 128,
                                           1.0 / (2097152.0 * 16384.0));
    style_k<<<dim3(2, 2, BN * 256), 256>>>(P3[1], P3[0], P3[2], 64, 64,
                                           1.0 / (1048576.0 * 65536.0));

    finalize_k<<<1, 32>>>((float*)d_out);
}

// round 9
// speedup vs baseline: 3.6120x; 1.1590x over previous
#include <cuda_runtime.h>
#include <cuda_fp16.h>
#include <math.h>
#include <stdint.h>

#define BN 2
#define CI_T 8

// ---------------- static scratch (no allocations allowed) ----------------
__device__ __half g_hA[6 * 64 * 512 * 512];      // NHWC fp16 ping
__device__ __half g_hB[6 * 64 * 512 * 512];      // NHWC fp16 pong
__device__ __half g_hp[6 * 64 * 256 * 256];      // NHWC fp16 pooled
__device__ float  g_comp[BN * 3 * 512 * 512];
__device__ float  g_wT1[1728];                   // layer-1 weights (fp32)
__device__ __half g_w16[1732608];                // layers 2-7 weights, A-fragment order

#define SZ1 (BN * 64 * 256 * 256)
#define SZ2 (BN * 128 * 128 * 128)
#define SZ3 (BN * 256 * 64 * 64)
__device__ float g_p1[3][SZ1];   // [gt, out, comp] fp32 NCHW pools
__device__ float g_p2[3][SZ2];
__device__ float g_p3[3][SZ3];

__device__ double g_acc[8];

// ---------------- helpers ----------------
__device__ __forceinline__ unsigned long long pk2(float a, float b) {
    unsigned long long r;
    asm("mov.b64 %0, {%1, %2};" : "=l"(r) : "f"(a), "f"(b));
    return r;
}
__device__ __forceinline__ unsigned long long fma_x2(unsigned long long a,
                                                     unsigned long long b,
                                                     unsigned long long c) {
    unsigned long long d;
    asm("fma.rn.f32x2 %0, %1, %2, %3;" : "=l"(d) : "l"(a), "l"(b), "l"(c));
    return d;
}
__device__ __forceinline__ void upk(unsigned long long v, float& lo, float& hi) {
    asm("mov.b64 {%0, %1}, %2;" : "=f"(lo), "=f"(hi) : "l"(v));
}
__device__ __forceinline__ uint32_t smem_u32(const void* p) {
    return (uint32_t)__cvta_generic_to_shared(p);
}
__device__ __forceinline__ void ldm4(uint32_t* r, uint32_t addr) {
    asm volatile("ldmatrix.sync.aligned.m8n8.x4.shared.b16 {%0,%1,%2,%3}, [%4];"
                 : "=r"(r[0]), "=r"(r[1]), "=r"(r[2]), "=r"(r[3]) : "r"(addr));
}
__device__ __forceinline__ void mma16(float* c, const uint32_t* a,
                                      uint32_t b0, uint32_t b1) {
    asm volatile(
        "mma.sync.aligned.m16n8k16.row.col.f32.f16.f16.f32 "
        "{%0,%1,%2,%3}, {%4,%5,%6,%7}, {%8,%9}, {%0,%1,%2,%3};"
        : "+f"(c[0]), "+f"(c[1]), "+f"(c[2]), "+f"(c[3])
        : "r"(a[0]), "r"(a[1]), "r"(a[2]), "r"(a[3]), "r"(b0), "r"(b1));
}
__device__ __forceinline__ void cp16(uint32_t dst, const void* src, int srcsize) {
    asm volatile("cp.async.ca.shared.global [%0], [%1], 16, %2;"
                 :: "r"(dst), "l"(src), "r"(srcsize));
}
__device__ __forceinline__ void warp_atomic(double* dst, float v) {
    #pragma unroll
    for (int o = 16; o > 0; o >>= 1) v += __shfl_down_sync(0xffffffffu, v, o);
    if ((threadIdx.x & 31) == 0) atomicAdd(dst, (double)v);
}

// ---------------- kernels ----------------
__global__ void zero_acc_k() {
    if (threadIdx.x < 8) g_acc[threadIdx.x] = 0.0;
}

// layer-1 weight transpose (fp32): wT[(ci*9+k)*Cout + co]
__global__ void wtrans1_k(const float* __restrict__ w, float* __restrict__ wT,
                          int Cin, int Cout) {
    int n = Cin * Cout * 9;
    for (int i = blockIdx.x * blockDim.x + threadIdx.x; i < n;
         i += gridDim.x * blockDim.x) {
        int co = i % Cout;
        int t = i / Cout;
        int k = t % 9;
        int ci = t / 9;
        wT[i] = w[((size_t)co * Cin + ci) * 9 + k];
    }
}

// layers 2-7: pack weights in m16n8k16 A-fragment order:
// wf[(((t*nM16 + m16)*rounds + r)*32 + lane)*8 + h]
__global__ void wtransfrag_k(const float* __restrict__ w, __half* __restrict__ wf,
                             int Cin, int Cout) {
    const int rounds = Cin >> 4, nM16 = Cout >> 4;
    int n = 9 * Cin * Cout;
    for (int i = blockIdx.x * blockDim.x + threadIdx.x; i < n;
         i += gridDim.x * blockDim.x) {
        int h = i & 7, lane = (i >> 3) & 31;
        int rest = i >> 8;
        int r = rest % rounds;
        rest /= rounds;
        int m16 = rest % nM16;
        int t = rest / nM16;
        int pair = h >> 1, lo = h & 1;
        int row = (lane >> 2) + (pair & 1) * 8;
        int ci = r * 16 + (lane & 3) * 2 + (pair >> 1) * 8 + lo;
        int co = m16 * 16 + row;
        wf[i] = __float2half_rn(w[((size_t)co * Cin + ci) * 9 + t]);
    }
}

// icomp + hole/valid L1 partial sums
__global__ void comp_l1_k(const float* __restrict__ igt,
                          const float* __restrict__ iout,
                          const float* __restrict__ mask) {
    const int n = BN * 3 * 512 * 512;
    const int hw = 512 * 512;
    float h = 0.f, v = 0.f;
    for (int i = blockIdx.x * blockDim.x + threadIdx.x; i < n;
         i += gridDim.x * blockDim.x) {
        int pix = i % hw;
        int b = (i / hw) / 3;
        float m = (mask[b * hw + pix] != 0.0f) ? 1.0f : 0.0f;
        float gt = igt[i], ot = iout[i];
        float d = ot - gt;
        h += fabsf((1.0f - m) * d);
        v += fabsf(m * d);
        g_comp[i] = (m == 1.0f) ? gt : ot;
    }
    warp_atomic(&g_acc[0], h);
    warp_atomic(&g_acc[1], v);
}

// ---------- FFMA2 conv layer 1 (Cin=3, fp32 NCHW in, fp16 NHWC out) ----------
__global__ __launch_bounds__(256, 3) void conv1_k(
    const float* __restrict__ in0, const float* __restrict__ in1,
    const float* __restrict__ in2,
    const float* __restrict__ wT, const float* __restrict__ bias,
    __half* __restrict__ out, int Cin, int Cout, int Hh, int Ww) {
    __shared__ __align__(16) float s_in[CI_T][18][20];
    __shared__ __align__(16) float s_w[CI_T][9][32];

    const int nCoT = Cout >> 5;
    const int coT = blockIdx.z % nCoT;
    const int be = blockIdx.z / nCoT;
    const int x0 = blockIdx.x * 16, y0 = blockIdx.y * 16;
    const int tid = threadIdx.x;
    const int p = tid & 63;
    const int g = tid >> 6;
    const int px = (p & 7) * 2, py = (p >> 3) * 2;
    const int g8 = g * 8;
    const size_t HW = (size_t)Hh * Ww;

    int s = be >> 1;
    const float* sp = (s == 0) ? in0 : ((s == 1) ? in1 : in2);
    const float* inB = sp + (size_t)(be & 1) * Cin * HW;

    unsigned long long acc[4][4];
    #pragma unroll
    for (int c = 0; c < 4; c++)
        #pragma unroll
        for (int q = 0; q < 4; q++) acc[c][q] = 0ull;

    const int rounds = (Cin + CI_T - 1) / CI_T;
    for (int r = 0; r < rounds; r++) {
        const int c0 = r * CI_T;
        for (int idx = tid; idx < CI_T * 324; idx += 256) {
            int q = idx / 324, rr = idx - q * 324;
            int iy = rr / 18, ix = rr - iy * 18;
            int ci = c0 + q;
            int gy = y0 + iy - 1, gx = x0 + ix - 1;
            float v = 0.f;
            if (ci < Cin && gy >= 0 && gy < Hh && gx >= 0 && gx < Ww)
                v = inB[(size_t)ci * HW + gy * Ww + gx];
            s_in[q][iy][ix] = v;
        }
        for (int idx = tid; idx < CI_T * 288; idx += 256) {
            int co = idx & 31;
            int t = idx >> 5;
            int k = t % 9, q = t / 9;
            int ci = c0 + q;
            float v = 0.f;
            if (ci < Cin) v = wT[((size_t)ci * 9 + k) * Cout + coT * 32 + co];
            s_w[q][k][co] = v;
        }
        __syncthreads();

        #pragma unroll 2
        for (int q = 0; q < CI_T; q++) {
            unsigned long long xx[4][4];
            #pragma unroll
            for (int dy = 0; dy < 4; dy++) {
                float2 a = *(const float2*)&s_in[q][py + dy][px];
                float2 b = *(const float2*)&s_in[q][py + dy][px + 2];
                xx[dy][0] = pk2(a.x, a.x);
                xx[dy][1] = pk2(a.y, a.y);
                xx[dy][2] = pk2(b.x, b.x);
                xx[dy][3] = pk2(b.y, b.y);
            }
            #pragma unroll
            for (int ky = 0; ky < 3; ky++)
                #pragma unroll
                for (int kx = 0; kx < 3; kx++) {
                    const int k = ky * 3 + kx;
                    float2 wa = *(const float2*)&s_w[q][k][g8];
                    float2 wb = *(const float2*)&s_w[q][k][g8 + 2];
                    float2 wc = *(const float2*)&s_w[q][k][g8 + 4];
                    float2 wd = *(const float2*)&s_w[q][k][g8 + 6];
                    unsigned long long w0 = pk2(wa.x, wa.y);
                    unsigned long long w1 = pk2(wb.x, wb.y);
                    unsigned long long w2 = pk2(wc.x, wc.y);
                    unsigned long long w3 = pk2(wd.x, wd.y);
                    #pragma unroll
                    for (int sy = 0; sy < 2; sy++)
                        #pragma unroll
                        for (int sx = 0; sx < 2; sx++) {
                            unsigned long long xf = xx[sy + ky][sx + kx];
                            const int pid = sy * 2 + sx;
                            acc[0][pid] = fma_x2(xf, w0, acc[0][pid]);
                            acc[1][pid] = fma_x2(xf, w1, acc[1][pid]);
                            acc[2][pid] = fma_x2(xf, w2, acc[2][pid]);
                            acc[3][pid] = fma_x2(xf, w3, acc[3][pid]);
                        }
                }
        }
        __syncthreads();
    }

    const int coBase = coT * 32 + g8;
    float bb[8];
    #pragma unroll
    for (int j = 0; j < 8; j++) bb[j] = bias[coBase + j];
    #pragma unroll
    for (int sy = 0; sy < 2; sy++)
        #pragma unroll
        for (int sx = 0; sx < 2; sx++) {
            int y = y0 + py + sy, x = x0 + px + sx;
            const int pid = sy * 2 + sx;
            union { uint4 u; __half2 h[4]; } pk;
            #pragma unroll
            for (int cp = 0; cp < 4; cp++) {
                float lo, hi;
                upk(acc[cp][pid], lo, hi);
                pk.h[cp] = __floats2half2_rn(fmaxf(lo + bb[2 * cp], 0.f),
                                             fmaxf(hi + bb[2 * cp + 1], 0.f));
            }
            *(uint4*)&out[((size_t)(be * Hh + y) * Ww + x) * Cout + coBase] = pk.u;
        }
}

// ---------- fp16 mma conv, A-frags direct from gmem, cp.async double buffer ----
// block 256 = 8 warps (2 warp_m x 4 warp_n); tile 64 co x (8y x 32x) = 256 px.
// act smem: per buf 340 cells x 24 halves (16 used + pad). grid (W/32,H/8,6*Cout/64)
#define ACT_H 8160   // halves per buffer (340*24)
__global__ __launch_bounds__(256) void conv_mma16b_k(
    const __half* __restrict__ in, const __half* __restrict__ wf,
    const float* __restrict__ bias, __half* __restrict__ out,
    int Cin, int Cout, int Hh, int Ww) {
    __shared__ __align__(16) __half sh[16896];   // max(2*8160, 64*264)

    const int nCoT = Cout >> 6;
    const int nM16 = Cout >> 4;
    const int coT = blockIdx.z % nCoT;
    const int be = blockIdx.z / nCoT;
    const int x0 = blockIdx.x * 32, y0 = blockIdx.y * 8;
    const int tid = threadIdx.x, wid = tid >> 5, lane = tid & 31;
    const int warp_m = wid >> 2, warp_n = wid & 3;
    const int rounds = Cin >> 4;

    float acc[2][8][4];
    #pragma unroll
    for (int mf = 0; mf < 2; mf++)
        #pragma unroll
        for (int nf = 0; nf < 8; nf++)
            #pragma unroll
            for (int q = 0; q < 4; q++) acc[mf][nf][q] = 0.f;

    const uint32_t sxb = smem_u32(sh);
    const int l7 = lane & 7, qd = lane >> 3;
    const int b_xx = ((qd >> 1) & 1) * 8 + l7;
    const int b_k = (qd & 1) * 8;
    uint32_t bRel[2][2];
    #pragma unroll
    for (int j = 0; j < 2; j++)
        #pragma unroll
        for (int xg = 0; xg < 2; xg++)
            bRel[j][xg] = (uint32_t)(
                (((2 * warp_n + j) * 34 + xg * 16 + b_xx) * 24 + b_k) * 2);

    // ---- stage round 0 ----
    {
        const int ci0 = 0;
        for (int idx = tid; idx < 680; idx += 256) {
            int cell = idx >> 1, hh = idx & 1;
            int yy = cell / 34, xx = cell - yy * 34;
            int gy = y0 + yy - 1, gx = x0 + xx - 1;
            bool ok = (gy >= 0 && gy < Hh && gx >= 0 && gx < Ww);
            const __half* src = ok
                ? &in[((size_t)(be * Hh + gy) * Ww + gx) * Cin + ci0 + hh * 8]
                : in;
            cp16(sxb + (uint32_t)((cell * 24 + hh * 8) * 2), src, ok ? 16 : 0);
        }
        asm volatile("cp.async.commit_group;");
    }

    for (int r = 0; r < rounds; r++) {
        asm volatile("cp.async.wait_group 0;");
        __syncthreads();
        if (r + 1 < rounds) {
            const int ci0 = (r + 1) << 4;
            const uint32_t dbase = sxb + (uint32_t)(((r + 1) & 1) * ACT_H * 2);
            for (int idx = tid; idx < 680; idx += 256) {
                int cell = idx >> 1, hh = idx & 1;
                int yy = cell / 34, xx = cell - yy * 34;
                int gy = y0 + yy - 1, gx = x0 + xx - 1;
                bool ok = (gy >= 0 && gy < Hh && gx >= 0 && gx < Ww);
                const __half* src = ok
                    ? &in[((size_t)(be * Hh + gy) * Ww + gx) * Cin + ci0 + hh * 8]
                    : in;
                cp16(dbase + (uint32_t)((cell * 24 + hh * 8) * 2), src, ok ? 16 : 0);
            }
            asm volatile("cp.async.commit_group;");
        }

        const uint32_t bufB = sxb + (uint32_t)((r & 1) * ACT_H * 2);
        #pragma unroll
        for (int t = 0; t < 9; t++) {
            const int dy = t / 3, dx = t - dy * 3;
            const uint32_t toff = (uint32_t)((dy * 34 + dx) * 48);
            uint32_t a0[4], a1[4];
            {
                size_t o = ((((size_t)t * nM16 + coT * 4 + warp_m * 2) * rounds + r)
                            * 32 + lane) * 8;
                uint4 v = *(const uint4*)(wf + o);
                a0[0] = v.x; a0[1] = v.y; a0[2] = v.z; a0[3] = v.w;
                v = *(const uint4*)(wf + o + (size_t)rounds * 256);
                a1[0] = v.x; a1[1] = v.y; a1[2] = v.z; a1[3] = v.w;
            }
            #pragma unroll
            for (int j = 0; j < 2; j++)
                #pragma unroll
                for (int xg = 0; xg < 2; xg++) {
                    uint32_t b[4];
                    ldm4(b, bufB + bRel[j][xg] + toff);
                    const int nb = j * 4 + xg * 2;
                    mma16(acc[0][nb], a0, b[0], b[1]);
                    mma16(acc[1][nb], a1, b[0], b[1]);
                    mma16(acc[0][nb + 1], a0, b[2], b[3]);
                    mma16(acc[1][nb + 1], a1, b[2], b[3]);
                }
        }
        __syncthreads();
    }

    // ---- epilogue: bias+relu -> smem [64co][264] -> NHWC fp16 ----
    #pragma unroll
    for (int mf = 0; mf < 2; mf++) {
        const int c0l = warp_m * 32 + mf * 16 + (lane >> 2);
        const float bb0 = bias[coT * 64 + c0l];
        const float bb1 = bias[coT * 64 + c0l + 8];
        #pragma unroll
        for (int nf = 0; nf < 8; nf++) {
            int px = (2 * warp_n + (nf >> 2)) * 32 + ((nf >> 1) & 1) * 16 +
                     (nf & 1) * 8 + (lane & 3) * 2;
            *(__half2*)&sh[c0l * 264 + px] =
                __floats2half2_rn(fmaxf(acc[mf][nf][0] + bb0, 0.f),
                                  fmaxf(acc[mf][nf][1] + bb0, 0.f));
            *(__half2*)&sh[(c0l + 8) * 264 + px] =
                __floats2half2_rn(fmaxf(acc[mf][nf][2] + bb1, 0.f),
                                  fmaxf(acc[mf][nf][3] + bb1, 0.f));
        }
    }
    __syncthreads();
    {
        const int px = tid;
        const int yy = px >> 5, xx = px & 31;
        __half* base = out + ((size_t)(be * Hh + y0 + yy) * Ww + (x0 + xx)) * Cout +
                       coT * 64;
        #pragma unroll
        for (int k = 0; k < 8; k++) {
            union { uint4 u; __half h[8]; } pk;
            #pragma unroll
            for (int j = 0; j < 8; j++) pk.h[j] = sh[(8 * k + j) * 264 + px];
            *(uint4*)&base[8 * k] = pk.u;
        }
    }
}

// 2x2 maxpool fp16 NHWC -> fp16 NHWC
__global__ void pool16_k(const __half* __restrict__ in, __half* __restrict__ out,
                         int total8, int Ho, int Wo, int C) {
    const int C8 = C >> 3;
    for (int i = blockIdx.x * blockDim.x + threadIdx.x; i < total8;
         i += gridDim.x * blockDim.x) {
        int c8 = i % C8;
        int t = i / C8;
        int x = t % Wo;
        t /= Wo;
        int y = t % Ho;
        int be = t / Ho;
        const __half* p =
            in + ((size_t)(be * 2 * Ho + 2 * y) * (2 * Wo) + 2 * x) * C + c8 * 8;
        union { uint4 u; __half2 h[4]; } a, b, c, d, rr;
        a.u = *(const uint4*)p;
        b.u = *(const uint4*)(p + C);
        c.u = *(const uint4*)(p + (size_t)2 * Wo * C);
        d.u = *(const uint4*)(p + (size_t)2 * Wo * C + C);
        #pragma unroll
        for (int j = 0; j < 4; j++)
            rr.h[j] = __hmax2(__hmax2(a.h[j], b.h[j]), __hmax2(c.h[j], d.h[j]));
        *(uint4*)&out[(size_t)i * 8] = rr.u;
    }
}

// NHWC fp16 -> NCHW fp32 (pool planes for perc/style)
__global__ void nhwc2nchw_k(const __half* __restrict__ in, float* __restrict__ out,
                            int HWp, int C, int SZlevel) {
    __shared__ float tl[32][33];
    const int px0 = blockIdx.x * 32, c0 = blockIdx.y * 32, be = blockIdx.z;
    const int tx = threadIdx.x, ty = threadIdx.y;
    for (int r = ty; r < 32; r += 8)
        tl[r][tx] = __half2float(in[((size_t)be * HWp + px0 + r) * C + c0 + tx]);
    __syncthreads();
    const int s = be >> 1, b = be & 1;
    float* ob = out + (size_t)s * SZlevel + (size_t)b * C * HWp;
    for (int r = ty; r < 32; r += 8)
        ob[(size_t)(c0 + r) * HWp + px0 + tx] = tl[tx][r];
}

// perceptual: sum |out-gt| + |comp-gt| -> g_acc[2]
__global__ void perc_sum_k(const float* __restrict__ aout,
                           const float* __restrict__ agt,
                           const float* __restrict__ acomp, int n) {
    float s = 0.f;
    for (int i = blockIdx.x * blockDim.x + threadIdx.x; i < n;
         i += gridDim.x * blockDim.x) {
        float g = agt[i];
        s += fabsf(aout[i] - g) + fabsf(acomp[i] - g);
    }
    warp_atomic(&g_acc[2], s);
}

// style Gram-difference, 32x32 Gram tile per block, 3 streams fused
__global__ __launch_bounds__(256) void style_k(
    const float* __restrict__ Xout, const float* __restrict__ Xgt,
    const float* __restrict__ Xcomp, int HHs, int WWs, double scale) {
    __shared__ float sh[6][32][33];
    const int bc = blockIdx.z;
    const size_t off = (size_t)bc * HHs * WWs;
    const float* p0 = Xout + off;
    const float* p1 = Xgt + off;
    const float* p2 = Xcomp + off;
    const int v0 = blockIdx.x * 32, w0 = blockIdx.y * 32;
    const int tx = threadIdx.x & 31, ty = threadIdx.x >> 5;

    float aO[4] = {0, 0, 0, 0}, aG[4] = {0, 0, 0, 0}, aC[4] = {0, 0, 0, 0};

    for (int h0 = 0; h0 < HHs; h0 += 32) {
        for (int e = threadIdx.x; e < 1024; e += 256) {
            int hh = e >> 5, cc = e & 31;
            int rw = (h0 + hh) * WWs;
            sh[0][hh][cc] = p0[rw + w0 + cc];
            sh[1][hh][cc] = p0[rw + v0 + cc];
            sh[2][hh][cc] = p1[rw + w0 + cc];
            sh[3][hh][cc] = p1[rw + v0 + cc];
            sh[4][hh][cc] = p2[rw + w0 + cc];
            sh[5][hh][cc] = p2[rw + v0 + cc];
        }
        __syncthreads();
        #pragma unroll 4
        for (int hh = 0; hh < 32; hh++) {
            float vO = sh[1][hh][tx], vG = sh[3][hh][tx], vC = sh[5][hh][tx];
            #pragma unroll
            for (int j = 0; j < 4; j++) {
                int wl = ty + j * 8;
                aO[j] += sh[0][hh][wl] * vO;
                aG[j] += sh[2][hh][wl] * vG;
                aC[j] += sh[4][hh][wl] * vC;
            }
        }
        __syncthreads();
    }

    float sO = 0.f, sC = 0.f;
    #pragma unroll
    for (int j = 0; j < 4; j++) {
        sO += fabsf(aO[j] - aG[j]);
        sC += fabsf(aC[j] - aG[j]);
    }
    #pragma unroll
    for (int o = 16; o > 0; o >>= 1) {
        sO += __shfl_down_sync(0xffffffffu, sO, o);
        sC += __shfl_down_sync(0xffffffffu, sC, o);
    }
    if ((threadIdx.x & 31) == 0) {
        atomicAdd(&g_acc[3], scale * (double)sO);
        atomicAdd(&g_acc[4], scale * (double)sC);
    }
}

__global__ void finalize_k(float* out) {
    if (threadIdx.x == 0 && blockIdx.x == 0) {
        const double N = 3.0 * 512.0 * 512.0 * (double)BN;
        const double Nigt = (double)SZ1;
        double l = (double)BN * g_acc[0] / N
                 + g_acc[1] / N
                 + g_acc[2] / Nigt
                 + g_acc[3]
                 + g_acc[4];
        out[0] = (float)l;
    }
}

// ---------------- host launcher ----------------
extern "C" void kernel_launch(void* const* d_in, const int* in_sizes, int n_in,
                              void* d_out, int out_size) {
    (void)in_sizes; (void)n_in; (void)out_size;
    const float* igt  = (const float*)d_in[0];
    const float* iout = (const float*)d_in[1];
    const float* mask = (const float*)d_in[2];
    const float* w[7];
    const float* bb[7];
    for (int i = 0; i < 7; i++) {
        w[i]  = (const float*)d_in[3 + 2 * i];
        bb[i] = (const float*)d_in[4 + 2 * i];
    }

    __half *hA, *hB, *hp, *w16b;
    float *comp, *p1b, *p2b, *p3b, *wT1;
    cudaGetSymbolAddress((void**)&hA, g_hA);
    cudaGetSymbolAddress((void**)&hB, g_hB);
    cudaGetSymbolAddress((void**)&hp, g_hp);
    cudaGetSymbolAddress((void**)&comp, g_comp);
    cudaGetSymbolAddress((void**)&p1b, g_p1);
    cudaGetSymbolAddress((void**)&p2b, g_p2);
    cudaGetSymbolAddress((void**)&p3b, g_p3);
    cudaGetSymbolAddress((void**)&wT1, g_wT1);
    cudaGetSymbolAddress((void**)&w16b, g_w16);

    const int cins[7]  = {3, 64, 64, 128, 128, 256, 256};
    const int couts[7] = {64, 64, 128, 128, 256, 256, 256};
    __half* w16[7];
    size_t ofs = 0;
    for (int i = 1; i < 7; i++) {
        w16[i] = w16b + ofs;
        ofs += (size_t)cins[i] * couts[i] * 9;
    }

    float* P1[3] = {p1b, p1b + SZ1, p1b + 2 * (size_t)SZ1};
    float* P2[3] = {p2b, p2b + SZ2, p2b + 2 * (size_t)SZ2};
    float* P3[3] = {p3b, p3b + SZ3, p3b + 2 * (size_t)SZ3};

    zero_acc_k<<<1, 32>>>();
    wtrans1_k<<<32, 256>>>(w[0], wT1, 3, 64);
    for (int i = 1; i < 7; i++)
        wtransfrag_k<<<256, 256>>>(w[i], w16[i], cins[i], couts[i]);
    comp_l1_k<<<1024, 256>>>(igt, iout, mask);

    // layer 1: FFMA2, fp32 NCHW in -> fp16 NHWC out
    conv1_k<<<dim3(32, 32, 6 * 2), 256>>>(igt, iout, comp, wT1, bb[0],
                                          hA, 3, 64, 512, 512);
    // layers 2-7: fp16 mma, A-frags from gmem, cp.async pipeline
    conv_mma16b_k<<<dim3(16, 64, 6), 256>>>(hA, w16[1], bb[1], hB, 64, 64, 512, 512);
    pool16_k<<<8192, 256>>>(hB, hp, 6 * 256 * 256 * 8, 256, 256, 64);
    nhwc2nchw_k<<<dim3(2048, 2, 6), dim3(32, 8)>>>(hp, p1b, 65536, 64, SZ1);
    conv_mma16b_k<<<dim3(8, 32, 12), 256>>>(hp, w16[2], bb[2], hA, 64, 128, 256, 256);
    conv_mma16b_k<<<dim3(8, 32, 12), 256>>>(hA, w16[3], bb[3], hB, 128, 128, 256, 256);
    pool16_k<<<4096, 256>>>(hB, hp, 6 * 128 * 128 * 16, 128, 128, 128);
    nhwc2nchw_k<<<dim3(512, 4, 6), dim3(32, 8)>>>(hp, p2b, 16384, 128, SZ2);
    conv_mma16b_k<<<dim3(4, 16, 24), 256>>>(hp, w16[4], bb[4], hA, 128, 256, 128, 128);
    conv_mma16b_k<<<dim3(4, 16, 24), 256>>>(hA, w16[5], bb[5], hB, 256, 256, 128, 128);
    conv_mma16b_k<<<dim3(4, 16, 24), 256>>>(hB, w16[6], bb[6], hA, 256, 256, 128, 128);
    pool16_k<<<2048, 256>>>(hA, hp, 6 * 64 * 64 * 32, 64, 64, 256);
    nhwc2nchw_k<<<dim3(128, 8, 6), dim3(32, 8)>>>(hp, p3b, 4096, 256, SZ3);

    perc_sum_k<<<4096, 256>>>(P1[1], P1[0], P1[2], SZ1);
    perc_sum_k<<<2048, 256>>>(P2[1], P2[0], P2[2], SZ2);
    perc_sum_k<<<1024, 256>>>(P3[1], P3[0], P3[2], SZ3);

    style_k<<<dim3(8, 8, BN * 64), 256>>>(P1[1], P1[0], P1[2], 256, 256,
                                          1.0 / (4194304.0 * 4096.0));
    style_k<<<dim3(4, 4, BN * 128), 256>>>(P2[1], P2[0], P2[2], 128, 128,
                                           1.0 / (2097152.0 * 16384.0));
    style_k<<<dim3(2, 2, BN * 256), 256>>>(P3[1], P3[0], P3[2], 64, 64,
                                           1.0 / (1048576.0 * 65536.0));

    finalize_k<<<1, 32>>>((float*)d_out);
}

// round 10
// speedup vs baseline: 5.0536x; 1.3991x over previous
#include <cuda_runtime.h>
#include <cuda_fp16.h>
#include <math.h>
#include <stdint.h>

#define BN 2
#define CI_T 8

// ---------------- static scratch (no allocations allowed) ----------------
__device__ __half g_hA[6 * 64 * 512 * 512];      // NHWC fp16 ping
__device__ __half g_hB[6 * 64 * 512 * 512];      // NHWC fp16 pong
__device__ __half g_hp[6 * 64 * 256 * 256];      // NHWC fp16 pooled
__device__ float  g_comp[BN * 3 * 512 * 512];
__device__ float  g_wT1[1728];                   // layer-1 weights (fp32)
__device__ __half g_w16[1732608];                // layers 2-7 weights, A-fragment order

#define SZ1 (BN * 64 * 256 * 256)
#define SZ2 (BN * 128 * 128 * 128)
#define SZ3 (BN * 256 * 64 * 64)
// fp16 NCHW pool planes per stream: [gt, out, comp]
__device__ __half g_q1[3][SZ1];
__device__ __half g_q2[3][SZ2];
__device__ __half g_q3[3][SZ3];

__device__ double g_acc[8];

// ---------------- helpers ----------------
__device__ __forceinline__ unsigned long long pk2(float a, float b) {
    unsigned long long r;
    asm("mov.b64 %0, {%1, %2};" : "=l"(r) : "f"(a), "f"(b));
    return r;
}
__device__ __forceinline__ unsigned long long fma_x2(unsigned long long a,
                                                     unsigned long long b,
                                                     unsigned long long c) {
    unsigned long long d;
    asm("fma.rn.f32x2 %0, %1, %2, %3;" : "=l"(d) : "l"(a), "l"(b), "l"(c));
    return d;
}
__device__ __forceinline__ void upk(unsigned long long v, float& lo, float& hi) {
    asm("mov.b64 {%0, %1}, %2;" : "=f"(lo), "=f"(hi) : "l"(v));
}
__device__ __forceinline__ uint32_t smem_u32(const void* p) {
    return (uint32_t)__cvta_generic_to_shared(p);
}
__device__ __forceinline__ void ldm4(uint32_t* r, uint32_t addr) {
    asm volatile("ldmatrix.sync.aligned.m8n8.x4.shared.b16 {%0,%1,%2,%3}, [%4];"
                 : "=r"(r[0]), "=r"(r[1]), "=r"(r[2]), "=r"(r[3]) : "r"(addr));
}
__device__ __forceinline__ void ldm4t(uint32_t* r, uint32_t addr) {
    asm volatile("ldmatrix.sync.aligned.m8n8.x4.trans.shared.b16 {%0,%1,%2,%3}, [%4];"
                 : "=r"(r[0]), "=r"(r[1]), "=r"(r[2]), "=r"(r[3]) : "r"(addr));
}
__device__ __forceinline__ void ldm2t(uint32_t* r, uint32_t addr) {
    asm volatile("ldmatrix.sync.aligned.m8n8.x2.trans.shared.b16 {%0,%1}, [%2];"
                 : "=r"(r[0]), "=r"(r[1]) : "r"(addr));
}
__device__ __forceinline__ void mma16(float* c, const uint32_t* a,
                                      uint32_t b0, uint32_t b1) {
    asm volatile(
        "mma.sync.aligned.m16n8k16.row.col.f32.f16.f16.f32 "
        "{%0,%1,%2,%3}, {%4,%5,%6,%7}, {%8,%9}, {%0,%1,%2,%3};"
        : "+f"(c[0]), "+f"(c[1]), "+f"(c[2]), "+f"(c[3])
        : "r"(a[0]), "r"(a[1]), "r"(a[2]), "r"(a[3]), "r"(b0), "r"(b1));
}
__device__ __forceinline__ void cp16(uint32_t dst, const void* src, int srcsize) {
    asm volatile("cp.async.ca.shared.global [%0], [%1], 16, %2;"
                 :: "r"(dst), "l"(src), "r"(srcsize));
}
__device__ __forceinline__ void warp_atomic(double* dst, float v) {
    #pragma unroll
    for (int o = 16; o > 0; o >>= 1) v += __shfl_down_sync(0xffffffffu, v, o);
    if ((threadIdx.x & 31) == 0) atomicAdd(dst, (double)v);
}

// ---------------- kernels ----------------
__global__ void zero_acc_k() {
    if (threadIdx.x < 8) g_acc[threadIdx.x] = 0.0;
}

// layer-1 weight transpose (fp32): wT[(ci*9+k)*Cout + co]
__global__ void wtrans1_k(const float* __restrict__ w, float* __restrict__ wT,
                          int Cin, int Cout) {
    int n = Cin * Cout * 9;
    for (int i = blockIdx.x * blockDim.x + threadIdx.x; i < n;
         i += gridDim.x * blockDim.x) {
        int co = i % Cout;
        int t = i / Cout;
        int k = t % 9;
        int ci = t / 9;
        wT[i] = w[((size_t)co * Cin + ci) * 9 + k];
    }
}

// layers 2-7: pack weights in m16n8k16 A-fragment order
__global__ void wtransfrag_k(const float* __restrict__ w, __half* __restrict__ wf,
                             int Cin, int Cout) {
    const int rounds = Cin >> 4, nM16 = Cout >> 4;
    int n = 9 * Cin * Cout;
    for (int i = blockIdx.x * blockDim.x + threadIdx.x; i < n;
         i += gridDim.x * blockDim.x) {
        int h = i & 7, lane = (i >> 3) & 31;
        int rest = i >> 8;
        int r = rest % rounds;
        rest /= rounds;
        int m16 = rest % nM16;
        int t = rest / nM16;
        int pair = h >> 1, lo = h & 1;
        int row = (lane >> 2) + (pair & 1) * 8;
        int ci = r * 16 + (lane & 3) * 2 + (pair >> 1) * 8 + lo;
        int co = m16 * 16 + row;
        wf[i] = __float2half_rn(w[((size_t)co * Cin + ci) * 9 + t]);
    }
}

// icomp + hole/valid L1 partial sums
__global__ void comp_l1_k(const float* __restrict__ igt,
                          const float* __restrict__ iout,
                          const float* __restrict__ mask) {
    const int n = BN * 3 * 512 * 512;
    const int hw = 512 * 512;
    float h = 0.f, v = 0.f;
    for (int i = blockIdx.x * blockDim.x + threadIdx.x; i < n;
         i += gridDim.x * blockDim.x) {
        int pix = i % hw;
        int b = (i / hw) / 3;
        float m = (mask[b * hw + pix] != 0.0f) ? 1.0f : 0.0f;
        float gt = igt[i], ot = iout[i];
        float d = ot - gt;
        h += fabsf((1.0f - m) * d);
        v += fabsf(m * d);
        g_comp[i] = (m == 1.0f) ? gt : ot;
    }
    warp_atomic(&g_acc[0], h);
    warp_atomic(&g_acc[1], v);
}

// ---------- FFMA2 conv layer 1 (Cin=3, fp32 NCHW in, fp16 NHWC out) ----------
__global__ __launch_bounds__(256, 3) void conv1_k(
    const float* __restrict__ in0, const float* __restrict__ in1,
    const float* __restrict__ in2,
    const float* __restrict__ wT, const float* __restrict__ bias,
    __half* __restrict__ out, int Cin, int Cout, int Hh, int Ww) {
    __shared__ __align__(16) float s_in[CI_T][18][20];
    __shared__ __align__(16) float s_w[CI_T][9][32];

    const int nCoT = Cout >> 5;
    const int coT = blockIdx.z % nCoT;
    const int be = blockIdx.z / nCoT;
    const int x0 = blockIdx.x * 16, y0 = blockIdx.y * 16;
    const int tid = threadIdx.x;
    const int p = tid & 63;
    const int g = tid >> 6;
    const int px = (p & 7) * 2, py = (p >> 3) * 2;
    const int g8 = g * 8;
    const size_t HW = (size_t)Hh * Ww;

    int s = be >> 1;
    const float* sp = (s == 0) ? in0 : ((s == 1) ? in1 : in2);
    const float* inB = sp + (size_t)(be & 1) * Cin * HW;

    unsigned long long acc[4][4];
    #pragma unroll
    for (int c = 0; c < 4; c++)
        #pragma unroll
        for (int q = 0; q < 4; q++) acc[c][q] = 0ull;

    const int rounds = (Cin + CI_T - 1) / CI_T;
    for (int r = 0; r < rounds; r++) {
        const int c0 = r * CI_T;
        for (int idx = tid; idx < CI_T * 324; idx += 256) {
            int q = idx / 324, rr = idx - q * 324;
            int iy = rr / 18, ix = rr - iy * 18;
            int ci = c0 + q;
            int gy = y0 + iy - 1, gx = x0 + ix - 1;
            float v = 0.f;
            if (ci < Cin && gy >= 0 && gy < Hh && gx >= 0 && gx < Ww)
                v = inB[(size_t)ci * HW + gy * Ww + gx];
            s_in[q][iy][ix] = v;
        }
        for (int idx = tid; idx < CI_T * 288; idx += 256) {
            int co = idx & 31;
            int t = idx >> 5;
            int k = t % 9, q = t / 9;
            int ci = c0 + q;
            float v = 0.f;
            if (ci < Cin) v = wT[((size_t)ci * 9 + k) * Cout + coT * 32 + co];
            s_w[q][k][co] = v;
        }
        __syncthreads();

        #pragma unroll 2
        for (int q = 0; q < CI_T; q++) {
            unsigned long long xx[4][4];
            #pragma unroll
            for (int dy = 0; dy < 4; dy++) {
                float2 a = *(const float2*)&s_in[q][py + dy][px];
                float2 b = *(const float2*)&s_in[q][py + dy][px + 2];
                xx[dy][0] = pk2(a.x, a.x);
                xx[dy][1] = pk2(a.y, a.y);
                xx[dy][2] = pk2(b.x, b.x);
                xx[dy][3] = pk2(b.y, b.y);
            }
            #pragma unroll
            for (int ky = 0; ky < 3; ky++)
                #pragma unroll
                for (int kx = 0; kx < 3; kx++) {
                    const int k = ky * 3 + kx;
                    float2 wa = *(const float2*)&s_w[q][k][g8];
                    float2 wb = *(const float2*)&s_w[q][k][g8 + 2];
                    float2 wc = *(const float2*)&s_w[q][k][g8 + 4];
                    float2 wd = *(const float2*)&s_w[q][k][g8 + 6];
                    unsigned long long w0 = pk2(wa.x, wa.y);
                    unsigned long long w1 = pk2(wb.x, wb.y);
                    unsigned long long w2 = pk2(wc.x, wc.y);
                    unsigned long long w3 = pk2(wd.x, wd.y);
                    #pragma unroll
                    for (int sy = 0; sy < 2; sy++)
                        #pragma unroll
                        for (int sx = 0; sx < 2; sx++) {
                            unsigned long long xf = xx[sy + ky][sx + kx];
                            const int pid = sy * 2 + sx;
                            acc[0][pid] = fma_x2(xf, w0, acc[0][pid]);
                            acc[1][pid] = fma_x2(xf, w1, acc[1][pid]);
                            acc[2][pid] = fma_x2(xf, w2, acc[2][pid]);
                            acc[3][pid] = fma_x2(xf, w3, acc[3][pid]);
                        }
                }
        }
        __syncthreads();
    }

    const int coBase = coT * 32 + g8;
    float bb[8];
    #pragma unroll
    for (int j = 0; j < 8; j++) bb[j] = bias[coBase + j];
    #pragma unroll
    for (int sy = 0; sy < 2; sy++)
        #pragma unroll
        for (int sx = 0; sx < 2; sx++) {
            int y = y0 + py + sy, x = x0 + px + sx;
            const int pid = sy * 2 + sx;
            union { uint4 u; __half2 h[4]; } pk;
            #pragma unroll
            for (int cp = 0; cp < 4; cp++) {
                float lo, hi;
                upk(acc[cp][pid], lo, hi);
                pk.h[cp] = __floats2half2_rn(fmaxf(lo + bb[2 * cp], 0.f),
                                             fmaxf(hi + bb[2 * cp + 1], 0.f));
            }
            *(uint4*)&out[((size_t)(be * Hh + y) * Ww + x) * Cout + coBase] = pk.u;
        }
}

// ---------- fp16 mma conv, A-frags direct from gmem, cp.async double buffer ----
#define ACT_H 8160   // halves per buffer (340*24)
__global__ __launch_bounds__(256) void conv_mma16b_k(
    const __half* __restrict__ in, const __half* __restrict__ wf,
    const float* __restrict__ bias, __half* __restrict__ out,
    int Cin, int Cout, int Hh, int Ww) {
    __shared__ __align__(16) __half sh[16896];   // max(2*8160, 64*264)

    const int nCoT = Cout >> 6;
    const int nM16 = Cout >> 4;
    const int coT = blockIdx.z % nCoT;
    const int be = blockIdx.z / nCoT;
    const int x0 = blockIdx.x * 32, y0 = blockIdx.y * 8;
    const int tid = threadIdx.x, wid = tid >> 5, lane = tid & 31;
    const int warp_m = wid >> 2, warp_n = wid & 3;
    const int rounds = Cin >> 4;

    float acc[2][8][4];
    #pragma unroll
    for (int mf = 0; mf < 2; mf++)
        #pragma unroll
        for (int nf = 0; nf < 8; nf++)
            #pragma unroll
            for (int q = 0; q < 4; q++) acc[mf][nf][q] = 0.f;

    const uint32_t sxb = smem_u32(sh);
    const int l7 = lane & 7, qd = lane >> 3;
    const int b_xx = ((qd >> 1) & 1) * 8 + l7;
    const int b_k = (qd & 1) * 8;
    uint32_t bRel[2][2];
    #pragma unroll
    for (int j = 0; j < 2; j++)
        #pragma unroll
        for (int xg = 0; xg < 2; xg++)
            bRel[j][xg] = (uint32_t)(
                (((2 * warp_n + j) * 34 + xg * 16 + b_xx) * 24 + b_k) * 2);

    {
        const int ci0 = 0;
        for (int idx = tid; idx < 680; idx += 256) {
            int cell = idx >> 1, hh = idx & 1;
            int yy = cell / 34, xx = cell - yy * 34;
            int gy = y0 + yy - 1, gx = x0 + xx - 1;
            bool ok = (gy >= 0 && gy < Hh && gx >= 0 && gx < Ww);
            const __half* src = ok
                ? &in[((size_t)(be * Hh + gy) * Ww + gx) * Cin + ci0 + hh * 8]
                : in;
            cp16(sxb + (uint32_t)((cell * 24 + hh * 8) * 2), src, ok ? 16 : 0);
        }
        asm volatile("cp.async.commit_group;");
    }

    for (int r = 0; r < rounds; r++) {
        asm volatile("cp.async.wait_group 0;");
        __syncthreads();
        if (r + 1 < rounds) {
            const int ci0 = (r + 1) << 4;
            const uint32_t dbase = sxb + (uint32_t)(((r + 1) & 1) * ACT_H * 2);
            for (int idx = tid; idx < 680; idx += 256) {
                int cell = idx >> 1, hh = idx & 1;
                int yy = cell / 34, xx = cell - yy * 34;
                int gy = y0 + yy - 1, gx = x0 + xx - 1;
                bool ok = (gy >= 0 && gy < Hh && gx >= 0 && gx < Ww);
                const __half* src = ok
                    ? &in[((size_t)(be * Hh + gy) * Ww + gx) * Cin + ci0 + hh * 8]
                    : in;
                cp16(dbase + (uint32_t)((cell * 24 + hh * 8) * 2), src, ok ? 16 : 0);
            }
            asm volatile("cp.async.commit_group;");
        }

        const uint32_t bufB = sxb + (uint32_t)((r & 1) * ACT_H * 2);
        #pragma unroll
        for (int t = 0; t < 9; t++) {
            const int dy = t / 3, dx = t - dy * 3;
            const uint32_t toff = (uint32_t)((dy * 34 + dx) * 48);
            uint32_t a0[4], a1[4];
            {
                size_t o = ((((size_t)t * nM16 + coT * 4 + warp_m * 2) * rounds + r)
                            * 32 + lane) * 8;
                uint4 v = *(const uint4*)(wf + o);
                a0[0] = v.x; a0[1] = v.y; a0[2] = v.z; a0[3] = v.w;
                v = *(const uint4*)(wf + o + (size_t)rounds * 256);
                a1[0] = v.x; a1[1] = v.y; a1[2] = v.z; a1[3] = v.w;
            }
            #pragma unroll
            for (int j = 0; j < 2; j++)
                #pragma unroll
                for (int xg = 0; xg < 2; xg++) {
                    uint32_t b[4];
                    ldm4(b, bufB + bRel[j][xg] + toff);
                    const int nb = j * 4 + xg * 2;
                    mma16(acc[0][nb], a0, b[0], b[1]);
                    mma16(acc[1][nb], a1, b[0], b[1]);
                    mma16(acc[0][nb + 1], a0, b[2], b[3]);
                    mma16(acc[1][nb + 1], a1, b[2], b[3]);
                }
        }
        __syncthreads();
    }

    #pragma unroll
    for (int mf = 0; mf < 2; mf++) {
        const int c0l = warp_m * 32 + mf * 16 + (lane >> 2);
        const float bb0 = bias[coT * 64 + c0l];
        const float bb1 = bias[coT * 64 + c0l + 8];
        #pragma unroll
        for (int nf = 0; nf < 8; nf++) {
            int px = (2 * warp_n + (nf >> 2)) * 32 + ((nf >> 1) & 1) * 16 +
                     (nf & 1) * 8 + (lane & 3) * 2;
            *(__half2*)&sh[c0l * 264 + px] =
                __floats2half2_rn(fmaxf(acc[mf][nf][0] + bb0, 0.f),
                                  fmaxf(acc[mf][nf][1] + bb0, 0.f));
            *(__half2*)&sh[(c0l + 8) * 264 + px] =
                __floats2half2_rn(fmaxf(acc[mf][nf][2] + bb1, 0.f),
                                  fmaxf(acc[mf][nf][3] + bb1, 0.f));
        }
    }
    __syncthreads();
    {
        const int px = tid;
        const int yy = px >> 5, xx = px & 31;
        __half* base = out + ((size_t)(be * Hh + y0 + yy) * Ww + (x0 + xx)) * Cout +
                       coT * 64;
        #pragma unroll
        for (int k = 0; k < 8; k++) {
            union { uint4 u; __half h[8]; } pk;
            #pragma unroll
            for (int j = 0; j < 8; j++) pk.h[j] = sh[(8 * k + j) * 264 + px];
            *(uint4*)&base[8 * k] = pk.u;
        }
    }
}

// 2x2 maxpool fp16 NHWC -> fp16 NHWC
__global__ void pool16_k(const __half* __restrict__ in, __half* __restrict__ out,
                         int total8, int Ho, int Wo, int C) {
    const int C8 = C >> 3;
    for (int i = blockIdx.x * blockDim.x + threadIdx.x; i < total8;
         i += gridDim.x * blockDim.x) {
        int c8 = i % C8;
        int t = i / C8;
        int x = t % Wo;
        t /= Wo;
        int y = t % Ho;
        int be = t / Ho;
        const __half* p =
            in + ((size_t)(be * 2 * Ho + 2 * y) * (2 * Wo) + 2 * x) * C + c8 * 8;
        union { uint4 u; __half2 h[4]; } a, b, c, d, rr;
        a.u = *(const uint4*)p;
        b.u = *(const uint4*)(p + C);
        c.u = *(const uint4*)(p + (size_t)2 * Wo * C);
        d.u = *(const uint4*)(p + (size_t)2 * Wo * C + C);
        #pragma unroll
        for (int j = 0; j < 4; j++)
            rr.h[j] = __hmax2(__hmax2(a.h[j], b.h[j]), __hmax2(c.h[j], d.h[j]));
        *(uint4*)&out[(size_t)i * 8] = rr.u;
    }
}

// NHWC fp16 -> NCHW fp16 pool planes (for perc + style)
__global__ void nhwc2nchw16_k(const __half* __restrict__ in,
                              __half* __restrict__ out,
                              int HWp, int C, int SZlevel) {
    __shared__ __half tl[32][34];
    const int px0 = blockIdx.x * 32, c0 = blockIdx.y * 32, be = blockIdx.z;
    const int tx = threadIdx.x, ty = threadIdx.y;
    for (int r = ty; r < 32; r += 8)
        tl[r][tx] = in[((size_t)be * HWp + px0 + r) * C + c0 + tx];
    __syncthreads();
    const int s = be >> 1, b = be & 1;
    __half* ob = out + (size_t)s * SZlevel + (size_t)b * C * HWp;
    for (int r = ty; r < 32; r += 8)
        ob[(size_t)(c0 + r) * HWp + px0 + tx] = tl[tx][r];
}

// perceptual: sum |out-gt| + |comp-gt| over fp16 planes -> g_acc[2]
__global__ void perc_sum16_k(const __half* __restrict__ aout,
                             const __half* __restrict__ agt,
                             const __half* __restrict__ acomp, int n8) {
    float s = 0.f;
    for (int i = blockIdx.x * blockDim.x + threadIdx.x; i < n8;
         i += gridDim.x * blockDim.x) {
        union { uint4 u; __half2 h[4]; } o, g, c;
        o.u = *(const uint4*)&aout[(size_t)i * 8];
        g.u = *(const uint4*)&agt[(size_t)i * 8];
        c.u = *(const uint4*)&acomp[(size_t)i * 8];
        #pragma unroll
        for (int j = 0; j < 4; j++) {
            float2 fo = __half22float2(o.h[j]);
            float2 fg = __half22float2(g.h[j]);
            float2 fc = __half22float2(c.h[j]);
            s += fabsf(fo.x - fg.x) + fabsf(fc.x - fg.x);
            s += fabsf(fo.y - fg.y) + fabsf(fc.y - fg.y);
        }
    }
    warp_atomic(&g_acc[2], s);
}

// ---------- style via fp16 mma: G = X^T X per (b,c) plane ----------
// grid (W/32, W/32, BN*C); block 256 = 8 warps (2 m x 4 n); 32x32 gram tile.
// K loop over H in chunks of 16. Planes are [h][w] fp16; ldmatrix.trans gives
// the [w][h] A fragment. Accumulates scale*|G_out-G_gt| and scale*|G_comp-G_gt|.
__global__ __launch_bounds__(256) void style_mma_k(
    const __half* __restrict__ Xout, const __half* __restrict__ Xgt,
    const __half* __restrict__ Xcomp, int Hs, int Ws, double scale) {
    __shared__ __align__(16) __half st[6][16][40];
    __shared__ float red[2][8];
    const int bc = blockIdx.z;
    const size_t off = (size_t)bc * Hs * Ws;
    const __half* P[3] = {Xout + off, Xgt + off, Xcomp + off};
    const int v0 = blockIdx.x * 32, w0 = blockIdx.y * 32;
    const int tid = threadIdx.x, wid = tid >> 5, lane = tid & 31;
    const int warp_m = wid >> 2, warp_n = wid & 3;
    const int l7 = lane & 7, qd = lane >> 3;

    float cO[4] = {0, 0, 0, 0}, cG[4] = {0, 0, 0, 0}, cC[4] = {0, 0, 0, 0};

    const uint32_t stb = smem_u32(st);
    // A (trans): mat qd -> (m_off=(qd&1)*8, k_off=(qd>>1)*8); lane row = k_off+l7
    uint32_t aA[3], bA[3];
    #pragma unroll
    for (int s = 0; s < 3; s++) {
        aA[s] = stb + (uint32_t)(((s * 16 + (qd >> 1) * 8 + l7) * 40 +
                                  warp_m * 16 + (qd & 1) * 8) * 2);
        // B (trans, x2): mat qd&1 -> k block; col = warp_n*8
        bA[s] = stb + (uint32_t)((((3 + s) * 16 + (qd & 1) * 8 + l7) * 40 +
                                  warp_n * 8) * 2);
    }

    for (int h0 = 0; h0 < Hs; h0 += 16) {
        // stage 6 tiles (3 streams x {w-cols, v-cols}), 16 h x 32 cols each
        for (int idx = tid; idx < 384; idx += 256) {
            int t = idx >> 6, rr = idx & 63;
            int kk = rr >> 2, c8 = (rr & 3) * 8;
            const __half* src =
                P[t % 3] + (size_t)(h0 + kk) * Ws + ((t < 3) ? w0 : v0) + c8;
            cp16(stb + (uint32_t)(((t * 16 + kk) * 40 + c8) * 2), src, 16);
        }
        asm volatile("cp.async.commit_group;");
        asm volatile("cp.async.wait_group 0;");
        __syncthreads();

        uint32_t a[4], b[2];
        ldm4t(a, aA[0]); ldm2t(b, bA[0]); mma16(cO, a, b[0], b[1]);
        ldm4t(a, aA[1]); ldm2t(b, bA[1]); mma16(cG, a, b[0], b[1]);
        ldm4t(a, aA[2]); ldm2t(b, bA[2]); mma16(cC, a, b[0], b[1]);
        __syncthreads();
    }

    float sO = 0.f, sC = 0.f;
    #pragma unroll
    for (int q = 0; q < 4; q++) {
        sO += fabsf(cO[q] - cG[q]);
        sC += fabsf(cC[q] - cG[q]);
    }
    #pragma unroll
    for (int o = 16; o > 0; o >>= 1) {
        sO += __shfl_down_sync(0xffffffffu, sO, o);
        sC += __shfl_down_sync(0xffffffffu, sC, o);
    }
    if (lane == 0) { red[0][wid] = sO; red[1][wid] = sC; }
    __syncthreads();
    if (tid == 0) {
        double tO = 0.0, tC = 0.0;
        #pragma unroll
        for (int j = 0; j < 8; j++) { tO += red[0][j]; tC += red[1][j]; }
        atomicAdd(&g_acc[3], scale * tO);
        atomicAdd(&g_acc[4], scale * tC);
    }
}

__global__ void finalize_k(float* out) {
    if (threadIdx.x == 0 && blockIdx.x == 0) {
        const double N = 3.0 * 512.0 * 512.0 * (double)BN;
        const double Nigt = (double)SZ1;
        double l = (double)BN * g_acc[0] / N
                 + g_acc[1] / N
                 + g_acc[2] / Nigt
                 + g_acc[3]
                 + g_acc[4];
        out[0] = (float)l;
    }
}

// ---------------- host launcher ----------------
extern "C" void kernel_launch(void* const* d_in, const int* in_sizes, int n_in,
                              void* d_out, int out_size) {
    (void)in_sizes; (void)n_in; (void)out_size;
    const float* igt  = (const float*)d_in[0];
    const float* iout = (const float*)d_in[1];
    const float* mask = (const float*)d_in[2];
    const float* w[7];
    const float* bb[7];
    for (int i = 0; i < 7; i++) {
        w[i]  = (const float*)d_in[3 + 2 * i];
        bb[i] = (const float*)d_in[4 + 2 * i];
    }

    __half *hA, *hB, *hp, *w16b, *q1, *q2, *q3;
    float *comp, *wT1;
    cudaGetSymbolAddress((void**)&hA, g_hA);
    cudaGetSymbolAddress((void**)&hB, g_hB);
    cudaGetSymbolAddress((void**)&hp, g_hp);
    cudaGetSymbolAddress((void**)&comp, g_comp);
    cudaGetSymbolAddress((void**)&wT1, g_wT1);
    cudaGetSymbolAddress((void**)&w16b, g_w16);
    cudaGetSymbolAddress((void**)&q1, g_q1);
    cudaGetSymbolAddress((void**)&q2, g_q2);
    cudaGetSymbolAddress((void**)&q3, g_q3);

    const int cins[7]  = {3, 64, 64, 128, 128, 256, 256};
    const int couts[7] = {64, 64, 128, 128, 256, 256, 256};
    __half* w16[7];
    size_t ofs = 0;
    for (int i = 1; i < 7; i++) {
        w16[i] = w16b + ofs;
        ofs += (size_t)cins[i] * couts[i] * 9;
    }

    // stream planes: s0 = gt, s1 = out, s2 = comp
    __half* Q1[3] = {q1, q1 + SZ1, q1 + 2 * (size_t)SZ1};
    __half* Q2[3] = {q2, q2 + SZ2, q2 + 2 * (size_t)SZ2};
    __half* Q3[3] = {q3, q3 + SZ3, q3 + 2 * (size_t)SZ3};

    zero_acc_k<<<1, 32>>>();
    wtrans1_k<<<32, 256>>>(w[0], wT1, 3, 64);
    for (int i = 1; i < 7; i++)
        wtransfrag_k<<<256, 256>>>(w[i], w16[i], cins[i], couts[i]);
    comp_l1_k<<<1024, 256>>>(igt, iout, mask);

    conv1_k<<<dim3(32, 32, 6 * 2), 256>>>(igt, iout, comp, wT1, bb[0],
                                          hA, 3, 64, 512, 512);
    conv_mma16b_k<<<dim3(16, 64, 6), 256>>>(hA, w16[1], bb[1], hB, 64, 64, 512, 512);
    pool16_k<<<8192, 256>>>(hB, hp, 6 * 256 * 256 * 8, 256, 256, 64);
    nhwc2nchw16_k<<<dim3(2048, 2, 6), dim3(32, 8)>>>(hp, q1, 65536, 64, SZ1);
    conv_mma16b_k<<<dim3(8, 32, 12), 256>>>(hp, w16[2], bb[2], hA, 64, 128, 256, 256);
    conv_mma16b_k<<<dim3(8, 32, 12), 256>>>(hA, w16[3], bb[3], hB, 128, 128, 256, 256);
    pool16_k<<<4096, 256>>>(hB, hp, 6 * 128 * 128 * 16, 128, 128, 128);
    nhwc2nchw16_k<<<dim3(512, 4, 6), dim3(32, 8)>>>(hp, q2, 16384, 128, SZ2);
    conv_mma16b_k<<<dim3(4, 16, 24), 256>>>(hp, w16[4], bb[4], hA, 128, 256, 128, 128);
    conv_mma16b_k<<<dim3(4, 16, 24), 256>>>(hA, w16[5], bb[5], hB, 256, 256, 128, 128);
    conv_mma16b_k<<<dim3(4, 16, 24), 256>>>(hB, w16[6], bb[6], hA, 256, 256, 128, 128);
    pool16_k<<<2048, 256>>>(hA, hp, 6 * 64 * 64 * 32, 64, 64, 256);
    nhwc2nchw16_k<<<dim3(128, 8, 6), dim3(32, 8)>>>(hp, q3, 4096, 256, SZ3);

    perc_sum16_k<<<2048, 256>>>(Q1[1], Q1[0], Q1[2], SZ1 / 8);
    perc_sum16_k<<<1024, 256>>>(Q2[1], Q2[0], Q2[2], SZ2 / 8);
    perc_sum16_k<<<512, 256>>>(Q3[1], Q3[0], Q3[2], SZ3 / 8);

    // scale = Kp / C^2 = 1/(C*H*W) / C^2
    style_mma_k<<<dim3(8, 8, BN * 64), 256>>>(Q1[1], Q1[0], Q1[2], 256, 256,
                                              1.0 / (4194304.0 * 4096.0));
    style_mma_k<<<dim3(4, 4, BN * 128), 256>>>(Q2[1], Q2[0], Q2[2], 128, 128,
                                               1.0 / (2097152.0 * 16384.0));
    style_mma_k<<<dim3(2, 2, BN * 256), 256>>>(Q3[1], Q3[0], Q3[2], 64, 64,
                                               1.0 / (1048576.0 * 65536.0));

    finalize_k<<<1, 32>>>((float*)d_out);
}

// round 13
// speedup vs baseline: 5.2753x; 1.0439x over previous
#include <cuda_runtime.h>
#include <cuda_fp16.h>
#include <math.h>
#include <stdint.h>

#define BN 2
#define CI_T 8

// ---------------- static scratch (no allocations allowed) ----------------
__device__ __half g_hA[6 * 64 * 512 * 512];      // NHWC fp16 ping
__device__ __half g_hB[6 * 64 * 512 * 512];      // NHWC fp16 pong
__device__ __half g_hp[6 * 64 * 256 * 256];      // NHWC fp16 pooled
__device__ float  g_comp[BN * 3 * 512 * 512];
__device__ float  g_wT1[1728];                   // layer-1 weights (fp32)
__device__ __half g_w16[1732608];                // layers 2-7 weights, A-fragment order

#define SZ1 (BN * 64 * 256 * 256)
#define SZ2 (BN * 128 * 128 * 128)
#define SZ3 (BN * 256 * 64 * 64)
// fp16 NCHW pool planes per stream: [gt, out, comp]
__device__ __half g_q1[3][SZ1];
__device__ __half g_q2[3][SZ2];
__device__ __half g_q3[3][SZ3];

__device__ double g_acc[8];

// ---------------- helpers ----------------
__device__ __forceinline__ unsigned long long pk2(float a, float b) {
    unsigned long long r;
    asm("mov.b64 %0, {%1, %2};" : "=l"(r) : "f"(a), "f"(b));
    return r;
}
__device__ __forceinline__ unsigned long long fma_x2(unsigned long long a,
                                                     unsigned long long b,
                                                     unsigned long long c) {
    unsigned long long d;
    asm("fma.rn.f32x2 %0, %1, %2, %3;" : "=l"(d) : "l"(a), "l"(b), "l"(c));
    return d;
}
__device__ __forceinline__ void upk(unsigned long long v, float& lo, float& hi) {
    asm("mov.b64 {%0, %1}, %2;" : "=f"(lo), "=f"(hi) : "l"(v));
}
__device__ __forceinline__ uint32_t smem_u32(const void* p) {
    return (uint32_t)__cvta_generic_to_shared(p);
}
__device__ __forceinline__ void ldm4(uint32_t* r, uint32_t addr) {
    asm volatile("ldmatrix.sync.aligned.m8n8.x4.shared.b16 {%0,%1,%2,%3}, [%4];"
                 : "=r"(r[0]), "=r"(r[1]), "=r"(r[2]), "=r"(r[3]) : "r"(addr));
}
__device__ __forceinline__ void ldm4t(uint32_t* r, uint32_t addr) {
    asm volatile("ldmatrix.sync.aligned.m8n8.x4.trans.shared.b16 {%0,%1,%2,%3}, [%4];"
                 : "=r"(r[0]), "=r"(r[1]), "=r"(r[2]), "=r"(r[3]) : "r"(addr));
}
__device__ __forceinline__ void ldm2t(uint32_t* r, uint32_t addr) {
    asm volatile("ldmatrix.sync.aligned.m8n8.x2.trans.shared.b16 {%0,%1}, [%2];"
                 : "=r"(r[0]), "=r"(r[1]) : "r"(addr));
}
__device__ __forceinline__ void mma16(float* c, const uint32_t* a,
                                      uint32_t b0, uint32_t b1) {
    asm volatile(
        "mma.sync.aligned.m16n8k16.row.col.f32.f16.f16.f32 "
        "{%0,%1,%2,%3}, {%4,%5,%6,%7}, {%8,%9}, {%0,%1,%2,%3};"
        : "+f"(c[0]), "+f"(c[1]), "+f"(c[2]), "+f"(c[3])
        : "r"(a[0]), "r"(a[1]), "r"(a[2]), "r"(a[3]), "r"(b0), "r"(b1));
}
__device__ __forceinline__ void cp16(uint32_t dst, const void* src, int srcsize) {
    asm volatile("cp.async.ca.shared.global [%0], [%1], 16, %2;"
                 :: "r"(dst), "l"(src), "r"(srcsize));
}
__device__ __forceinline__ void warp_atomic(double* dst, float v) {
    #pragma unroll
    for (int o = 16; o > 0; o >>= 1) v += __shfl_down_sync(0xffffffffu, v, o);
    if ((threadIdx.x & 31) == 0) atomicAdd(dst, (double)v);
}

// ---------------- kernels ----------------

// single weight-prep kernel: zero accs, layer-1 fp32 transpose, layers 2-7
// A-fragment fp16 pack
__global__ void wprep_k(const float* __restrict__ w0, const float* __restrict__ w1,
                        const float* __restrict__ w2, const float* __restrict__ w3,
                        const float* __restrict__ w4, const float* __restrict__ w5,
                        const float* __restrict__ w6,
                        float* __restrict__ wT1, __half* __restrict__ wfb) {
    const int tid0 = blockIdx.x * blockDim.x + threadIdx.x;
    const int stride = gridDim.x * blockDim.x;
    if (tid0 < 8) g_acc[tid0] = 0.0;
    for (int i = tid0; i < 1728; i += stride) {
        int co = i & 63;
        int t = i >> 6;
        int k = t % 9, ci = t / 9;
        wT1[i] = w0[(co * 3 + ci) * 9 + k];
    }
    const float* ws[6] = {w1, w2, w3, w4, w5, w6};
    const int cins[6] = {64, 64, 128, 128, 256, 256};
    const int couts[6] = {64, 128, 128, 256, 256, 256};
    size_t ofs = 0;
    for (int L = 0; L < 6; L++) {
        const int Cin = cins[L], Cout = couts[L];
        const int rounds = Cin >> 4, nM16 = Cout >> 4;
        const int n = 9 * Cin * Cout;
        const float* w = ws[L];
        __half* wf = wfb + ofs;
        for (int i = tid0; i < n; i += stride) {
            int h = i & 7, lane = (i >> 3) & 31;
            int rest = i >> 8;
            int r = rest % rounds;
            rest /= rounds;
            int m16 = rest % nM16;
            int t = rest / nM16;
            int pair = h >> 1, lo = h & 1;
            int row = (lane >> 2) + (pair & 1) * 8;
            int ci = r * 16 + (lane & 3) * 2 + (pair >> 1) * 8 + lo;
            int cco = m16 * 16 + row;
            wf[i] = __float2half_rn(w[((size_t)cco * Cin + ci) * 9 + t]);
        }
        ofs += n;
    }
}

// icomp + hole/valid L1 partial sums
__global__ void comp_l1_k(const float* __restrict__ igt,
                          const float* __restrict__ iout,
                          const float* __restrict__ mask) {
    const int n = BN * 3 * 512 * 512;
    const int hw = 512 * 512;
    float h = 0.f, v = 0.f;
    for (int i = blockIdx.x * blockDim.x + threadIdx.x; i < n;
         i += gridDim.x * blockDim.x) {
        int pix = i % hw;
        int b = (i / hw) / 3;
        float m = (mask[b * hw + pix] != 0.0f) ? 1.0f : 0.0f;
        float gt = igt[i], ot = iout[i];
        float d = ot - gt;
        h += fabsf((1.0f - m) * d);
        v += fabsf(m * d);
        g_comp[i] = (m == 1.0f) ? gt : ot;
    }
    warp_atomic(&g_acc[0], h);
    warp_atomic(&g_acc[1], v);
}

// ---------- FFMA2 conv layer 1 (Cin=3, fp32 NCHW in, fp16 NHWC out) ----------
__global__ __launch_bounds__(256, 3) void conv1_k(
    const float* __restrict__ in0, const float* __restrict__ in1,
    const float* __restrict__ in2,
    const float* __restrict__ wT, const float* __restrict__ bias,
    __half* __restrict__ out, int Cin, int Cout, int Hh, int Ww) {
    __shared__ __align__(16) float s_in[CI_T][18][20];
    __shared__ __align__(16) float s_w[CI_T][9][32];

    const int nCoT = Cout >> 5;
    const int coT = blockIdx.z % nCoT;
    const int be = blockIdx.z / nCoT;
    const int x0 = blockIdx.x * 16, y0 = blockIdx.y * 16;
    const int tid = threadIdx.x;
    const int p = tid & 63;
    const int g = tid >> 6;
    const int px = (p & 7) * 2, py = (p >> 3) * 2;
    const int g8 = g * 8;
    const size_t HW = (size_t)Hh * Ww;

    int s = be >> 1;
    const float* sp = (s == 0) ? in0 : ((s == 1) ? in1 : in2);
    const float* inB = sp + (size_t)(be & 1) * Cin * HW;

    unsigned long long acc[4][4];
    #pragma unroll
    for (int c = 0; c < 4; c++)
        #pragma unroll
        for (int q = 0; q < 4; q++) acc[c][q] = 0ull;

    const int rounds = (Cin + CI_T - 1) / CI_T;
    for (int r = 0; r < rounds; r++) {
        const int c0 = r * CI_T;
        for (int idx = tid; idx < CI_T * 324; idx += 256) {
            int q = idx / 324, rr = idx - q * 324;
            int iy = rr / 18, ix = rr - iy * 18;
            int ci = c0 + q;
            int gy = y0 + iy - 1, gx = x0 + ix - 1;
            float v = 0.f;
            if (ci < Cin && gy >= 0 && gy < Hh && gx >= 0 && gx < Ww)
                v = inB[(size_t)ci * HW + gy * Ww + gx];
            s_in[q][iy][ix] = v;
        }
        for (int idx = tid; idx < CI_T * 288; idx += 256) {
            int co = idx & 31;
            int t = idx >> 5;
            int k = t % 9, q = t / 9;
            int ci = c0 + q;
            float v = 0.f;
            if (ci < Cin) v = wT[((size_t)ci * 9 + k) * Cout + coT * 32 + co];
            s_w[q][k][co] = v;
        }
        __syncthreads();

        #pragma unroll 2
        for (int q = 0; q < CI_T; q++) {
            unsigned long long xx[4][4];
            #pragma unroll
            for (int dy = 0; dy < 4; dy++) {
                float2 a = *(const float2*)&s_in[q][py + dy][px];
                float2 b = *(const float2*)&s_in[q][py + dy][px + 2];
                xx[dy][0] = pk2(a.x, a.x);
                xx[dy][1] = pk2(a.y, a.y);
                xx[dy][2] = pk2(b.x, b.x);
                xx[dy][3] = pk2(b.y, b.y);
            }
            #pragma unroll
            for (int ky = 0; ky < 3; ky++)
                #pragma unroll
                for (int kx = 0; kx < 3; kx++) {
                    const int k = ky * 3 + kx;
                    float2 wa = *(const float2*)&s_w[q][k][g8];
                    float2 wb = *(const float2*)&s_w[q][k][g8 + 2];
                    float2 wc = *(const float2*)&s_w[q][k][g8 + 4];
                    float2 wd = *(const float2*)&s_w[q][k][g8 + 6];
                    unsigned long long w0 = pk2(wa.x, wa.y);
                    unsigned long long w1 = pk2(wb.x, wb.y);
                    unsigned long long w2 = pk2(wc.x, wc.y);
                    unsigned long long w3 = pk2(wd.x, wd.y);
                    #pragma unroll
                    for (int sy = 0; sy < 2; sy++)
                        #pragma unroll
                        for (int sx = 0; sx < 2; sx++) {
                            unsigned long long xf = xx[sy + ky][sx + kx];
                            const int pid = sy * 2 + sx;
                            acc[0][pid] = fma_x2(xf, w0, acc[0][pid]);
                            acc[1][pid] = fma_x2(xf, w1, acc[1][pid]);
                            acc[2][pid] = fma_x2(xf, w2, acc[2][pid]);
                            acc[3][pid] = fma_x2(xf, w3, acc[3][pid]);
                        }
                }
        }
        __syncthreads();
    }

    const int coBase = coT * 32 + g8;
    float bb[8];
    #pragma unroll
    for (int j = 0; j < 8; j++) bb[j] = bias[coBase + j];
    #pragma unroll
    for (int sy = 0; sy < 2; sy++)
        #pragma unroll
        for (int sx = 0; sx < 2; sx++) {
            int y = y0 + py + sy, x = x0 + px + sx;
            const int pid = sy * 2 + sx;
            union { uint4 u; __half2 h[4]; } pk;
            #pragma unroll
            for (int cp = 0; cp < 4; cp++) {
                float lo, hi;
                upk(acc[cp][pid], lo, hi);
                pk.h[cp] = __floats2half2_rn(fmaxf(lo + bb[2 * cp], 0.f),
                                             fmaxf(hi + bb[2 * cp + 1], 0.f));
            }
            *(uint4*)&out[((size_t)(be * Hh + y) * Ww + x) * Cout + coBase] = pk.u;
        }
}

// ---------- fp16 mma conv, co-tile 64 (layer 2 only) ----------
#define ACT_H 8160   // halves per buffer (340*24)
__global__ __launch_bounds__(256) void conv_mma16b_k(
    const __half* __restrict__ in, const __half* __restrict__ wf,
    const float* __restrict__ bias, __half* __restrict__ out,
    int Cin, int Cout, int Hh, int Ww) {
    __shared__ __align__(16) __half sh[16896];   // max(2*8160, 64*264)

    const int nCoT = Cout >> 6;
    const int nM16 = Cout >> 4;
    const int coT = blockIdx.z % nCoT;
    const int be = blockIdx.z / nCoT;
    const int x0 = blockIdx.x * 32, y0 = blockIdx.y * 8;
    const int tid = threadIdx.x, wid = tid >> 5, lane = tid & 31;
    const int warp_m = wid >> 2, warp_n = wid & 3;
    const int rounds = Cin >> 4;

    float acc[2][8][4];
    #pragma unroll
    for (int mf = 0; mf < 2; mf++)
        #pragma unroll
        for (int nf = 0; nf < 8; nf++)
            #pragma unroll
            for (int q = 0; q < 4; q++) acc[mf][nf][q] = 0.f;

    const uint32_t sxb = smem_u32(sh);
    const int l7 = lane & 7, qd = lane >> 3;
    const int b_xx = ((qd >> 1) & 1) * 8 + l7;
    const int b_k = (qd & 1) * 8;
    uint32_t bRel[2][2];
    #pragma unroll
    for (int j = 0; j < 2; j++)
        #pragma unroll
        for (int xg = 0; xg < 2; xg++)
            bRel[j][xg] = (uint32_t)(
                (((2 * warp_n + j) * 34 + xg * 16 + b_xx) * 24 + b_k) * 2);

    {
        for (int idx = tid; idx < 680; idx += 256) {
            int cell = idx >> 1, hh = idx & 1;
            int yy = cell / 34, xx = cell - yy * 34;
            int gy = y0 + yy - 1, gx = x0 + xx - 1;
            bool ok = (gy >= 0 && gy < Hh && gx >= 0 && gx < Ww);
            const __half* src = ok
                ? &in[((size_t)(be * Hh + gy) * Ww + gx) * Cin + hh * 8]
                : in;
            cp16(sxb + (uint32_t)((cell * 24 + hh * 8) * 2), src, ok ? 16 : 0);
        }
        asm volatile("cp.async.commit_group;");
    }

    for (int r = 0; r < rounds; r++) {
        asm volatile("cp.async.wait_group 0;");
        __syncthreads();
        if (r + 1 < rounds) {
            const int ci0 = (r + 1) << 4;
            const uint32_t dbase = sxb + (uint32_t)(((r + 1) & 1) * ACT_H * 2);
            for (int idx = tid; idx < 680; idx += 256) {
                int cell = idx >> 1, hh = idx & 1;
                int yy = cell / 34, xx = cell - yy * 34;
                int gy = y0 + yy - 1, gx = x0 + xx - 1;
                bool ok = (gy >= 0 && gy < Hh && gx >= 0 && gx < Ww);
                const __half* src = ok
                    ? &in[((size_t)(be * Hh + gy) * Ww + gx) * Cin + ci0 + hh * 8]
                    : in;
                cp16(dbase + (uint32_t)((cell * 24 + hh * 8) * 2), src, ok ? 16 : 0);
            }
            asm volatile("cp.async.commit_group;");
        }

        const uint32_t bufB = sxb + (uint32_t)((r & 1) * ACT_H * 2);
        #pragma unroll
        for (int t = 0; t < 9; t++) {
            const int dy = t / 3, dx = t - dy * 3;
            const uint32_t toff = (uint32_t)((dy * 34 + dx) * 48);
            uint32_t a0[4], a1[4];
            {
                size_t o = ((((size_t)t * nM16 + coT * 4 + warp_m * 2) * rounds + r)
                            * 32 + lane) * 8;
                uint4 v = *(const uint4*)(wf + o);
                a0[0] = v.x; a0[1] = v.y; a0[2] = v.z; a0[3] = v.w;
                v = *(const uint4*)(wf + o + (size_t)rounds * 256);
                a1[0] = v.x; a1[1] = v.y; a1[2] = v.z; a1[3] = v.w;
            }
            #pragma unroll
            for (int j = 0; j < 2; j++)
                #pragma unroll
                for (int xg = 0; xg < 2; xg++) {
                    uint32_t b[4];
                    ldm4(b, bufB + bRel[j][xg] + toff);
                    const int nb = j * 4 + xg * 2;
                    mma16(acc[0][nb], a0, b[0], b[1]);
                    mma16(acc[1][nb], a1, b[0], b[1]);
                    mma16(acc[0][nb + 1], a0, b[2], b[3]);
                    mma16(acc[1][nb + 1], a1, b[2], b[3]);
                }
        }
        __syncthreads();
    }

    #pragma unroll
    for (int mf = 0; mf < 2; mf++) {
        const int c0l = warp_m * 32 + mf * 16 + (lane >> 2);
        const float bb0 = bias[coT * 64 + c0l];
        const float bb1 = bias[coT * 64 + c0l + 8];
        #pragma unroll
        for (int nf = 0; nf < 8; nf++) {
            int px = (2 * warp_n + (nf >> 2)) * 32 + ((nf >> 1) & 1) * 16 +
                     (nf & 1) * 8 + (lane & 3) * 2;
            *(__half2*)&sh[c0l * 264 + px] =
                __floats2half2_rn(fmaxf(acc[mf][nf][0] + bb0, 0.f),
                                  fmaxf(acc[mf][nf][1] + bb0, 0.f));
            *(__half2*)&sh[(c0l + 8) * 264 + px] =
                __floats2half2_rn(fmaxf(acc[mf][nf][2] + bb1, 0.f),
                                  fmaxf(acc[mf][nf][3] + bb1, 0.f));
        }
    }
    __syncthreads();
    {
        const int px = tid;
        const int yy = px >> 5, xx = px & 31;
        __half* base = out + ((size_t)(be * Hh + y0 + yy) * Ww + (x0 + xx)) * Cout +
                       coT * 64;
        #pragma unroll
        for (int k = 0; k < 8; k++) {
            union { uint4 u; __half h[8]; } pk;
            #pragma unroll
            for (int j = 0; j < 8; j++) pk.h[j] = sh[(8 * k + j) * 264 + px];
            *(uint4*)&base[8 * k] = pk.u;
        }
    }
}

// ---------- fp16 mma conv, co-tile 128 (layers 3-7) ----------
__global__ __launch_bounds__(256) void conv_mma128_k(
    const __half* __restrict__ in, const __half* __restrict__ wf,
    const float* __restrict__ bias, __half* __restrict__ out,
    int Cin, int Cout, int Hh, int Ww) {
    __shared__ __align__(16) __half sh[16896];

    const int nCoT = Cout >> 7;
    const int nM16 = Cout >> 4;
    const int coT = blockIdx.z % nCoT;
    const int be = blockIdx.z / nCoT;
    const int x0 = blockIdx.x * 32, y0 = blockIdx.y * 8;
    const int tid = threadIdx.x, wid = tid >> 5, lane = tid & 31;
    const int warp_m = wid >> 2, warp_n = wid & 3;
    const int rounds = Cin >> 4;

    float acc[4][8][4];   // [m-frag][n-frag][quad]
    #pragma unroll
    for (int mf = 0; mf < 4; mf++)
        #pragma unroll
        for (int nf = 0; nf < 8; nf++)
            #pragma unroll
            for (int q = 0; q < 4; q++) acc[mf][nf][q] = 0.f;

    const uint32_t sxb = smem_u32(sh);
    const int l7 = lane & 7, qd = lane >> 3;
    const int b_xx = ((qd >> 1) & 1) * 8 + l7;
    const int b_k = (qd & 1) * 8;
    uint32_t bRel[2][2];
    #pragma unroll
    for (int j = 0; j < 2; j++)
        #pragma unroll
        for (int xg = 0; xg < 2; xg++)
            bRel[j][xg] = (uint32_t)(
                (((2 * warp_n + j) * 34 + xg * 16 + b_xx) * 24 + b_k) * 2);

    {
        for (int idx = tid; idx < 680; idx += 256) {
            int cell = idx >> 1, hh = idx & 1;
            int yy = cell / 34, xx = cell - yy * 34;
            int gy = y0 + yy - 1, gx = x0 + xx - 1;
            bool ok = (gy >= 0 && gy < Hh && gx >= 0 && gx < Ww);
            const __half* src = ok
                ? &in[((size_t)(be * Hh + gy) * Ww + gx) * Cin + hh * 8]
                : in;
            cp16(sxb + (uint32_t)((cell * 24 + hh * 8) * 2), src, ok ? 16 : 0);
        }
        asm volatile("cp.async.commit_group;");
    }

    for (int r = 0; r < rounds; r++) {
        asm volatile("cp.async.wait_group 0;");
        __syncthreads();
        if (r + 1 < rounds) {
            const int ci0 = (r + 1) << 4;
            const uint32_t dbase = sxb + (uint32_t)(((r + 1) & 1) * ACT_H * 2);
            for (int idx = tid; idx < 680; idx += 256) {
                int cell = idx >> 1, hh = idx & 1;
                int yy = cell / 34, xx = cell - yy * 34;
                int gy = y0 + yy - 1, gx = x0 + xx - 1;
                bool ok = (gy >= 0 && gy < Hh && gx >= 0 && gx < Ww);
                const __half* src = ok
                    ? &in[((size_t)(be * Hh + gy) * Ww + gx) * Cin + ci0 + hh * 8]
                    : in;
                cp16(dbase + (uint32_t)((cell * 24 + hh * 8) * 2), src, ok ? 16 : 0);
            }
            asm volatile("cp.async.commit_group;");
        }

        const uint32_t bufB = sxb + (uint32_t)((r & 1) * ACT_H * 2);
        #pragma unroll
        for (int t = 0; t < 9; t++) {
            const int dy = t / 3, dx = t - dy * 3;
            const uint32_t toff = (uint32_t)((dy * 34 + dx) * 48);
            uint32_t a[4][4];
            {
                size_t o = ((((size_t)t * nM16 + coT * 8 + warp_m * 4) * rounds + r)
                            * 32 + lane) * 8;
                #pragma unroll
                for (int mf = 0; mf < 4; mf++) {
                    uint4 v = *(const uint4*)(wf + o + (size_t)mf * rounds * 256);
                    a[mf][0] = v.x; a[mf][1] = v.y; a[mf][2] = v.z; a[mf][3] = v.w;
                }
            }
            #pragma unroll
            for (int j = 0; j < 2; j++)
                #pragma unroll
                for (int xg = 0; xg < 2; xg++) {
                    uint32_t b[4];
                    ldm4(b, bufB + bRel[j][xg] + toff);
                    const int nb = j * 4 + xg * 2;
                    #pragma unroll
                    for (int mf = 0; mf < 4; mf++) {
                        mma16(acc[mf][nb], a[mf], b[0], b[1]);
                        mma16(acc[mf][nb + 1], a[mf], b[2], b[3]);
                    }
                }
        }
        __syncthreads();
    }

    // epilogue in two 64-channel passes (smem stays 64x264)
    #pragma unroll
    for (int pass = 0; pass < 2; pass++) {
        if (warp_m == pass) {
            #pragma unroll
            for (int mf = 0; mf < 4; mf++) {
                const int c0l = mf * 16 + (lane >> 2);   // local row 0..63
                const float bb0 = bias[coT * 128 + pass * 64 + c0l];
                const float bb1 = bias[coT * 128 + pass * 64 + c0l + 8];
                #pragma unroll
                for (int nf = 0; nf < 8; nf++) {
                    int px = (2 * warp_n + (nf >> 2)) * 32 + ((nf >> 1) & 1) * 16 +
                             (nf & 1) * 8 + (lane & 3) * 2;
                    *(__half2*)&sh[c0l * 264 + px] =
                        __floats2half2_rn(fmaxf(acc[mf][nf][0] + bb0, 0.f),
                                          fmaxf(acc[mf][nf][1] + bb0, 0.f));
                    *(__half2*)&sh[(c0l + 8) * 264 + px] =
                        __floats2half2_rn(fmaxf(acc[mf][nf][2] + bb1, 0.f),
                                          fmaxf(acc[mf][nf][3] + bb1, 0.f));
                }
            }
        }
        __syncthreads();
        {
            const int px = tid;
            const int yy = px >> 5, xx = px & 31;
            __half* base = out +
                ((size_t)(be * Hh + y0 + yy) * Ww + (x0 + xx)) * Cout +
                coT * 128 + pass * 64;
            #pragma unroll
            for (int k = 0; k < 8; k++) {
                union { uint4 u; __half h[8]; } pk;
                #pragma unroll
                for (int j = 0; j < 8; j++) pk.h[j] = sh[(8 * k + j) * 264 + px];
                *(uint4*)&base[8 * k] = pk.u;
            }
        }
        __syncthreads();
    }
}

// 2x2 maxpool fp16 NHWC -> fp16 NHWC
__global__ void pool16_k(const __half* __restrict__ in, __half* __restrict__ out,
                         int total8, int Ho, int Wo, int C) {
    const int C8 = C >> 3;
    for (int i = blockIdx.x * blockDim.x + threadIdx.x; i < total8;
         i += gridDim.x * blockDim.x) {
        int c8 = i % C8;
        int t = i / C8;
        int x = t % Wo;
        t /= Wo;
        int y = t % Ho;
        int be = t / Ho;
        const __half* p =
            in + ((size_t)(be * 2 * Ho + 2 * y) * (2 * Wo) + 2 * x) * C + c8 * 8;
        union { uint4 u; __half2 h[4]; } a, b, c, d, rr;
        a.u = *(const uint4*)p;
        b.u = *(const uint4*)(p + C);
        c.u = *(const uint4*)(p + (size_t)2 * Wo * C);
        d.u = *(const uint4*)(p + (size_t)2 * Wo * C + C);
        #pragma unroll
        for (int j = 0; j < 4; j++)
            rr.h[j] = __hmax2(__hmax2(a.h[j], b.h[j]), __hmax2(c.h[j], d.h[j]));
        *(uint4*)&out[(size_t)i * 8] = rr.u;
    }
}

// NHWC fp16 -> NCHW fp16 pool planes (for perc + style)
__global__ void nhwc2nchw16_k(const __half* __restrict__ in,
                              __half* __restrict__ out,
                              int HWp, int C, int SZlevel) {
    __shared__ __half tl[32][34];
    const int px0 = blockIdx.x * 32, c0 = blockIdx.y * 32, be = blockIdx.z;
    const int tx = threadIdx.x, ty = threadIdx.y;
    for (int r = ty; r < 32; r += 8)
        tl[r][tx] = in[((size_t)be * HWp + px0 + r) * C + c0 + tx];
    __syncthreads();
    const int s = be >> 1, b = be & 1;
    __half* ob = out + (size_t)s * SZlevel + (size_t)b * C * HWp;
    for (int r = ty; r < 32; r += 8)
        ob[(size_t)(c0 + r) * HWp + px0 + tx] = tl[tx][r];
}

// perceptual: sum |out-gt| + |comp-gt| over fp16 planes -> g_acc[2]
__global__ void perc_sum16_k(const __half* __restrict__ aout,
                             const __half* __restrict__ agt,
                             const __half* __restrict__ acomp, int n8) {
    float s = 0.f;
    for (int i = blockIdx.x * blockDim.x + threadIdx.x; i < n8;
         i += gridDim.x * blockDim.x) {
        union { uint4 u; __half2 h[4]; } o, g, c;
        o.u = *(const uint4*)&aout[(size_t)i * 8];
        g.u = *(const uint4*)&agt[(size_t)i * 8];
        c.u = *(const uint4*)&acomp[(size_t)i * 8];
        #pragma unroll
        for (int j = 0; j < 4; j++) {
            float2 fo = __half22float2(o.h[j]);
            float2 fg = __half22float2(g.h[j]);
            float2 fc = __half22float2(c.h[j]);
            s += fabsf(fo.x - fg.x) + fabsf(fc.x - fg.x);
            s += fabsf(fo.y - fg.y) + fabsf(fc.y - fg.y);
        }
    }
    warp_atomic(&g_acc[2], s);
}

// ---------- style via fp16 mma: G = X^T X per (b,c) plane ----------
__global__ __launch_bounds__(256) void style_mma_k(
    const __half* __restrict__ Xout, const __half* __restrict__ Xgt,
    const __half* __restrict__ Xcomp, int Hs, int Ws, double scale) {
    __shared__ __align__(16) __half st[6][16][40];
    __shared__ float red[2][8];
    const int bc = blockIdx.z;
    const size_t off = (size_t)bc * Hs * Ws;
    const __half* P[3] = {Xout + off, Xgt + off, Xcomp + off};
    const int v0 = blockIdx.x * 32, w0 = blockIdx.y * 32;
    const int tid = threadIdx.x, wid = tid >> 5, lane = tid & 31;
    const int warp_m = wid >> 2, warp_n = wid & 3;
    const int l7 = lane & 7, qd = lane >> 3;

    float cO[4] = {0, 0, 0, 0}, cG[4] = {0, 0, 0, 0}, cC[4] = {0, 0, 0, 0};

    const uint32_t stb = smem_u32(st);
    uint32_t aA[3], bA[3];
    #pragma unroll
    for (int s = 0; s < 3; s++) {
        aA[s] = stb + (uint32_t)(((s * 16 + (qd >> 1) * 8 + l7) * 40 +
                                  warp_m * 16 + (qd & 1) * 8) * 2);
        bA[s] = stb + (uint32_t)((((3 + s) * 16 + (qd & 1) * 8 + l7) * 40 +
                                  warp_n * 8) * 2);
    }

    for (int h0 = 0; h0 < Hs; h0 += 16) {
        for (int idx = tid; idx < 384; idx += 256) {
            int t = idx >> 6, rr = idx & 63;
            int kk = rr >> 2, c8 = (rr & 3) * 8;
            const __half* src =
                P[t % 3] + (size_t)(h0 + kk) * Ws + ((t < 3) ? w0 : v0) + c8;
            cp16(stb + (uint32_t)(((t * 16 + kk) * 40 + c8) * 2), src, 16);
        }
        asm volatile("cp.async.commit_group;");
        asm volatile("cp.async.wait_group 0;");
        __syncthreads();

        uint32_t a[4], b[2];
        ldm4t(a, aA[0]); ldm2t(b, bA[0]); mma16(cO, a, b[0], b[1]);
        ldm4t(a, aA[1]); ldm2t(b, bA[1]); mma16(cG, a, b[0], b[1]);
        ldm4t(a, aA[2]); ldm2t(b, bA[2]); mma16(cC, a, b[0], b[1]);
        __syncthreads();
    }

    float sO = 0.f, sC = 0.f;
    #pragma unroll
    for (int q = 0; q < 4; q++) {
        sO += fabsf(cO[q] - cG[q]);
        sC += fabsf(cC[q] - cG[q]);
    }
    #pragma unroll
    for (int o = 16; o > 0; o >>= 1) {
        sO += __shfl_down_sync(0xffffffffu, sO, o);
        sC += __shfl_down_sync(0xffffffffu, sC, o);
    }
    if (lane == 0) { red[0][wid] = sO; red[1][wid] = sC; }
    __syncthreads();
    if (tid == 0) {
        double tO = 0.0, tC = 0.0;
        #pragma unroll
        for (int j = 0; j < 8; j++) { tO += red[0][j]; tC += red[1][j]; }
        atomicAdd(&g_acc[3], scale * tO);
        atomicAdd(&g_acc[4], scale * tC);
    }
}

__global__ void finalize_k(float* out) {
    if (threadIdx.x == 0 && blockIdx.x == 0) {
        const double N = 3.0 * 512.0 * 512.0 * (double)BN;
        const double Nigt = (double)SZ1;
        double l = (double)BN * g_acc[0] / N
                 + g_acc[1] / N
                 + g_acc[2] / Nigt
                 + g_acc[3]
                 + g_acc[4];
        out[0] = (float)l;
    }
}

// ---------------- host launcher ----------------
extern "C" void kernel_launch(void* const* d_in, const int* in_sizes, int n_in,
                              void* d_out, int out_size) {
    (void)in_sizes; (void)n_in; (void)out_size;
    const float* igt  = (const float*)d_in[0];
    const float* iout = (const float*)d_in[1];
    const float* mask = (const float*)d_in[2];
    const float* w[7];
    const float* bb[7];
    for (int i = 0; i < 7; i++) {
        w[i]  = (const float*)d_in[3 + 2 * i];
        bb[i] = (const float*)d_in[4 + 2 * i];
    }

    __half *hA, *hB, *hp, *w16b, *q1, *q2, *q3;
    float *comp, *wT1;
    cudaGetSymbolAddress((void**)&hA, g_hA);
    cudaGetSymbolAddress((void**)&hB, g_hB);
    cudaGetSymbolAddress((void**)&hp, g_hp);
    cudaGetSymbolAddress((void**)&comp, g_comp);
    cudaGetSymbolAddress((void**)&wT1, g_wT1);
    cudaGetSymbolAddress((void**)&w16b, g_w16);
    cudaGetSymbolAddress((void**)&q1, g_q1);
    cudaGetSymbolAddress((void**)&q2, g_q2);
    cudaGetSymbolAddress((void**)&q3, g_q3);

    const int cins[7]  = {3, 64, 64, 128, 128, 256, 256};
    const int couts[7] = {64, 64, 128, 128, 256, 256, 256};
    __half* w16[7];
    size_t ofs = 0;
    for (int i = 1; i < 7; i++) {
        w16[i] = w16b + ofs;
        ofs += (size_t)cins[i] * couts[i] * 9;
    }

    __half* Q1[3] = {q1, q1 + SZ1, q1 + 2 * (size_t)SZ1};
    __half* Q2[3] = {q2, q2 + SZ2, q2 + 2 * (size_t)SZ2};
    __half* Q3[3] = {q3, q3 + SZ3, q3 + 2 * (size_t)SZ3};

    // 1: weight prep (+ acc zero)
    wprep_k<<<256, 256>>>(w[0], w[1], w[2], w[3], w[4], w[5], w[6], wT1, w16b);
    // 2: comp + L1
    comp_l1_k<<<1024, 256>>>(igt, iout, mask);
    // 3: layer 1 (FFMA2): -> hA
    conv1_k<<<dim3(32, 32, 6 * 2), 256>>>(igt, iout, comp, wT1, bb[0],
                                          hA, 3, 64, 512, 512);
    // 4: layer 2 (co=64): hA -> hB
    conv_mma16b_k<<<dim3(16, 64, 6), 256>>>(hA, w16[1], bb[1], hB, 64, 64, 512, 512);
    // 5: pool 1: hB -> hp
    pool16_k<<<8192, 256>>>(hB, hp, 6 * 256 * 256 * 8, 256, 256, 64);
    // 6: layer 3 (co=128): hp -> hA   <- ncu -s 5 -c 1 captures this
    conv_mma128_k<<<dim3(8, 32, 6), 256>>>(hp, w16[2], bb[2], hA, 64, 128, 256, 256);
    // 7: transpose pool-1 (hp still live) -> q1
    nhwc2nchw16_k<<<dim3(2048, 2, 6), dim3(32, 8)>>>(hp, q1, 65536, 64, SZ1);
    // 8: layer 4: hA -> hB
    conv_mma128_k<<<dim3(8, 32, 6), 256>>>(hA, w16[3], bb[3], hB, 128, 128, 256, 256);
    // 9: pool 2: hB -> hp
    pool16_k<<<4096, 256>>>(hB, hp, 6 * 128 * 128 * 16, 128, 128, 128);
    // 10: layer 5: hp -> hA
    conv_mma128_k<<<dim3(4, 16, 12), 256>>>(hp, w16[4], bb[4], hA, 128, 256, 128, 128);
    // 11: transpose pool-2 (hp still live) -> q2
    nhwc2nchw16_k<<<dim3(512, 4, 6), dim3(32, 8)>>>(hp, q2, 16384, 128, SZ2);
    // 12: layer 6: hA -> hB
    conv_mma128_k<<<dim3(4, 16, 12), 256>>>(hA, w16[5], bb[5], hB, 256, 256, 128, 128);
    // 13: layer 7: hB -> hA
    conv_mma128_k<<<dim3(4, 16, 12), 256>>>(hB, w16[6], bb[6], hA, 256, 256, 128, 128);
    // 14: pool 3: hA -> hp
    pool16_k<<<2048, 256>>>(hA, hp, 6 * 64 * 64 * 32, 64, 64, 256);
    // 15: transpose pool-3 -> q3
    nhwc2nchw16_k<<<dim3(128, 8, 6), dim3(32, 8)>>>(hp, q3, 4096, 256, SZ3);

    perc_sum16_k<<<2048, 256>>>(Q1[1], Q1[0], Q1[2], SZ1 / 8);
    perc_sum16_k<<<1024, 256>>>(Q2[1], Q2[0], Q2[2], SZ2 / 8);
    perc_sum16_k<<<512, 256>>>(Q3[1], Q3[0], Q3[2], SZ3 / 8);

    style_mma_k<<<dim3(8, 8, BN * 64), 256>>>(Q1[1], Q1[0], Q1[2], 256, 256,
                                              1.0 / (4194304.0 * 4096.0));
    style_mma_k<<<dim3(4, 4, BN * 128), 256>>>(Q2[1], Q2[0], Q2[2], 128, 128,
                                               1.0 / (2097152.0 * 16384.0));
    style_mma_k<<<dim3(2, 2, BN * 256), 256>>>(Q3[1], Q3[0], Q3[2], 64, 64,
                                               1.0 / (1048576.0 * 65536.0));

    finalize_k<<<1, 32>>>((float*)d_out);
}

// round 14
// speedup vs baseline: 5.4371x; 1.0307x over previous
#include <cuda_runtime.h>
#include <cuda_fp16.h>
#include <math.h>
#include <stdint.h>

#define BN 2
#define CI_T 8

// ---------------- static scratch (no allocations allowed) ----------------
__device__ __half g_hA[6 * 64 * 512 * 512];      // NHWC fp16 ping
__device__ __half g_hB[6 * 64 * 512 * 512];      // NHWC fp16 pong
__device__ __half g_hp[6 * 64 * 256 * 256];      // NHWC fp16 pooled
__device__ float  g_comp[BN * 3 * 512 * 512];
__device__ float  g_wT1[1728];                   // layer-1 weights (fp32)
__device__ __half g_w16[1732608];                // layers 2-7 weights, A-fragment order

#define SZ1 (BN * 64 * 256 * 256)
#define SZ2 (BN * 128 * 128 * 128)
#define SZ3 (BN * 256 * 64 * 64)
// fp16 NCHW pool planes per stream: [gt, out, comp]
__device__ __half g_q1[3][SZ1];
__device__ __half g_q2[3][SZ2];
__device__ __half g_q3[3][SZ3];

__device__ double g_acc[8];

// ---------------- helpers ----------------
__device__ __forceinline__ unsigned long long pk2(float a, float b) {
    unsigned long long r;
    asm("mov.b64 %0, {%1, %2};" : "=l"(r) : "f"(a), "f"(b));
    return r;
}
__device__ __forceinline__ unsigned long long fma_x2(unsigned long long a,
                                                     unsigned long long b,
                                                     unsigned long long c) {
    unsigned long long d;
    asm("fma.rn.f32x2 %0, %1, %2, %3;" : "=l"(d) : "l"(a), "l"(b), "l"(c));
    return d;
}
__device__ __forceinline__ void upk(unsigned long long v, float& lo, float& hi) {
    asm("mov.b64 {%0, %1}, %2;" : "=f"(lo), "=f"(hi) : "l"(v));
}
__device__ __forceinline__ uint32_t smem_u32(const void* p) {
    return (uint32_t)__cvta_generic_to_shared(p);
}
__device__ __forceinline__ void ldm4(uint32_t* r, uint32_t addr) {
    asm volatile("ldmatrix.sync.aligned.m8n8.x4.shared.b16 {%0,%1,%2,%3}, [%4];"
                 : "=r"(r[0]), "=r"(r[1]), "=r"(r[2]), "=r"(r[3]) : "r"(addr));
}
__device__ __forceinline__ void ldm4t(uint32_t* r, uint32_t addr) {
    asm volatile("ldmatrix.sync.aligned.m8n8.x4.trans.shared.b16 {%0,%1,%2,%3}, [%4];"
                 : "=r"(r[0]), "=r"(r[1]), "=r"(r[2]), "=r"(r[3]) : "r"(addr));
}
__device__ __forceinline__ void ldm2t(uint32_t* r, uint32_t addr) {
    asm volatile("ldmatrix.sync.aligned.m8n8.x2.trans.shared.b16 {%0,%1}, [%2];"
                 : "=r"(r[0]), "=r"(r[1]) : "r"(addr));
}
__device__ __forceinline__ void mma16(float* c, const uint32_t* a,
                                      uint32_t b0, uint32_t b1) {
    asm volatile(
        "mma.sync.aligned.m16n8k16.row.col.f32.f16.f16.f32 "
        "{%0,%1,%2,%3}, {%4,%5,%6,%7}, {%8,%9}, {%0,%1,%2,%3};"
        : "+f"(c[0]), "+f"(c[1]), "+f"(c[2]), "+f"(c[3])
        : "r"(a[0]), "r"(a[1]), "r"(a[2]), "r"(a[3]), "r"(b0), "r"(b1));
}
__device__ __forceinline__ void cp16(uint32_t dst, const void* src, int srcsize) {
    asm volatile("cp.async.ca.shared.global [%0], [%1], 16, %2;"
                 :: "r"(dst), "l"(src), "r"(srcsize));
}
__device__ __forceinline__ void warp_atomic(double* dst, float v) {
    #pragma unroll
    for (int o = 16; o > 0; o >>= 1) v += __shfl_down_sync(0xffffffffu, v, o);
    if ((threadIdx.x & 31) == 0) atomicAdd(dst, (double)v);
}

// ---------------- kernels ----------------

// weight prep: zero accs, layer-1 fp32 transpose, layers 2-7 A-fragment pack
__global__ void wprep_k(const float* __restrict__ w0, const float* __restrict__ w1,
                        const float* __restrict__ w2, const float* __restrict__ w3,
                        const float* __restrict__ w4, const float* __restrict__ w5,
                        const float* __restrict__ w6,
                        float* __restrict__ wT1, __half* __restrict__ wfb) {
    const int tid0 = blockIdx.x * blockDim.x + threadIdx.x;
    const int stride = gridDim.x * blockDim.x;
    if (tid0 < 8) g_acc[tid0] = 0.0;
    for (int i = tid0; i < 1728; i += stride) {
        int co = i & 63;
        int t = i >> 6;
        int k = t % 9, ci = t / 9;
        wT1[i] = w0[(co * 3 + ci) * 9 + k];
    }
    const float* ws[6] = {w1, w2, w3, w4, w5, w6};
    const int cins[6] = {64, 64, 128, 128, 256, 256};
    const int couts[6] = {64, 128, 128, 256, 256, 256};
    size_t ofs = 0;
    for (int L = 0; L < 6; L++) {
        const int Cin = cins[L], Cout = couts[L];
        const int rounds = Cin >> 4, nM16 = Cout >> 4;
        const int n = 9 * Cin * Cout;
        const float* w = ws[L];
        __half* wf = wfb + ofs;
        for (int i = tid0; i < n; i += stride) {
            int h = i & 7, lane = (i >> 3) & 31;
            int rest = i >> 8;
            int r = rest % rounds;
            rest /= rounds;
            int m16 = rest % nM16;
            int t = rest / nM16;
            int pair = h >> 1, lo = h & 1;
            int row = (lane >> 2) + (pair & 1) * 8;
            int ci = r * 16 + (lane & 3) * 2 + (pair >> 1) * 8 + lo;
            int cco = m16 * 16 + row;
            wf[i] = __float2half_rn(w[((size_t)cco * Cin + ci) * 9 + t]);
        }
        ofs += n;
    }
}

// icomp + hole/valid L1 partial sums
__global__ void comp_l1_k(const float* __restrict__ igt,
                          const float* __restrict__ iout,
                          const float* __restrict__ mask) {
    const int n = BN * 3 * 512 * 512;
    const int hw = 512 * 512;
    float h = 0.f, v = 0.f;
    for (int i = blockIdx.x * blockDim.x + threadIdx.x; i < n;
         i += gridDim.x * blockDim.x) {
        int pix = i % hw;
        int b = (i / hw) / 3;
        float m = (mask[b * hw + pix] != 0.0f) ? 1.0f : 0.0f;
        float gt = igt[i], ot = iout[i];
        float d = ot - gt;
        h += fabsf((1.0f - m) * d);
        v += fabsf(m * d);
        g_comp[i] = (m == 1.0f) ? gt : ot;
    }
    warp_atomic(&g_acc[0], h);
    warp_atomic(&g_acc[1], v);
}

// ---------- FFMA2 conv layer 1 (Cin=3, fp32 NCHW in, fp16 NHWC out) ----------
__global__ __launch_bounds__(256, 3) void conv1_k(
    const float* __restrict__ in0, const float* __restrict__ in1,
    const float* __restrict__ in2,
    const float* __restrict__ wT, const float* __restrict__ bias,
    __half* __restrict__ out, int Cin, int Cout, int Hh, int Ww) {
    __shared__ __align__(16) float s_in[CI_T][18][20];
    __shared__ __align__(16) float s_w[CI_T][9][32];

    const int nCoT = Cout >> 5;
    const int coT = blockIdx.z % nCoT;
    const int be = blockIdx.z / nCoT;
    const int x0 = blockIdx.x * 16, y0 = blockIdx.y * 16;
    const int tid = threadIdx.x;
    const int p = tid & 63;
    const int g = tid >> 6;
    const int px = (p & 7) * 2, py = (p >> 3) * 2;
    const int g8 = g * 8;
    const size_t HW = (size_t)Hh * Ww;

    int s = be >> 1;
    const float* sp = (s == 0) ? in0 : ((s == 1) ? in1 : in2);
    const float* inB = sp + (size_t)(be & 1) * Cin * HW;

    unsigned long long acc[4][4];
    #pragma unroll
    for (int c = 0; c < 4; c++)
        #pragma unroll
        for (int q = 0; q < 4; q++) acc[c][q] = 0ull;

    const int rounds = (Cin + CI_T - 1) / CI_T;
    for (int r = 0; r < rounds; r++) {
        const int c0 = r * CI_T;
        for (int idx = tid; idx < CI_T * 324; idx += 256) {
            int q = idx / 324, rr = idx - q * 324;
            int iy = rr / 18, ix = rr - iy * 18;
            int ci = c0 + q;
            int gy = y0 + iy - 1, gx = x0 + ix - 1;
            float v = 0.f;
            if (ci < Cin && gy >= 0 && gy < Hh && gx >= 0 && gx < Ww)
                v = inB[(size_t)ci * HW + gy * Ww + gx];
            s_in[q][iy][ix] = v;
        }
        for (int idx = tid; idx < CI_T * 288; idx += 256) {
            int co = idx & 31;
            int t = idx >> 5;
            int k = t % 9, q = t / 9;
            int ci = c0 + q;
            float v = 0.f;
            if (ci < Cin) v = wT[((size_t)ci * 9 + k) * Cout + coT * 32 + co];
            s_w[q][k][co] = v;
        }
        __syncthreads();

        #pragma unroll 2
        for (int q = 0; q < CI_T; q++) {
            unsigned long long xx[4][4];
            #pragma unroll
            for (int dy = 0; dy < 4; dy++) {
                float2 a = *(const float2*)&s_in[q][py + dy][px];
                float2 b = *(const float2*)&s_in[q][py + dy][px + 2];
                xx[dy][0] = pk2(a.x, a.x);
                xx[dy][1] = pk2(a.y, a.y);
                xx[dy][2] = pk2(b.x, b.x);
                xx[dy][3] = pk2(b.y, b.y);
            }
            #pragma unroll
            for (int ky = 0; ky < 3; ky++)
                #pragma unroll
                for (int kx = 0; kx < 3; kx++) {
                    const int k = ky * 3 + kx;
                    float2 wa = *(const float2*)&s_w[q][k][g8];
                    float2 wb = *(const float2*)&s_w[q][k][g8 + 2];
                    float2 wc = *(const float2*)&s_w[q][k][g8 + 4];
                    float2 wd = *(const float2*)&s_w[q][k][g8 + 6];
                    unsigned long long w0 = pk2(wa.x, wa.y);
                    unsigned long long w1 = pk2(wb.x, wb.y);
                    unsigned long long w2 = pk2(wc.x, wc.y);
                    unsigned long long w3 = pk2(wd.x, wd.y);
                    #pragma unroll
                    for (int sy = 0; sy < 2; sy++)
                        #pragma unroll
                        for (int sx = 0; sx < 2; sx++) {
                            unsigned long long xf = xx[sy + ky][sx + kx];
                            const int pid = sy * 2 + sx;
                            acc[0][pid] = fma_x2(xf, w0, acc[0][pid]);
                            acc[1][pid] = fma_x2(xf, w1, acc[1][pid]);
                            acc[2][pid] = fma_x2(xf, w2, acc[2][pid]);
                            acc[3][pid] = fma_x2(xf, w3, acc[3][pid]);
                        }
                }
        }
        __syncthreads();
    }

    const int coBase = coT * 32 + g8;
    float bb[8];
    #pragma unroll
    for (int j = 0; j < 8; j++) bb[j] = bias[coBase + j];
    #pragma unroll
    for (int sy = 0; sy < 2; sy++)
        #pragma unroll
        for (int sx = 0; sx < 2; sx++) {
            int y = y0 + py + sy, x = x0 + px + sx;
            const int pid = sy * 2 + sx;
            union { uint4 u; __half2 h[4]; } pk;
            #pragma unroll
            for (int cp = 0; cp < 4; cp++) {
                float lo, hi;
                upk(acc[cp][pid], lo, hi);
                pk.h[cp] = __floats2half2_rn(fmaxf(lo + bb[2 * cp], 0.f),
                                             fmaxf(hi + bb[2 * cp + 1], 0.f));
            }
            *(uint4*)&out[((size_t)(be * Hh + y) * Ww + x) * Cout + coBase] = pk.u;
        }
}

// ---------- fp16 mma conv, co-tile 64 x (8y x 16x), 2 CTAs/SM (layers 2-7) ----
// block 256 = 8 warps (2 warp_m x 4 warp_n); warp = 32co x 32px; acc 32 regs.
// A-frags direct from gmem (L2), activations cp.async double-buffered.
// grid (W/16, H/8, 6 * Cout/64)
#define ACT64_H 4320   // halves per buffer (180 cells * 24)
__global__ __launch_bounds__(256, 2) void conv_mma64_k(
    const __half* __restrict__ in, const __half* __restrict__ wf,
    const float* __restrict__ bias, __half* __restrict__ out,
    int Cin, int Cout, int Hh, int Ww) {
    __shared__ __align__(16) __half sh[8704];   // max(2*4320, 64*136)

    const int nCoT = Cout >> 6;
    const int nM16 = Cout >> 4;
    const int coT = blockIdx.z % nCoT;
    const int be = blockIdx.z / nCoT;
    const int x0 = blockIdx.x * 16, y0 = blockIdx.y * 8;
    const int tid = threadIdx.x, wid = tid >> 5, lane = tid & 31;
    const int warp_m = wid >> 2, warp_n = wid & 3;
    const int rounds = Cin >> 4;

    float acc[2][4][4];
    #pragma unroll
    for (int mf = 0; mf < 2; mf++)
        #pragma unroll
        for (int nf = 0; nf < 4; nf++)
            #pragma unroll
            for (int q = 0; q < 4; q++) acc[mf][nf][q] = 0.f;

    const uint32_t sxb = smem_u32(sh);
    const int l7 = lane & 7, qd = lane >> 3;
    const int b_xx = ((qd >> 1) & 1) * 8 + l7;
    const int b_k = (qd & 1) * 8;
    uint32_t bRel[2];
    #pragma unroll
    for (int j = 0; j < 2; j++)
        bRel[j] = (uint32_t)((((2 * warp_n + j) * 18 + b_xx) * 24 + b_k) * 2);

    {
        for (int idx = tid; idx < 360; idx += 256) {
            int cell = idx >> 1, hh = idx & 1;
            int yy = cell / 18, xx = cell - yy * 18;
            int gy = y0 + yy - 1, gx = x0 + xx - 1;
            bool ok = (gy >= 0 && gy < Hh && gx >= 0 && gx < Ww);
            const __half* src = ok
                ? &in[((size_t)(be * Hh + gy) * Ww + gx) * Cin + hh * 8]
                : in;
            cp16(sxb + (uint32_t)((cell * 24 + hh * 8) * 2), src, ok ? 16 : 0);
        }
        asm volatile("cp.async.commit_group;");
    }

    for (int r = 0; r < rounds; r++) {
        asm volatile("cp.async.wait_group 0;");
        __syncthreads();
        if (r + 1 < rounds) {
            const int ci0 = (r + 1) << 4;
            const uint32_t dbase = sxb + (uint32_t)(((r + 1) & 1) * ACT64_H * 2);
            for (int idx = tid; idx < 360; idx += 256) {
                int cell = idx >> 1, hh = idx & 1;
                int yy = cell / 18, xx = cell - yy * 18;
                int gy = y0 + yy - 1, gx = x0 + xx - 1;
                bool ok = (gy >= 0 && gy < Hh && gx >= 0 && gx < Ww);
                const __half* src = ok
                    ? &in[((size_t)(be * Hh + gy) * Ww + gx) * Cin + ci0 + hh * 8]
                    : in;
                cp16(dbase + (uint32_t)((cell * 24 + hh * 8) * 2), src, ok ? 16 : 0);
            }
            asm volatile("cp.async.commit_group;");
        }

        const uint32_t bufB = sxb + (uint32_t)((r & 1) * ACT64_H * 2);
        #pragma unroll
        for (int t = 0; t < 9; t++) {
            const int dy = t / 3, dx = t - dy * 3;
            const uint32_t toff = (uint32_t)((dy * 18 + dx) * 48);
            uint32_t a0[4], a1[4];
            {
                size_t o = ((((size_t)t * nM16 + coT * 4 + warp_m * 2) * rounds + r)
                            * 32 + lane) * 8;
                uint4 v = *(const uint4*)(wf + o);
                a0[0] = v.x; a0[1] = v.y; a0[2] = v.z; a0[3] = v.w;
                v = *(const uint4*)(wf + o + (size_t)rounds * 256);
                a1[0] = v.x; a1[1] = v.y; a1[2] = v.z; a1[3] = v.w;
            }
            #pragma unroll
            for (int j = 0; j < 2; j++) {
                uint32_t b[4];
                ldm4(b, bufB + bRel[j] + toff);
                const int nb = j * 2;
                mma16(acc[0][nb], a0, b[0], b[1]);
                mma16(acc[1][nb], a1, b[0], b[1]);
                mma16(acc[0][nb + 1], a0, b[2], b[3]);
                mma16(acc[1][nb + 1], a1, b[2], b[3]);
            }
        }
        __syncthreads();
    }

    // epilogue: bias+relu -> smem [64co][136] -> NHWC fp16
    #pragma unroll
    for (int mf = 0; mf < 2; mf++) {
        const int c0l = warp_m * 32 + mf * 16 + (lane >> 2);
        const float bb0 = bias[coT * 64 + c0l];
        const float bb1 = bias[coT * 64 + c0l + 8];
        #pragma unroll
        for (int nf = 0; nf < 4; nf++) {
            int px = (2 * warp_n + (nf >> 1)) * 16 + (nf & 1) * 8 + (lane & 3) * 2;
            *(__half2*)&sh[c0l * 136 + px] =
                __floats2half2_rn(fmaxf(acc[mf][nf][0] + bb0, 0.f),
                                  fmaxf(acc[mf][nf][1] + bb0, 0.f));
            *(__half2*)&sh[(c0l + 8) * 136 + px] =
                __floats2half2_rn(fmaxf(acc[mf][nf][2] + bb1, 0.f),
                                  fmaxf(acc[mf][nf][3] + bb1, 0.f));
        }
    }
    __syncthreads();
    {
        const int px = tid >> 1, ch = (tid & 1) * 32;
        const int yy = px >> 4, xx = px & 15;
        __half* base = out + ((size_t)(be * Hh + y0 + yy) * Ww + (x0 + xx)) * Cout +
                       coT * 64 + ch;
        #pragma unroll
        for (int k = 0; k < 4; k++) {
            union { uint4 u; __half h[8]; } pk;
            #pragma unroll
            for (int j = 0; j < 8; j++) pk.h[j] = sh[(ch + 8 * k + j) * 136 + px];
            *(uint4*)&base[8 * k] = pk.u;
        }
    }
}

// 2x2 maxpool fp16 NHWC -> fp16 NHWC
__global__ void pool16_k(const __half* __restrict__ in, __half* __restrict__ out,
                         int total8, int Ho, int Wo, int C) {
    const int C8 = C >> 3;
    for (int i = blockIdx.x * blockDim.x + threadIdx.x; i < total8;
         i += gridDim.x * blockDim.x) {
        int c8 = i % C8;
        int t = i / C8;
        int x = t % Wo;
        t /= Wo;
        int y = t % Ho;
        int be = t / Ho;
        const __half* p =
            in + ((size_t)(be * 2 * Ho + 2 * y) * (2 * Wo) + 2 * x) * C + c8 * 8;
        union { uint4 u; __half2 h[4]; } a, b, c, d, rr;
        a.u = *(const uint4*)p;
        b.u = *(const uint4*)(p + C);
        c.u = *(const uint4*)(p + (size_t)2 * Wo * C);
        d.u = *(const uint4*)(p + (size_t)2 * Wo * C + C);
        #pragma unroll
        for (int j = 0; j < 4; j++)
            rr.h[j] = __hmax2(__hmax2(a.h[j], b.h[j]), __hmax2(c.h[j], d.h[j]));
        *(uint4*)&out[(size_t)i * 8] = rr.u;
    }
}

// NHWC fp16 -> NCHW fp16 pool planes (for perc + style)
__global__ void nhwc2nchw16_k(const __half* __restrict__ in,
                              __half* __restrict__ out,
                              int HWp, int C, int SZlevel) {
    __shared__ __half tl[32][34];
    const int px0 = blockIdx.x * 32, c0 = blockIdx.y * 32, be = blockIdx.z;
    const int tx = threadIdx.x, ty = threadIdx.y;
    for (int r = ty; r < 32; r += 8)
        tl[r][tx] = in[((size_t)be * HWp + px0 + r) * C + c0 + tx];
    __syncthreads();
    const int s = be >> 1, b = be & 1;
    __half* ob = out + (size_t)s * SZlevel + (size_t)b * C * HWp;
    for (int r = ty; r < 32; r += 8)
        ob[(size_t)(c0 + r) * HWp + px0 + tx] = tl[tx][r];
}

// perceptual: sum |out-gt| + |comp-gt| over fp16 planes -> g_acc[2]
__global__ void perc_sum16_k(const __half* __restrict__ aout,
                             const __half* __restrict__ agt,
                             const __half* __restrict__ acomp, int n8) {
    float s = 0.f;
    for (int i = blockIdx.x * blockDim.x + threadIdx.x; i < n8;
         i += gridDim.x * blockDim.x) {
        union { uint4 u; __half2 h[4]; } o, g, c;
        o.u = *(const uint4*)&aout[(size_t)i * 8];
        g.u = *(const uint4*)&agt[(size_t)i * 8];
        c.u = *(const uint4*)&acomp[(size_t)i * 8];
        #pragma unroll
        for (int j = 0; j < 4; j++) {
            float2 fo = __half22float2(o.h[j]);
            float2 fg = __half22float2(g.h[j]);
            float2 fc = __half22float2(c.h[j]);
            s += fabsf(fo.x - fg.x) + fabsf(fc.x - fg.x);
            s += fabsf(fo.y - fg.y) + fabsf(fc.y - fg.y);
        }
    }
    warp_atomic(&g_acc[2], s);
}

// ---------- style via fp16 mma: G = X^T X per (b,c) plane ----------
__global__ __launch_bounds__(256) void style_mma_k(
    const __half* __restrict__ Xout, const __half* __restrict__ Xgt,
    const __half* __restrict__ Xcomp, int Hs, int Ws, double scale) {
    __shared__ __align__(16) __half st[6][16][40];
    __shared__ float red[2][8];
    const int bc = blockIdx.z;
    const size_t off = (size_t)bc * Hs * Ws;
    const __half* P[3] = {Xout + off, Xgt + off, Xcomp + off};
    const int v0 = blockIdx.x * 32, w0 = blockIdx.y * 32;
    const int tid = threadIdx.x, wid = tid >> 5, lane = tid & 31;
    const int warp_m = wid >> 2, warp_n = wid & 3;
    const int l7 = lane & 7, qd = lane >> 3;

    float cO[4] = {0, 0, 0, 0}, cG[4] = {0, 0, 0, 0}, cC[4] = {0, 0, 0, 0};

    const uint32_t stb = smem_u32(st);
    uint32_t aA[3], bA[3];
    #pragma unroll
    for (int s = 0; s < 3; s++) {
        aA[s] = stb + (uint32_t)(((s * 16 + (qd >> 1) * 8 + l7) * 40 +
                                  warp_m * 16 + (qd & 1) * 8) * 2);
        bA[s] = stb + (uint32_t)((((3 + s) * 16 + (qd & 1) * 8 + l7) * 40 +
                                  warp_n * 8) * 2);
    }

    for (int h0 = 0; h0 < Hs; h0 += 16) {
        for (int idx = tid; idx < 384; idx += 256) {
            int t = idx >> 6, rr = idx & 63;
            int kk = rr >> 2, c8 = (rr & 3) * 8;
            const __half* src =
                P[t % 3] + (size_t)(h0 + kk) * Ws + ((t < 3) ? w0 : v0) + c8;
            cp16(stb + (uint32_t)(((t * 16 + kk) * 40 + c8) * 2), src, 16);
        }
        asm volatile("cp.async.commit_group;");
        asm volatile("cp.async.wait_group 0;");
        __syncthreads();

        uint32_t a[4], b[2];
        ldm4t(a, aA[0]); ldm2t(b, bA[0]); mma16(cO, a, b[0], b[1]);
        ldm4t(a, aA[1]); ldm2t(b, bA[1]); mma16(cG, a, b[0], b[1]);
        ldm4t(a, aA[2]); ldm2t(b, bA[2]); mma16(cC, a, b[0], b[1]);
        __syncthreads();
    }

    float sO = 0.f, sC = 0.f;
    #pragma unroll
    for (int q = 0; q < 4; q++) {
        sO += fabsf(cO[q] - cG[q]);
        sC += fabsf(cC[q] - cG[q]);
    }
    #pragma unroll
    for (int o = 16; o > 0; o >>= 1) {
        sO += __shfl_down_sync(0xffffffffu, sO, o);
        sC += __shfl_down_sync(0xffffffffu, sC, o);
    }
    if (lane == 0) { red[0][wid] = sO; red[1][wid] = sC; }
    __syncthreads();
    if (tid == 0) {
        double tO = 0.0, tC = 0.0;
        #pragma unroll
        for (int j = 0; j < 8; j++) { tO += red[0][j]; tC += red[1][j]; }
        atomicAdd(&g_acc[3], scale * tO);
        atomicAdd(&g_acc[4], scale * tC);
    }
}

__global__ void finalize_k(float* out) {
    if (threadIdx.x == 0 && blockIdx.x == 0) {
        const double N = 3.0 * 512.0 * 512.0 * (double)BN;
        const double Nigt = (double)SZ1;
        double l = (double)BN * g_acc[0] / N
                 + g_acc[1] / N
                 + g_acc[2] / Nigt
                 + g_acc[3]
                 + g_acc[4];
        out[0] = (float)l;
    }
}

// ---------------- host launcher ----------------
extern "C" void kernel_launch(void* const* d_in, const int* in_sizes, int n_in,
                              void* d_out, int out_size) {
    (void)in_sizes; (void)n_in; (void)out_size;
    const float* igt  = (const float*)d_in[0];
    const float* iout = (const float*)d_in[1];
    const float* mask = (const float*)d_in[2];
    const float* w[7];
    const float* bb[7];
    for (int i = 0; i < 7; i++) {
        w[i]  = (const float*)d_in[3 + 2 * i];
        bb[i] = (const float*)d_in[4 + 2 * i];
    }

    __half *hA, *hB, *hp, *w16b, *q1, *q2, *q3;
    float *comp, *wT1;
    cudaGetSymbolAddress((void**)&hA, g_hA);
    cudaGetSymbolAddress((void**)&hB, g_hB);
    cudaGetSymbolAddress((void**)&hp, g_hp);
    cudaGetSymbolAddress((void**)&comp, g_comp);
    cudaGetSymbolAddress((void**)&wT1, g_wT1);
    cudaGetSymbolAddress((void**)&w16b, g_w16);
    cudaGetSymbolAddress((void**)&q1, g_q1);
    cudaGetSymbolAddress((void**)&q2, g_q2);
    cudaGetSymbolAddress((void**)&q3, g_q3);

    const int cins[7]  = {3, 64, 64, 128, 128, 256, 256};
    const int couts[7] = {64, 64, 128, 128, 256, 256, 256};
    __half* w16[7];
    size_t ofs = 0;
    for (int i = 1; i < 7; i++) {
        w16[i] = w16b + ofs;
        ofs += (size_t)cins[i] * couts[i] * 9;
    }

    __half* Q1[3] = {q1, q1 + SZ1, q1 + 2 * (size_t)SZ1};
    __half* Q2[3] = {q2, q2 + SZ2, q2 + 2 * (size_t)SZ2};
    __half* Q3[3] = {q3, q3 + SZ3, q3 + 2 * (size_t)SZ3};

    // 1: weight prep (+ acc zero)
    wprep_k<<<256, 256>>>(w[0], w[1], w[2], w[3], w[4], w[5], w[6], wT1, w16b);
    // 2: comp + L1
    comp_l1_k<<<1024, 256>>>(igt, iout, mask);
    // 3: layer 1 (FFMA2): -> hA
    conv1_k<<<dim3(32, 32, 6 * 2), 256>>>(igt, iout, comp, wT1, bb[0],
                                          hA, 3, 64, 512, 512);
    // 4: layer 2: hA -> hB
    conv_mma64_k<<<dim3(32, 64, 6), 256>>>(hA, w16[1], bb[1], hB, 64, 64, 512, 512);
    // 5: pool 1: hB -> hp
    pool16_k<<<8192, 256>>>(hB, hp, 6 * 256 * 256 * 8, 256, 256, 64);
    // 6: layer 3: hp -> hA   <- ncu -s 5 -c 1 captures this
    conv_mma64_k<<<dim3(16, 32, 12), 256>>>(hp, w16[2], bb[2], hA, 64, 128, 256, 256);
    // 7: transpose pool-1 (hp still live) -> q1
    nhwc2nchw16_k<<<dim3(2048, 2, 6), dim3(32, 8)>>>(hp, q1, 65536, 64, SZ1);
    // 8: layer 4: hA -> hB
    conv_mma64_k<<<dim3(16, 32, 12), 256>>>(hA, w16[3], bb[3], hB, 128, 128, 256, 256);
    // 9: pool 2: hB -> hp
    pool16_k<<<4096, 256>>>(hB, hp, 6 * 128 * 128 * 16, 128, 128, 128);
    // 10: layer 5: hp -> hA
    conv_mma64_k<<<dim3(8, 16, 24), 256>>>(hp, w16[4], bb[4], hA, 128, 256, 128, 128);
    // 11: transpose pool-2 (hp still live) -> q2
    nhwc2nchw16_k<<<dim3(512, 4, 6), dim3(32, 8)>>>(hp, q2, 16384, 128, SZ2);
    // 12: layer 6: hA -> hB
    conv_mma64_k<<<dim3(8, 16, 24), 256>>>(hA, w16[5], bb[5], hB, 256, 256, 128, 128);
    // 13: layer 7: hB -> hA
    conv_mma64_k<<<dim3(8, 16, 24), 256>>>(hB, w16[6], bb[6], hA, 256, 256, 128, 128);
    // 14: pool 3: hA -> hp
    pool16_k<<<2048, 256>>>(hA, hp, 6 * 64 * 64 * 32, 64, 64, 256);
    // 15: transpose pool-3 -> q3
    nhwc2nchw16_k<<<dim3(128, 8, 6), dim3(32, 8)>>>(hp, q3, 4096, 256, SZ3);

    perc_sum16_k<<<2048, 256>>>(Q1[1], Q1[0], Q1[2], SZ1 / 8);
    perc_sum16_k<<<1024, 256>>>(Q2[1], Q2[0], Q2[2], SZ2 / 8);
    perc_sum16_k<<<512, 256>>>(Q3[1], Q3[0], Q3[2], SZ3 / 8);

    style_mma_k<<<dim3(8, 8, BN * 64), 256>>>(Q1[1], Q1[0], Q1[2], 256, 256,
                                              1.0 / (4194304.0 * 4096.0));
    style_mma_k<<<dim3(4, 4, BN * 128), 256>>>(Q2[1], Q2[0], Q2[2], 128, 128,
                                               1.0 / (2097152.0 * 16384.0));
    style_mma_k<<<dim3(2, 2, BN * 256), 256>>>(Q3[1], Q3[0], Q3[2], 64, 64,
                                               1.0 / (1048576.0 * 65536.0));

    finalize_k<<<1, 32>>>((float*)d_out);
}

// round 15
// speedup vs baseline: 5.8688x; 1.0794x over previous
#include <cuda_runtime.h>
#include <cuda_fp16.h>
#include <math.h>
#include <stdint.h>

#define BN 2
#define CI_T 8

// ---------------- static scratch (no allocations allowed) ----------------
__device__ __half g_hA[6 * 64 * 512 * 512];      // NHWC fp16 ping
__device__ __half g_hB[6 * 64 * 512 * 512];      // NHWC fp16 pong
__device__ __half g_hp[6 * 64 * 256 * 256];      // NHWC fp16 pooled
__device__ float  g_comp[BN * 3 * 512 * 512];
__device__ float  g_wT1[1728];                   // layer-1 weights (fp32)
__device__ __half g_w16[1732608];                // layers 2-7 weights, A-fragment order

#define SZ1 (BN * 64 * 256 * 256)
#define SZ2 (BN * 128 * 128 * 128)
#define SZ3 (BN * 256 * 64 * 64)
// fp16 NCHW pool planes per stream: [gt, out, comp]
__device__ __half g_q1[3][SZ1];
__device__ __half g_q2[3][SZ2];
__device__ __half g_q3[3][SZ3];

__device__ double g_acc[8];

// ---------------- helpers ----------------
__device__ __forceinline__ unsigned long long pk2(float a, float b) {
    unsigned long long r;
    asm("mov.b64 %0, {%1, %2};" : "=l"(r) : "f"(a), "f"(b));
    return r;
}
__device__ __forceinline__ unsigned long long fma_x2(unsigned long long a,
                                                     unsigned long long b,
                                                     unsigned long long c) {
    unsigned long long d;
    asm("fma.rn.f32x2 %0, %1, %2, %3;" : "=l"(d) : "l"(a), "l"(b), "l"(c));
    return d;
}
__device__ __forceinline__ void upk(unsigned long long v, float& lo, float& hi) {
    asm("mov.b64 {%0, %1}, %2;" : "=f"(lo), "=f"(hi) : "l"(v));
}
__device__ __forceinline__ uint32_t smem_u32(const void* p) {
    return (uint32_t)__cvta_generic_to_shared(p);
}
__device__ __forceinline__ void ldm4(uint32_t* r, uint32_t addr) {
    asm volatile("ldmatrix.sync.aligned.m8n8.x4.shared.b16 {%0,%1,%2,%3}, [%4];"
                 : "=r"(r[0]), "=r"(r[1]), "=r"(r[2]), "=r"(r[3]) : "r"(addr));
}
__device__ __forceinline__ void ldm4t(uint32_t* r, uint32_t addr) {
    asm volatile("ldmatrix.sync.aligned.m8n8.x4.trans.shared.b16 {%0,%1,%2,%3}, [%4];"
                 : "=r"(r[0]), "=r"(r[1]), "=r"(r[2]), "=r"(r[3]) : "r"(addr));
}
__device__ __forceinline__ void ldm2t(uint32_t* r, uint32_t addr) {
    asm volatile("ldmatrix.sync.aligned.m8n8.x2.trans.shared.b16 {%0,%1}, [%2];"
                 : "=r"(r[0]), "=r"(r[1]) : "r"(addr));
}
__device__ __forceinline__ void mma16(float* c, const uint32_t* a,
                                      uint32_t b0, uint32_t b1) {
    asm volatile(
        "mma.sync.aligned.m16n8k16.row.col.f32.f16.f16.f32 "
        "{%0,%1,%2,%3}, {%4,%5,%6,%7}, {%8,%9}, {%0,%1,%2,%3};"
        : "+f"(c[0]), "+f"(c[1]), "+f"(c[2]), "+f"(c[3])
        : "r"(a[0]), "r"(a[1]), "r"(a[2]), "r"(a[3]), "r"(b0), "r"(b1));
}
// cp.async with L1 bypass (.cg): staged-once data should not pollute/occupy L1
__device__ __forceinline__ void cp16cg(uint32_t dst, const void* src, int srcsize) {
    asm volatile("cp.async.cg.shared.global [%0], [%1], 16, %2;"
                 :: "r"(dst), "l"(src), "r"(srcsize));
}
__device__ __forceinline__ void warp_atomic(double* dst, float v) {
    #pragma unroll
    for (int o = 16; o > 0; o >>= 1) v += __shfl_down_sync(0xffffffffu, v, o);
    if ((threadIdx.x & 31) == 0) atomicAdd(dst, (double)v);
}

// ---------------- kernels ----------------

// weight prep: zero accs, layer-1 fp32 transpose, layers 2-7 A-fragment pack
__global__ void wprep_k(const float* __restrict__ w0, const float* __restrict__ w1,
                        const float* __restrict__ w2, const float* __restrict__ w3,
                        const float* __restrict__ w4, const float* __restrict__ w5,
                        const float* __restrict__ w6,
                        float* __restrict__ wT1, __half* __restrict__ wfb) {
    const int tid0 = blockIdx.x * blockDim.x + threadIdx.x;
    const int stride = gridDim.x * blockDim.x;
    if (tid0 < 8) g_acc[tid0] = 0.0;
    for (int i = tid0; i < 1728; i += stride) {
        int co = i & 63;
        int t = i >> 6;
        int k = t % 9, ci = t / 9;
        wT1[i] = w0[(co * 3 + ci) * 9 + k];
    }
    const float* ws[6] = {w1, w2, w3, w4, w5, w6};
    const int cins[6] = {64, 64, 128, 128, 256, 256};
    const int couts[6] = {64, 128, 128, 256, 256, 256};
    size_t ofs = 0;
    for (int L = 0; L < 6; L++) {
        const int Cin = cins[L], Cout = couts[L];
        const int rounds = Cin >> 4, nM16 = Cout >> 4;
        const int n = 9 * Cin * Cout;
        const float* w = ws[L];
        __half* wf = wfb + ofs;
        for (int i = tid0; i < n; i += stride) {
            int h = i & 7, lane = (i >> 3) & 31;
            int rest = i >> 8;
            int r = rest % rounds;
            rest /= rounds;
            int m16 = rest % nM16;
            int t = rest / nM16;
            int pair = h >> 1, lo = h & 1;
            int row = (lane >> 2) + (pair & 1) * 8;
            int ci = r * 16 + (lane & 3) * 2 + (pair >> 1) * 8 + lo;
            int cco = m16 * 16 + row;
            wf[i] = __float2half_rn(w[((size_t)cco * Cin + ci) * 9 + t]);
        }
        ofs += n;
    }
}

// icomp + hole/valid L1 partial sums
__global__ void comp_l1_k(const float* __restrict__ igt,
                          const float* __restrict__ iout,
                          const float* __restrict__ mask) {
    const int n = BN * 3 * 512 * 512;
    const int hw = 512 * 512;
    float h = 0.f, v = 0.f;
    for (int i = blockIdx.x * blockDim.x + threadIdx.x; i < n;
         i += gridDim.x * blockDim.x) {
        int pix = i % hw;
        int b = (i / hw) / 3;
        float m = (mask[b * hw + pix] != 0.0f) ? 1.0f : 0.0f;
        float gt = igt[i], ot = iout[i];
        float d = ot - gt;
        h += fabsf((1.0f - m) * d);
        v += fabsf(m * d);
        g_comp[i] = (m == 1.0f) ? gt : ot;
    }
    warp_atomic(&g_acc[0], h);
    warp_atomic(&g_acc[1], v);
}

// ---------- FFMA2 conv layer 1 (Cin=3, fp32 NCHW in, fp16 NHWC out) ----------
__global__ __launch_bounds__(256, 3) void conv1_k(
    const float* __restrict__ in0, const float* __restrict__ in1,
    const float* __restrict__ in2,
    const float* __restrict__ wT, const float* __restrict__ bias,
    __half* __restrict__ out, int Cin, int Cout, int Hh, int Ww) {
    __shared__ __align__(16) float s_in[CI_T][18][20];
    __shared__ __align__(16) float s_w[CI_T][9][32];

    const int nCoT = Cout >> 5;
    const int coT = blockIdx.z % nCoT;
    const int be = blockIdx.z / nCoT;
    const int x0 = blockIdx.x * 16, y0 = blockIdx.y * 16;
    const int tid = threadIdx.x;
    const int p = tid & 63;
    const int g = tid >> 6;
    const int px = (p & 7) * 2, py = (p >> 3) * 2;
    const int g8 = g * 8;
    const size_t HW = (size_t)Hh * Ww;

    int s = be >> 1;
    const float* sp = (s == 0) ? in0 : ((s == 1) ? in1 : in2);
    const float* inB = sp + (size_t)(be & 1) * Cin * HW;

    unsigned long long acc[4][4];
    #pragma unroll
    for (int c = 0; c < 4; c++)
        #pragma unroll
        for (int q = 0; q < 4; q++) acc[c][q] = 0ull;

    const int rounds = (Cin + CI_T - 1) / CI_T;
    for (int r = 0; r < rounds; r++) {
        const int c0 = r * CI_T;
        for (int idx = tid; idx < CI_T * 324; idx += 256) {
            int q = idx / 324, rr = idx - q * 324;
            int iy = rr / 18, ix = rr - iy * 18;
            int ci = c0 + q;
            int gy = y0 + iy - 1, gx = x0 + ix - 1;
            float v = 0.f;
            if (ci < Cin && gy >= 0 && gy < Hh && gx >= 0 && gx < Ww)
                v = inB[(size_t)ci * HW + gy * Ww + gx];
            s_in[q][iy][ix] = v;
        }
        for (int idx = tid; idx < CI_T * 288; idx += 256) {
            int co = idx & 31;
            int t = idx >> 5;
            int k = t % 9, q = t / 9;
            int ci = c0 + q;
            float v = 0.f;
            if (ci < Cin) v = wT[((size_t)ci * 9 + k) * Cout + coT * 32 + co];
            s_w[q][k][co] = v;
        }
        __syncthreads();

        #pragma unroll 2
        for (int q = 0; q < CI_T; q++) {
            unsigned long long xx[4][4];
            #pragma unroll
            for (int dy = 0; dy < 4; dy++) {
                float2 a = *(const float2*)&s_in[q][py + dy][px];
                float2 b = *(const float2*)&s_in[q][py + dy][px + 2];
                xx[dy][0] = pk2(a.x, a.x);
                xx[dy][1] = pk2(a.y, a.y);
                xx[dy][2] = pk2(b.x, b.x);
                xx[dy][3] = pk2(b.y, b.y);
            }
            #pragma unroll
            for (int ky = 0; ky < 3; ky++)
                #pragma unroll
                for (int kx = 0; kx < 3; kx++) {
                    const int k = ky * 3 + kx;
                    float2 wa = *(const float2*)&s_w[q][k][g8];
                    float2 wb = *(const float2*)&s_w[q][k][g8 + 2];
                    float2 wc = *(const float2*)&s_w[q][k][g8 + 4];
                    float2 wd = *(const float2*)&s_w[q][k][g8 + 6];
                    unsigned long long w0 = pk2(wa.x, wa.y);
                    unsigned long long w1 = pk2(wb.x, wb.y);
                    unsigned long long w2 = pk2(wc.x, wc.y);
                    unsigned long long w3 = pk2(wd.x, wd.y);
                    #pragma unroll
                    for (int sy = 0; sy < 2; sy++)
                        #pragma unroll
                        for (int sx = 0; sx < 2; sx++) {
                            unsigned long long xf = xx[sy + ky][sx + kx];
                            const int pid = sy * 2 + sx;
                            acc[0][pid] = fma_x2(xf, w0, acc[0][pid]);
                            acc[1][pid] = fma_x2(xf, w1, acc[1][pid]);
                            acc[2][pid] = fma_x2(xf, w2, acc[2][pid]);
                            acc[3][pid] = fma_x2(xf, w3, acc[3][pid]);
                        }
                }
        }
        __syncthreads();
    }

    const int coBase = coT * 32 + g8;
    float bb[8];
    #pragma unroll
    for (int j = 0; j < 8; j++) bb[j] = bias[coBase + j];
    #pragma unroll
    for (int sy = 0; sy < 2; sy++)
        #pragma unroll
        for (int sx = 0; sx < 2; sx++) {
            int y = y0 + py + sy, x = x0 + px + sx;
            const int pid = sy * 2 + sx;
            union { uint4 u; __half2 h[4]; } pk;
            #pragma unroll
            for (int cp = 0; cp < 4; cp++) {
                float lo, hi;
                upk(acc[cp][pid], lo, hi);
                pk.h[cp] = __floats2half2_rn(fmaxf(lo + bb[2 * cp], 0.f),
                                             fmaxf(hi + bb[2 * cp + 1], 0.f));
            }
            *(uint4*)&out[((size_t)(be * Hh + y) * Ww + x) * Cout + coBase] = pk.u;
        }
}

// ---------- fp16 mma conv, co-tile 64 x (8y x 16x), 2 CTAs/SM (layers 2-7) ----
// Staging addresses hoisted out of the round loop; cp.async.cg (L1 bypass).
#define ACT64_H 4320   // halves per buffer (180 cells * 24)
__global__ __launch_bounds__(256, 2) void conv_mma64_k(
    const __half* __restrict__ in, const __half* __restrict__ wf,
    const float* __restrict__ bias, __half* __restrict__ out,
    int Cin, int Cout, int Hh, int Ww) {
    __shared__ __align__(16) __half sh[8704];   // max(2*4320, 64*136)

    const int nCoT = Cout >> 6;
    const int nM16 = Cout >> 4;
    const int coT = blockIdx.z % nCoT;
    const int be = blockIdx.z / nCoT;
    const int x0 = blockIdx.x * 16, y0 = blockIdx.y * 8;
    const int tid = threadIdx.x, wid = tid >> 5, lane = tid & 31;
    const int warp_m = wid >> 2, warp_n = wid & 3;
    const int rounds = Cin >> 4;

    float acc[2][4][4];
    #pragma unroll
    for (int mf = 0; mf < 2; mf++)
        #pragma unroll
        for (int nf = 0; nf < 4; nf++)
            #pragma unroll
            for (int q = 0; q < 4; q++) acc[mf][nf][q] = 0.f;

    const uint32_t sxb = smem_u32(sh);
    const int l7 = lane & 7, qd = lane >> 3;
    const int b_xx = ((qd >> 1) & 1) * 8 + l7;
    const int b_k = (qd & 1) * 8;
    uint32_t bRel[2];
    #pragma unroll
    for (int j = 0; j < 2; j++)
        bRel[j] = (uint32_t)((((2 * warp_n + j) * 18 + b_xx) * 24 + b_k) * 2);

    // ---- precompute staging tuples (<=2 per thread), constant over rounds ----
    const __half* sSrc[2];
    uint32_t sDst[2];
    int sOk[2];
    #pragma unroll
    for (int it = 0; it < 2; it++) {
        int idx = tid + it * 256;
        int cell = idx >> 1, hh = idx & 1;
        int yy = cell / 18, xx = cell - yy * 18;
        int gy = y0 + yy - 1, gx = x0 + xx - 1;
        int ok = (idx < 360) && gy >= 0 && gy < Hh && gx >= 0 && gx < Ww;
        sOk[it] = ok;
        sSrc[it] = ok ? &in[((size_t)(be * Hh + gy) * Ww + gx) * Cin + hh * 8] : in;
        sDst[it] = (uint32_t)((cell * 24 + hh * 8) * 2);
    }
    const int has2 = (tid < 104);

    // weight A-frag base: o(t, r) = wBase + t*tapStride + r*256 (in halves)
    const size_t tapStride = (size_t)nM16 * rounds * 256;
    const __half* wBase = wf + ((size_t)(coT * 4 + warp_m * 2) * rounds) * 256 +
                          (size_t)lane * 8;
    const size_t a1Off = (size_t)rounds * 256;

    // stage round 0
    {
        cp16cg(sxb + sDst[0], sSrc[0], sOk[0] ? 16 : 0);
        if (has2) cp16cg(sxb + sDst[1], sSrc[1], sOk[1] ? 16 : 0);
        asm volatile("cp.async.commit_group;");
    }

    for (int r = 0; r < rounds; r++) {
        asm volatile("cp.async.wait_group 0;");
        __syncthreads();
        if (r + 1 < rounds) {
            const int hOff = (r + 1) << 4;   // halves into the ci dimension
            const uint32_t dbase = sxb + (uint32_t)(((r + 1) & 1) * ACT64_H * 2);
            cp16cg(dbase + sDst[0], sSrc[0] + hOff, sOk[0] ? 16 : 0);
            if (has2) cp16cg(dbase + sDst[1], sSrc[1] + hOff, sOk[1] ? 16 : 0);
            asm volatile("cp.async.commit_group;");
        }

        const uint32_t bufB = sxb + (uint32_t)((r & 1) * ACT64_H * 2);
        const __half* wRound = wBase + (size_t)r * 256;
        #pragma unroll
        for (int t = 0; t < 9; t++) {
            const int dy = t / 3, dx = t - dy * 3;
            const uint32_t toff = (uint32_t)((dy * 18 + dx) * 48);
            uint32_t a0[4], a1[4];
            {
                const __half* wp = wRound + (size_t)t * tapStride;
                uint4 v = *(const uint4*)wp;
                a0[0] = v.x; a0[1] = v.y; a0[2] = v.z; a0[3] = v.w;
                v = *(const uint4*)(wp + a1Off);
                a1[0] = v.x; a1[1] = v.y; a1[2] = v.z; a1[3] = v.w;
            }
            #pragma unroll
            for (int j = 0; j < 2; j++) {
                uint32_t b[4];
                ldm4(b, bufB + bRel[j] + toff);
                const int nb = j * 2;
                mma16(acc[0][nb], a0, b[0], b[1]);
                mma16(acc[1][nb], a1, b[0], b[1]);
                mma16(acc[0][nb + 1], a0, b[2], b[3]);
                mma16(acc[1][nb + 1], a1, b[2], b[3]);
            }
        }
        __syncthreads();
    }

    // epilogue: bias+relu -> smem [64co][136] -> NHWC fp16
    #pragma unroll
    for (int mf = 0; mf < 2; mf++) {
        const int c0l = warp_m * 32 + mf * 16 + (lane >> 2);
        const float bb0 = bias[coT * 64 + c0l];
        const float bb1 = bias[coT * 64 + c0l + 8];
        #pragma unroll
        for (int nf = 0; nf < 4; nf++) {
            int px = (2 * warp_n + (nf >> 1)) * 16 + (nf & 1) * 8 + (lane & 3) * 2;
            *(__half2*)&sh[c0l * 136 + px] =
                __floats2half2_rn(fmaxf(acc[mf][nf][0] + bb0, 0.f),
                                  fmaxf(acc[mf][nf][1] + bb0, 0.f));
            *(__half2*)&sh[(c0l + 8) * 136 + px] =
                __floats2half2_rn(fmaxf(acc[mf][nf][2] + bb1, 0.f),
                                  fmaxf(acc[mf][nf][3] + bb1, 0.f));
        }
    }
    __syncthreads();
    {
        const int px = tid >> 1, ch = (tid & 1) * 32;
        const int yy = px >> 4, xx = px & 15;
        __half* base = out + ((size_t)(be * Hh + y0 + yy) * Ww + (x0 + xx)) * Cout +
                       coT * 64 + ch;
        #pragma unroll
        for (int k = 0; k < 4; k++) {
            union { uint4 u; __half h[8]; } pk;
            #pragma unroll
            for (int j = 0; j < 8; j++) pk.h[j] = sh[(ch + 8 * k + j) * 136 + px];
            *(uint4*)&base[8 * k] = pk.u;
        }
    }
}

// 2x2 maxpool fp16 NHWC -> fp16 NHWC
__global__ void pool16_k(const __half* __restrict__ in, __half* __restrict__ out,
                         int total8, int Ho, int Wo, int C) {
    const int C8 = C >> 3;
    for (int i = blockIdx.x * blockDim.x + threadIdx.x; i < total8;
         i += gridDim.x * blockDim.x) {
        int c8 = i % C8;
        int t = i / C8;
        int x = t % Wo;
        t /= Wo;
        int y = t % Ho;
        int be = t / Ho;
        const __half* p =
            in + ((size_t)(be * 2 * Ho + 2 * y) * (2 * Wo) + 2 * x) * C + c8 * 8;
        union { uint4 u; __half2 h[4]; } a, b, c, d, rr;
        a.u = *(const uint4*)p;
        b.u = *(const uint4*)(p + C);
        c.u = *(const uint4*)(p + (size_t)2 * Wo * C);
        d.u = *(const uint4*)(p + (size_t)2 * Wo * C + C);
        #pragma unroll
        for (int j = 0; j < 4; j++)
            rr.h[j] = __hmax2(__hmax2(a.h[j], b.h[j]), __hmax2(c.h[j], d.h[j]));
        *(uint4*)&out[(size_t)i * 8] = rr.u;
    }
}

// NHWC fp16 -> NCHW fp16 pool planes (for perc + style)
__global__ void nhwc2nchw16_k(const __half* __restrict__ in,
                              __half* __restrict__ out,
                              int HWp, int C, int SZlevel) {
    __shared__ __half tl[32][34];
    const int px0 = blockIdx.x * 32, c0 = blockIdx.y * 32, be = blockIdx.z;
    const int tx = threadIdx.x, ty = threadIdx.y;
    for (int r = ty; r < 32; r += 8)
        tl[r][tx] = in[((size_t)be * HWp + px0 + r) * C + c0 + tx];
    __syncthreads();
    const int s = be >> 1, b = be & 1;
    __half* ob = out + (size_t)s * SZlevel + (size_t)b * C * HWp;
    for (int r = ty; r < 32; r += 8)
        ob[(size_t)(c0 + r) * HWp + px0 + tx] = tl[tx][r];
}

// perceptual: sum |out-gt| + |comp-gt| over fp16 planes -> g_acc[2]
__global__ void perc_sum16_k(const __half* __restrict__ aout,
                             const __half* __restrict__ agt,
                             const __half* __restrict__ acomp, int n8) {
    float s = 0.f;
    for (int i = blockIdx.x * blockDim.x + threadIdx.x; i < n8;
         i += gridDim.x * blockDim.x) {
        union { uint4 u; __half2 h[4]; } o, g, c;
        o.u = *(const uint4*)&aout[(size_t)i * 8];
        g.u = *(const uint4*)&agt[(size_t)i * 8];
        c.u = *(const uint4*)&acomp[(size_t)i * 8];
        #pragma unroll
        for (int j = 0; j < 4; j++) {
            float2 fo = __half22float2(o.h[j]);
            float2 fg = __half22float2(g.h[j]);
            float2 fc = __half22float2(c.h[j]);
            s += fabsf(fo.x - fg.x) + fabsf(fc.x - fg.x);
            s += fabsf(fo.y - fg.y) + fabsf(fc.y - fg.y);
        }
    }
    warp_atomic(&g_acc[2], s);
}

// ---------- style via fp16 mma: G = X^T X per (b,c) plane ----------
__global__ __launch_bounds__(256) void style_mma_k(
    const __half* __restrict__ Xout, const __half* __restrict__ Xgt,
    const __half* __restrict__ Xcomp, int Hs, int Ws, double scale) {
    __shared__ __align__(16) __half st[6][16][40];
    __shared__ float red[2][8];
    const int bc = blockIdx.z;
    const size_t off = (size_t)bc * Hs * Ws;
    const __half* P[3] = {Xout + off, Xgt + off, Xcomp + off};
    const int v0 = blockIdx.x * 32, w0 = blockIdx.y * 32;
    const int tid = threadIdx.x, wid = tid >> 5, lane = tid & 31;
    const int warp_m = wid >> 2, warp_n = wid & 3;
    const int l7 = lane & 7, qd = lane >> 3;

    float cO[4] = {0, 0, 0, 0}, cG[4] = {0, 0, 0, 0}, cC[4] = {0, 0, 0, 0};

    const uint32_t stb = smem_u32(st);
    uint32_t aA[3], bA[3];
    #pragma unroll
    for (int s = 0; s < 3; s++) {
        aA[s] = stb + (uint32_t)(((s * 16 + (qd >> 1) * 8 + l7) * 40 +
                                  warp_m * 16 + (qd & 1) * 8) * 2);
        bA[s] = stb + (uint32_t)((((3 + s) * 16 + (qd & 1) * 8 + l7) * 40 +
                                  warp_n * 8) * 2);
    }

    for (int h0 = 0; h0 < Hs; h0 += 16) {
        for (int idx = tid; idx < 384; idx += 256) {
            int t = idx >> 6, rr = idx & 63;
            int kk = rr >> 2, c8 = (rr & 3) * 8;
            const __half* src =
                P[t % 3] + (size_t)(h0 + kk) * Ws + ((t < 3) ? w0 : v0) + c8;
            cp16cg(stb + (uint32_t)(((t * 16 + kk) * 40 + c8) * 2), src, 16);
        }
        asm volatile("cp.async.commit_group;");
        asm volatile("cp.async.wait_group 0;");
        __syncthreads();

        uint32_t a[4], b[2];
        ldm4t(a, aA[0]); ldm2t(b, bA[0]); mma16(cO, a, b[0], b[1]);
        ldm4t(a, aA[1]); ldm2t(b, bA[1]); mma16(cG, a, b[0], b[1]);
        ldm4t(a, aA[2]); ldm2t(b, bA[2]); mma16(cC, a, b[0], b[1]);
        __syncthreads();
    }

    float sO = 0.f, sC = 0.f;
    #pragma unroll
    for (int q = 0; q < 4; q++) {
        sO += fabsf(cO[q] - cG[q]);
        sC += fabsf(cC[q] - cG[q]);
    }
    #pragma unroll
    for (int o = 16; o > 0; o >>= 1) {
        sO += __shfl_down_sync(0xffffffffu, sO, o);
        sC += __shfl_down_sync(0xffffffffu, sC, o);
    }
    if (lane == 0) { red[0][wid] = sO; red[1][wid] = sC; }
    __syncthreads();
    if (tid == 0) {
        double tO = 0.0, tC = 0.0;
        #pragma unroll
        for (int j = 0; j < 8; j++) { tO += red[0][j]; tC += red[1][j]; }
        atomicAdd(&g_acc[3], scale * tO);
        atomicAdd(&g_acc[4], scale * tC);
    }
}

__global__ void finalize_k(float* out) {
    if (threadIdx.x == 0 && blockIdx.x == 0) {
        const double N = 3.0 * 512.0 * 512.0 * (double)BN;
        const double Nigt = (double)SZ1;
        double l = (double)BN * g_acc[0] / N
                 + g_acc[1] / N
                 + g_acc[2] / Nigt
                 + g_acc[3]
                 + g_acc[4];
        out[0] = (float)l;
    }
}

// ---------------- host launcher ----------------
extern "C" void kernel_launch(void* const* d_in, const int* in_sizes, int n_in,
                              void* d_out, int out_size) {
    (void)in_sizes; (void)n_in; (void)out_size;
    const float* igt  = (const float*)d_in[0];
    const float* iout = (const float*)d_in[1];
    const float* mask = (const float*)d_in[2];
    const float* w[7];
    const float* bb[7];
    for (int i = 0; i < 7; i++) {
        w[i]  = (const float*)d_in[3 + 2 * i];
        bb[i] = (const float*)d_in[4 + 2 * i];
    }

    __half *hA, *hB, *hp, *w16b, *q1, *q2, *q3;
    float *comp, *wT1;
    cudaGetSymbolAddress((void**)&hA, g_hA);
    cudaGetSymbolAddress((void**)&hB, g_hB);
    cudaGetSymbolAddress((void**)&hp, g_hp);
    cudaGetSymbolAddress((void**)&comp, g_comp);
    cudaGetSymbolAddress((void**)&wT1, g_wT1);
    cudaGetSymbolAddress((void**)&w16b, g_w16);
    cudaGetSymbolAddress((void**)&q1, g_q1);
    cudaGetSymbolAddress((void**)&q2, g_q2);
    cudaGetSymbolAddress((void**)&q3, g_q3);

    const int cins[7]  = {3, 64, 64, 128, 128, 256, 256};
    const int couts[7] = {64, 64, 128, 128, 256, 256, 256};
    __half* w16[7];
    size_t ofs = 0;
    for (int i = 1; i < 7; i++) {
        w16[i] = w16b + ofs;
        ofs += (size_t)cins[i] * couts[i] * 9;
    }

    __half* Q1[3] = {q1, q1 + SZ1, q1 + 2 * (size_t)SZ1};
    __half* Q2[3] = {q2, q2 + SZ2, q2 + 2 * (size_t)SZ2};
    __half* Q3[3] = {q3, q3 + SZ3, q3 + 2 * (size_t)SZ3};

    // 1: weight prep (+ acc zero)
    wprep_k<<<256, 256>>>(w[0], w[1], w[2], w[3], w[4], w[5], w[6], wT1, w16b);
    // 2: comp + L1
    comp_l1_k<<<1024, 256>>>(igt, iout, mask);
    // 3: layer 1 (FFMA2): -> hA
    conv1_k<<<dim3(32, 32, 6 * 2), 256>>>(igt, iout, comp, wT1, bb[0],
                                          hA, 3, 64, 512, 512);
    // 4: layer 2: hA -> hB
    conv_mma64_k<<<dim3(32, 64, 6), 256>>>(hA, w16[1], bb[1], hB, 64, 64, 512, 512);
    // 5: pool 1: hB -> hp
    pool16_k<<<8192, 256>>>(hB, hp, 6 * 256 * 256 * 8, 256, 256, 64);
    // 6: layer 3: hp -> hA   <- ncu -s 5 -c 1 captures this
    conv_mma64_k<<<dim3(16, 32, 12), 256>>>(hp, w16[2], bb[2], hA, 64, 128, 256, 256);
    // 7: transpose pool-1 (hp still live) -> q1
    nhwc2nchw16_k<<<dim3(2048, 2, 6), dim3(32, 8)>>>(hp, q1, 65536, 64, SZ1);
    // 8: layer 4: hA -> hB
    conv_mma64_k<<<dim3(16, 32, 12), 256>>>(hA, w16[3], bb[3], hB, 128, 128, 256, 256);
    // 9: pool 2: hB -> hp
    pool16_k<<<4096, 256>>>(hB, hp, 6 * 128 * 128 * 16, 128, 128, 128);
    // 10: layer 5: hp -> hA
    conv_mma64_k<<<dim3(8, 16, 24), 256>>>(hp, w16[4], bb[4], hA, 128, 256, 128, 128);
    // 11: transpose pool-2 (hp still live) -> q2
    nhwc2nchw16_k<<<dim3(512, 4, 6), dim3(32, 8)>>>(hp, q2, 16384, 128, SZ2);
    // 12: layer 6: hA -> hB
    conv_mma64_k<<<dim3(8, 16, 24), 256>>>(hA, w16[5], bb[5], hB, 256, 256, 128, 128);
    // 13: layer 7: hB -> hA
    conv_mma64_k<<<dim3(8, 16, 24), 256>>>(hB, w16[6], bb[6], hA, 256, 256, 128, 128);
    // 14: pool 3: hA -> hp
    pool16_k<<<2048, 256>>>(hA, hp, 6 * 64 * 64 * 32, 64, 64, 256);
    // 15: transpose pool-3 -> q3
    nhwc2nchw16_k<<<dim3(128, 8, 6), dim3(32, 8)>>>(hp, q3, 4096, 256, SZ3);

    perc_sum16_k<<<2048, 256>>>(Q1[1], Q1[0], Q1[2], SZ1 / 8);
    perc_sum16_k<<<1024, 256>>>(Q2[1], Q2[0], Q2[2], SZ2 / 8);
    perc_sum16_k<<<512, 256>>>(Q3[1], Q3[0], Q3[2], SZ3 / 8);

    style_mma_k<<<dim3(8, 8, BN * 64), 256>>>(Q1[1], Q1[0], Q1[2], 256, 256,
                                              1.0 / (4194304.0 * 4096.0));
    style_mma_k<<<dim3(4, 4, BN * 128), 256>>>(Q2[1], Q2[0], Q2[2], 128, 128,
                                               1.0 / (2097152.0 * 16384.0));
    style_mma_k<<<dim3(2, 2, BN * 256), 256>>>(Q3[1], Q3[0], Q3[2], 64, 64,
                                               1.0 / (1048576.0 * 65536.0));

    finalize_k<<<1, 32>>>((float*)d_out);
}

// round 16
// speedup vs baseline: 6.0867x; 1.0371x over previous
#include <cuda_runtime.h>
#include <cuda_fp16.h>
#include <math.h>
#include <stdint.h>

#define BN 2
#define CI_T 8

// ---------------- static scratch (no allocations allowed) ----------------
__device__ __half g_hA[6 * 64 * 512 * 512];      // NHWC fp16 ping
__device__ __half g_hB[6 * 64 * 512 * 512];      // NHWC fp16 pong
__device__ __half g_hp[6 * 64 * 256 * 256];      // NHWC fp16 pooled
__device__ float  g_comp[BN * 3 * 512 * 512];
__device__ float  g_wT1[1728];                   // layer-1 weights (fp32)
__device__ __half g_w16[1732608];                // layers 2-7 weights, A-fragment order

#define SZ1 (BN * 64 * 256 * 256)
#define SZ2 (BN * 128 * 128 * 128)
#define SZ3 (BN * 256 * 64 * 64)
// fp16 NCHW pool planes per stream: [gt, out, comp]
__device__ __half g_q1[3][SZ1];
__device__ __half g_q2[3][SZ2];
__device__ __half g_q3[3][SZ3];

__device__ double g_acc[8];

// ---------------- helpers ----------------
__device__ __forceinline__ unsigned long long pk2(float a, float b) {
    unsigned long long r;
    asm("mov.b64 %0, {%1, %2};" : "=l"(r) : "f"(a), "f"(b));
    return r;
}
__device__ __forceinline__ unsigned long long fma_x2(unsigned long long a,
                                                     unsigned long long b,
                                                     unsigned long long c) {
    unsigned long long d;
    asm("fma.rn.f32x2 %0, %1, %2, %3;" : "=l"(d) : "l"(a), "l"(b), "l"(c));
    return d;
}
__device__ __forceinline__ void upk(unsigned long long v, float& lo, float& hi) {
    asm("mov.b64 {%0, %1}, %2;" : "=f"(lo), "=f"(hi) : "l"(v));
}
__device__ __forceinline__ uint32_t smem_u32(const void* p) {
    return (uint32_t)__cvta_generic_to_shared(p);
}
__device__ __forceinline__ void ldm4(uint32_t* r, uint32_t addr) {
    asm volatile("ldmatrix.sync.aligned.m8n8.x4.shared.b16 {%0,%1,%2,%3}, [%4];"
                 : "=r"(r[0]), "=r"(r[1]), "=r"(r[2]), "=r"(r[3]) : "r"(addr));
}
__device__ __forceinline__ void ldm4t(uint32_t* r, uint32_t addr) {
    asm volatile("ldmatrix.sync.aligned.m8n8.x4.trans.shared.b16 {%0,%1,%2,%3}, [%4];"
                 : "=r"(r[0]), "=r"(r[1]), "=r"(r[2]), "=r"(r[3]) : "r"(addr));
}
__device__ __forceinline__ void ldm2t(uint32_t* r, uint32_t addr) {
    asm volatile("ldmatrix.sync.aligned.m8n8.x2.trans.shared.b16 {%0,%1}, [%2];"
                 : "=r"(r[0]), "=r"(r[1]) : "r"(addr));
}
__device__ __forceinline__ void mma16(float* c, const uint32_t* a,
                                      uint32_t b0, uint32_t b1) {
    asm volatile(
        "mma.sync.aligned.m16n8k16.row.col.f32.f16.f16.f32 "
        "{%0,%1,%2,%3}, {%4,%5,%6,%7}, {%8,%9}, {%0,%1,%2,%3};"
        : "+f"(c[0]), "+f"(c[1]), "+f"(c[2]), "+f"(c[3])
        : "r"(a[0]), "r"(a[1]), "r"(a[2]), "r"(a[3]), "r"(b0), "r"(b1));
}
// cp.async with L1 bypass (.cg)
__device__ __forceinline__ void cp16cg(uint32_t dst, const void* src, int srcsize) {
    asm volatile("cp.async.cg.shared.global [%0], [%1], 16, %2;"
                 :: "r"(dst), "l"(src), "r"(srcsize));
}
__device__ __forceinline__ void warp_atomic(double* dst, float v) {
    #pragma unroll
    for (int o = 16; o > 0; o >>= 1) v += __shfl_down_sync(0xffffffffu, v, o);
    if ((threadIdx.x & 31) == 0) atomicAdd(dst, (double)v);
}

// ---------------- kernels ----------------

// weight prep: zero accs, layer-1 fp32 transpose, layers 2-7 A-fragment pack
__global__ void wprep_k(const float* __restrict__ w0, const float* __restrict__ w1,
                        const float* __restrict__ w2, const float* __restrict__ w3,
                        const float* __restrict__ w4, const float* __restrict__ w5,
                        const float* __restrict__ w6,
                        float* __restrict__ wT1, __half* __restrict__ wfb) {
    const int tid0 = blockIdx.x * blockDim.x + threadIdx.x;
    const int stride = gridDim.x * blockDim.x;
    if (tid0 < 8) g_acc[tid0] = 0.0;
    for (int i = tid0; i < 1728; i += stride) {
        int co = i & 63;
        int t = i >> 6;
        int k = t % 9, ci = t / 9;
        wT1[i] = w0[(co * 3 + ci) * 9 + k];
    }
    const float* ws[6] = {w1, w2, w3, w4, w5, w6};
    const int cins[6] = {64, 64, 128, 128, 256, 256};
    const int couts[6] = {64, 128, 128, 256, 256, 256};
    size_t ofs = 0;
    for (int L = 0; L < 6; L++) {
        const int Cin = cins[L], Cout = couts[L];
        const int rounds = Cin >> 4, nM16 = Cout >> 4;
        const int n = 9 * Cin * Cout;
        const float* w = ws[L];
        __half* wf = wfb + ofs;
        for (int i = tid0; i < n; i += stride) {
            int h = i & 7, lane = (i >> 3) & 31;
            int rest = i >> 8;
            int r = rest % rounds;
            rest /= rounds;
            int m16 = rest % nM16;
            int t = rest / nM16;
            int pair = h >> 1, lo = h & 1;
            int row = (lane >> 2) + (pair & 1) * 8;
            int ci = r * 16 + (lane & 3) * 2 + (pair >> 1) * 8 + lo;
            int cco = m16 * 16 + row;
            wf[i] = __float2half_rn(w[((size_t)cco * Cin + ci) * 9 + t]);
        }
        ofs += n;
    }
}

// icomp + hole/valid L1 partial sums
__global__ void comp_l1_k(const float* __restrict__ igt,
                          const float* __restrict__ iout,
                          const float* __restrict__ mask) {
    const int n = BN * 3 * 512 * 512;
    const int hw = 512 * 512;
    float h = 0.f, v = 0.f;
    for (int i = blockIdx.x * blockDim.x + threadIdx.x; i < n;
         i += gridDim.x * blockDim.x) {
        int pix = i % hw;
        int b = (i / hw) / 3;
        float m = (mask[b * hw + pix] != 0.0f) ? 1.0f : 0.0f;
        float gt = igt[i], ot = iout[i];
        float d = ot - gt;
        h += fabsf((1.0f - m) * d);
        v += fabsf(m * d);
        g_comp[i] = (m == 1.0f) ? gt : ot;
    }
    warp_atomic(&g_acc[0], h);
    warp_atomic(&g_acc[1], v);
}

// ---------- FFMA2 conv layer 1 (Cin=3, fp32 NCHW in, fp16 NHWC out) ----------
__global__ __launch_bounds__(256, 3) void conv1_k(
    const float* __restrict__ in0, const float* __restrict__ in1,
    const float* __restrict__ in2,
    const float* __restrict__ wT, const float* __restrict__ bias,
    __half* __restrict__ out, int Cin, int Cout, int Hh, int Ww) {
    __shared__ __align__(16) float s_in[CI_T][18][20];
    __shared__ __align__(16) float s_w[CI_T][9][32];

    const int nCoT = Cout >> 5;
    const int coT = blockIdx.z % nCoT;
    const int be = blockIdx.z / nCoT;
    const int x0 = blockIdx.x * 16, y0 = blockIdx.y * 16;
    const int tid = threadIdx.x;
    const int p = tid & 63;
    const int g = tid >> 6;
    const int px = (p & 7) * 2, py = (p >> 3) * 2;
    const int g8 = g * 8;
    const size_t HW = (size_t)Hh * Ww;

    int s = be >> 1;
    const float* sp = (s == 0) ? in0 : ((s == 1) ? in1 : in2);
    const float* inB = sp + (size_t)(be & 1) * Cin * HW;

    unsigned long long acc[4][4];
    #pragma unroll
    for (int c = 0; c < 4; c++)
        #pragma unroll
        for (int q = 0; q < 4; q++) acc[c][q] = 0ull;

    const int rounds = (Cin + CI_T - 1) / CI_T;
    for (int r = 0; r < rounds; r++) {
        const int c0 = r * CI_T;
        for (int idx = tid; idx < CI_T * 324; idx += 256) {
            int q = idx / 324, rr = idx - q * 324;
            int iy = rr / 18, ix = rr - iy * 18;
            int ci = c0 + q;
            int gy = y0 + iy - 1, gx = x0 + ix - 1;
            float v = 0.f;
            if (ci < Cin && gy >= 0 && gy < Hh && gx >= 0 && gx < Ww)
                v = inB[(size_t)ci * HW + gy * Ww + gx];
            s_in[q][iy][ix] = v;
        }
        for (int idx = tid; idx < CI_T * 288; idx += 256) {
            int co = idx & 31;
            int t = idx >> 5;
            int k = t % 9, q = t / 9;
            int ci = c0 + q;
            float v = 0.f;
            if (ci < Cin) v = wT[((size_t)ci * 9 + k) * Cout + coT * 32 + co];
            s_w[q][k][co] = v;
        }
        __syncthreads();

        #pragma unroll 2
        for (int q = 0; q < CI_T; q++) {
            unsigned long long xx[4][4];
            #pragma unroll
            for (int dy = 0; dy < 4; dy++) {
                float2 a = *(const float2*)&s_in[q][py + dy][px];
                float2 b = *(const float2*)&s_in[q][py + dy][px + 2];
                xx[dy][0] = pk2(a.x, a.x);
                xx[dy][1] = pk2(a.y, a.y);
                xx[dy][2] = pk2(b.x, b.x);
                xx[dy][3] = pk2(b.y, b.y);
            }
            #pragma unroll
            for (int ky = 0; ky < 3; ky++)
                #pragma unroll
                for (int kx = 0; kx < 3; kx++) {
                    const int k = ky * 3 + kx;
                    float2 wa = *(const float2*)&s_w[q][k][g8];
                    float2 wb = *(const float2*)&s_w[q][k][g8 + 2];
                    float2 wc = *(const float2*)&s_w[q][k][g8 + 4];
                    float2 wd = *(const float2*)&s_w[q][k][g8 + 6];
                    unsigned long long w0 = pk2(wa.x, wa.y);
                    unsigned long long w1 = pk2(wb.x, wb.y);
                    unsigned long long w2 = pk2(wc.x, wc.y);
                    unsigned long long w3 = pk2(wd.x, wd.y);
                    #pragma unroll
                    for (int sy = 0; sy < 2; sy++)
                        #pragma unroll
                        for (int sx = 0; sx < 2; sx++) {
                            unsigned long long xf = xx[sy + ky][sx + kx];
                            const int pid = sy * 2 + sx;
                            acc[0][pid] = fma_x2(xf, w0, acc[0][pid]);
                            acc[1][pid] = fma_x2(xf, w1, acc[1][pid]);
                            acc[2][pid] = fma_x2(xf, w2, acc[2][pid]);
                            acc[3][pid] = fma_x2(xf, w3, acc[3][pid]);
                        }
                }
        }
        __syncthreads();
    }

    const int coBase = coT * 32 + g8;
    float bb[8];
    #pragma unroll
    for (int j = 0; j < 8; j++) bb[j] = bias[coBase + j];
    #pragma unroll
    for (int sy = 0; sy < 2; sy++)
        #pragma unroll
        for (int sx = 0; sx < 2; sx++) {
            int y = y0 + py + sy, x = x0 + px + sx;
            const int pid = sy * 2 + sx;
            union { uint4 u; __half2 h[4]; } pk;
            #pragma unroll
            for (int cp = 0; cp < 4; cp++) {
                float lo, hi;
                upk(acc[cp][pid], lo, hi);
                pk.h[cp] = __floats2half2_rn(fmaxf(lo + bb[2 * cp], 0.f),
                                             fmaxf(hi + bb[2 * cp + 1], 0.f));
            }
            *(uint4*)&out[((size_t)(be * Hh + y) * Ww + x) * Cout + coBase] = pk.u;
        }
}

// ---------- fp16 mma conv, co-tile 64 x (8y x 32x), 2 CTAs/SM (layers 2-7) ----
// Wider warp tile (32co x 64px) -> 1.5 L1 wavefronts per MMA (was 2.0).
// Hoisted staging tuples + cp.async.cg keep regs ~115 so 2 CTAs/SM hold.
#define ACTW_H 8160   // halves per buffer (340 cells * 24)
__global__ __launch_bounds__(256, 2) void conv_mma64w_k(
    const __half* __restrict__ in, const __half* __restrict__ wf,
    const float* __restrict__ bias, __half* __restrict__ out,
    int Cin, int Cout, int Hh, int Ww) {
    __shared__ __align__(16) __half sh[16896];   // max(2*8160=16320, 64*264=16896)

    const int nCoT = Cout >> 6;
    const int nM16 = Cout >> 4;
    const int coT = blockIdx.z % nCoT;
    const int be = blockIdx.z / nCoT;
    const int x0 = blockIdx.x * 32, y0 = blockIdx.y * 8;
    const int tid = threadIdx.x, wid = tid >> 5, lane = tid & 31;
    const int warp_m = wid >> 2, warp_n = wid & 3;
    const int rounds = Cin >> 4;

    float acc[2][8][4];
    #pragma unroll
    for (int mf = 0; mf < 2; mf++)
        #pragma unroll
        for (int nf = 0; nf < 8; nf++)
            #pragma unroll
            for (int q = 0; q < 4; q++) acc[mf][nf][q] = 0.f;

    const uint32_t sxb = smem_u32(sh);
    const int l7 = lane & 7, qd = lane >> 3;
    const int b_xx = ((qd >> 1) & 1) * 8 + l7;
    const int b_k = (qd & 1) * 8;
    uint32_t bRel[2][2];
    #pragma unroll
    for (int j = 0; j < 2; j++)
        #pragma unroll
        for (int xg = 0; xg < 2; xg++)
            bRel[j][xg] = (uint32_t)(
                (((2 * warp_n + j) * 34 + xg * 16 + b_xx) * 24 + b_k) * 2);

    // ---- hoisted staging tuples: 680 ops, <=3 per thread ----
    const __half* sSrc[3];
    uint32_t sDst[3];
    int sOk[3];
    #pragma unroll
    for (int it = 0; it < 3; it++) {
        int idx = tid + it * 256;
        int cell = idx >> 1, hh = idx & 1;
        int yy = cell / 34, xx = cell - yy * 34;
        int gy = y0 + yy - 1, gx = x0 + xx - 1;
        int ok = (idx < 680) && gy >= 0 && gy < Hh && gx >= 0 && gx < Ww;
        sOk[it] = ok;
        sSrc[it] = ok ? &in[((size_t)(be * Hh + gy) * Ww + gx) * Cin + hh * 8] : in;
        sDst[it] = (idx < 680) ? (uint32_t)((cell * 24 + hh * 8) * 2) : 0u;
    }
    const int has3 = (tid < 168);

    // weight A-frag addressing
    const size_t tapStride = (size_t)nM16 * rounds * 256;
    const __half* wBase = wf + ((size_t)(coT * 4 + warp_m * 2) * rounds) * 256 +
                          (size_t)lane * 8;
    const size_t a1Off = (size_t)rounds * 256;

    // stage round 0
    {
        cp16cg(sxb + sDst[0], sSrc[0], sOk[0] ? 16 : 0);
        cp16cg(sxb + sDst[1], sSrc[1], sOk[1] ? 16 : 0);
        if (has3) cp16cg(sxb + sDst[2], sSrc[2], sOk[2] ? 16 : 0);
        asm volatile("cp.async.commit_group;");
    }

    for (int r = 0; r < rounds; r++) {
        asm volatile("cp.async.wait_group 0;");
        __syncthreads();
        if (r + 1 < rounds) {
            const int hOff = (r + 1) << 4;
            const uint32_t dbase = sxb + (uint32_t)(((r + 1) & 1) * ACTW_H * 2);
            cp16cg(dbase + sDst[0], sSrc[0] + hOff, sOk[0] ? 16 : 0);
            cp16cg(dbase + sDst[1], sSrc[1] + hOff, sOk[1] ? 16 : 0);
            if (has3) cp16cg(dbase + sDst[2], sSrc[2] + hOff, sOk[2] ? 16 : 0);
            asm volatile("cp.async.commit_group;");
        }

        const uint32_t bufB = sxb + (uint32_t)((r & 1) * ACTW_H * 2);
        const __half* wRound = wBase + (size_t)r * 256;
        #pragma unroll
        for (int t = 0; t < 9; t++) {
            const int dy = t / 3, dx = t - dy * 3;
            const uint32_t toff = (uint32_t)((dy * 34 + dx) * 48);
            uint32_t a0[4], a1[4];
            {
                const __half* wp = wRound + (size_t)t * tapStride;
                uint4 v = *(const uint4*)wp;
                a0[0] = v.x; a0[1] = v.y; a0[2] = v.z; a0[3] = v.w;
                v = *(const uint4*)(wp + a1Off);
                a1[0] = v.x; a1[1] = v.y; a1[2] = v.z; a1[3] = v.w;
            }
            #pragma unroll
            for (int j = 0; j < 2; j++)
                #pragma unroll
                for (int xg = 0; xg < 2; xg++) {
                    uint32_t b[4];
                    ldm4(b, bufB + bRel[j][xg] + toff);
                    const int nb = j * 4 + xg * 2;
                    mma16(acc[0][nb], a0, b[0], b[1]);
                    mma16(acc[1][nb], a1, b[0], b[1]);
                    mma16(acc[0][nb + 1], a0, b[2], b[3]);
                    mma16(acc[1][nb + 1], a1, b[2], b[3]);
                }
        }
        __syncthreads();
    }

    // epilogue: bias+relu -> smem [64co][264] -> NHWC fp16
    #pragma unroll
    for (int mf = 0; mf < 2; mf++) {
        const int c0l = warp_m * 32 + mf * 16 + (lane >> 2);
        const float bb0 = bias[coT * 64 + c0l];
        const float bb1 = bias[coT * 64 + c0l + 8];
        #pragma unroll
        for (int nf = 0; nf < 8; nf++) {
            int px = (2 * warp_n + (nf >> 2)) * 32 + ((nf >> 1) & 1) * 16 +
                     (nf & 1) * 8 + (lane & 3) * 2;
            *(__half2*)&sh[c0l * 264 + px] =
                __floats2half2_rn(fmaxf(acc[mf][nf][0] + bb0, 0.f),
                                  fmaxf(acc[mf][nf][1] + bb0, 0.f));
            *(__half2*)&sh[(c0l + 8) * 264 + px] =
                __floats2half2_rn(fmaxf(acc[mf][nf][2] + bb1, 0.f),
                                  fmaxf(acc[mf][nf][3] + bb1, 0.f));
        }
    }
    __syncthreads();
    {
        const int px = tid;
        const int yy = px >> 5, xx = px & 31;
        __half* base = out + ((size_t)(be * Hh + y0 + yy) * Ww + (x0 + xx)) * Cout +
                       coT * 64;
        #pragma unroll
        for (int k = 0; k < 8; k++) {
            union { uint4 u; __half h[8]; } pk;
            #pragma unroll
            for (int j = 0; j < 8; j++) pk.h[j] = sh[(8 * k + j) * 264 + px];
            *(uint4*)&base[8 * k] = pk.u;
        }
    }
}

// 2x2 maxpool fp16 NHWC -> fp16 NHWC
__global__ void pool16_k(const __half* __restrict__ in, __half* __restrict__ out,
                         int total8, int Ho, int Wo, int C) {
    const int C8 = C >> 3;
    for (int i = blockIdx.x * blockDim.x + threadIdx.x; i < total8;
         i += gridDim.x * blockDim.x) {
        int c8 = i % C8;
        int t = i / C8;
        int x = t % Wo;
        t /= Wo;
        int y = t % Ho;
        int be = t / Ho;
        const __half* p =
            in + ((size_t)(be * 2 * Ho + 2 * y) * (2 * Wo) + 2 * x) * C + c8 * 8;
        union { uint4 u; __half2 h[4]; } a, b, c, d, rr;
        a.u = *(const uint4*)p;
        b.u = *(const uint4*)(p + C);
        c.u = *(const uint4*)(p + (size_t)2 * Wo * C);
        d.u = *(const uint4*)(p + (size_t)2 * Wo * C + C);
        #pragma unroll
        for (int j = 0; j < 4; j++)
            rr.h[j] = __hmax2(__hmax2(a.h[j], b.h[j]), __hmax2(c.h[j], d.h[j]));
        *(uint4*)&out[(size_t)i * 8] = rr.u;
    }
}

// NHWC fp16 -> NCHW fp16 pool planes (for perc + style)
__global__ void nhwc2nchw16_k(const __half* __restrict__ in,
                              __half* __restrict__ out,
                              int HWp, int C, int SZlevel) {
    __shared__ __half tl[32][34];
    const int px0 = blockIdx.x * 32, c0 = blockIdx.y * 32, be = blockIdx.z;
    const int tx = threadIdx.x, ty = threadIdx.y;
    for (int r = ty; r < 32; r += 8)
        tl[r][tx] = in[((size_t)be * HWp + px0 + r) * C + c0 + tx];
    __syncthreads();
    const int s = be >> 1, b = be & 1;
    __half* ob = out + (size_t)s * SZlevel + (size_t)b * C * HWp;
    for (int r = ty; r < 32; r += 8)
        ob[(size_t)(c0 + r) * HWp + px0 + tx] = tl[tx][r];
}

// perceptual: sum |out-gt| + |comp-gt| over fp16 planes -> g_acc[2]
__global__ void perc_sum16_k(const __half* __restrict__ aout,
                             const __half* __restrict__ agt,
                             const __half* __restrict__ acomp, int n8) {
    float s = 0.f;
    for (int i = blockIdx.x * blockDim.x + threadIdx.x; i < n8;
         i += gridDim.x * blockDim.x) {
        union { uint4 u; __half2 h[4]; } o, g, c;
        o.u = *(const uint4*)&aout[(size_t)i * 8];
        g.u = *(const uint4*)&agt[(size_t)i * 8];
        c.u = *(const uint4*)&acomp[(size_t)i * 8];
        #pragma unroll
        for (int j = 0; j < 4; j++) {
            float2 fo = __half22float2(o.h[j]);
            float2 fg = __half22float2(g.h[j]);
            float2 fc = __half22float2(c.h[j]);
            s += fabsf(fo.x - fg.x) + fabsf(fc.x - fg.x);
            s += fabsf(fo.y - fg.y) + fabsf(fc.y - fg.y);
        }
    }
    warp_atomic(&g_acc[2], s);
}

// ---------- style via fp16 mma: G = X^T X per (b,c) plane ----------
__global__ __launch_bounds__(256) void style_mma_k(
    const __half* __restrict__ Xout, const __half* __restrict__ Xgt,
    const __half* __restrict__ Xcomp, int Hs, int Ws, double scale) {
    __shared__ __align__(16) __half st[6][16][40];
    __shared__ float red[2][8];
    const int bc = blockIdx.z;
    const size_t off = (size_t)bc * Hs * Ws;
    const __half* P[3] = {Xout + off, Xgt + off, Xcomp + off};
    const int v0 = blockIdx.x * 32, w0 = blockIdx.y * 32;
    const int tid = threadIdx.x, wid = tid >> 5, lane = tid & 31;
    const int warp_m = wid >> 2, warp_n = wid & 3;
    const int l7 = lane & 7, qd = lane >> 3;

    float cO[4] = {0, 0, 0, 0}, cG[4] = {0, 0, 0, 0}, cC[4] = {0, 0, 0, 0};

    const uint32_t stb = smem_u32(st);
    uint32_t aA[3], bA[3];
    #pragma unroll
    for (int s = 0; s < 3; s++) {
        aA[s] = stb + (uint32_t)(((s * 16 + (qd >> 1) * 8 + l7) * 40 +
                                  warp_m * 16 + (qd & 1) * 8) * 2);
        bA[s] = stb + (uint32_t)((((3 + s) * 16 + (qd & 1) * 8 + l7) * 40 +
                                  warp_n * 8) * 2);
    }

    for (int h0 = 0; h0 < Hs; h0 += 16) {
        for (int idx = tid; idx < 384; idx += 256) {
            int t = idx >> 6, rr = idx & 63;
            int kk = rr >> 2, c8 = (rr & 3) * 8;
            const __half* src =
                P[t % 3] + (size_t)(h0 + kk) * Ws + ((t < 3) ? w0 : v0) + c8;
            cp16cg(stb + (uint32_t)(((t * 16 + kk) * 40 + c8) * 2), src, 16);
        }
        asm volatile("cp.async.commit_group;");
        asm volatile("cp.async.wait_group 0;");
        __syncthreads();

        uint32_t a[4], b[2];
        ldm4t(a, aA[0]); ldm2t(b, bA[0]); mma16(cO, a, b[0], b[1]);
        ldm4t(a, aA[1]); ldm2t(b, bA[1]); mma16(cG, a, b[0], b[1]);
        ldm4t(a, aA[2]); ldm2t(b, bA[2]); mma16(cC, a, b[0], b[1]);
        __syncthreads();
    }

    float sO = 0.f, sC = 0.f;
    #pragma unroll
    for (int q = 0; q < 4; q++) {
        sO += fabsf(cO[q] - cG[q]);
        sC += fabsf(cC[q] - cG[q]);
    }
    #pragma unroll
    for (int o = 16; o > 0; o >>= 1) {
        sO += __shfl_down_sync(0xffffffffu, sO, o);
        sC += __shfl_down_sync(0xffffffffu, sC, o);
    }
    if (lane == 0) { red[0][wid] = sO; red[1][wid] = sC; }
    __syncthreads();
    if (tid == 0) {
        double tO = 0.0, tC = 0.0;
        #pragma unroll
        for (int j = 0; j < 8; j++) { tO += red[0][j]; tC += red[1][j]; }
        atomicAdd(&g_acc[3], scale * tO);
        atomicAdd(&g_acc[4], scale * tC);
    }
}

__global__ void finalize_k(float* out) {
    if (threadIdx.x == 0 && blockIdx.x == 0) {
        const double N = 3.0 * 512.0 * 512.0 * (double)BN;
        const double Nigt = (double)SZ1;
        double l = (double)BN * g_acc[0] / N
                 + g_acc[1] / N
                 + g_acc[2] / Nigt
                 + g_acc[3]
                 + g_acc[4];
        out[0] = (float)l;
    }
}

// ---------------- host launcher ----------------
extern "C" void kernel_launch(void* const* d_in, const int* in_sizes, int n_in,
                              void* d_out, int out_size) {
    (void)in_sizes; (void)n_in; (void)out_size;
    const float* igt  = (const float*)d_in[0];
    const float* iout = (const float*)d_in[1];
    const float* mask = (const float*)d_in[2];
    const float* w[7];
    const float* bb[7];
    for (int i = 0; i < 7; i++) {
        w[i]  = (const float*)d_in[3 + 2 * i];
        bb[i] = (const float*)d_in[4 + 2 * i];
    }

    __half *hA, *hB, *hp, *w16b, *q1, *q2, *q3;
    float *comp, *wT1;
    cudaGetSymbolAddress((void**)&hA, g_hA);
    cudaGetSymbolAddress((void**)&hB, g_hB);
    cudaGetSymbolAddress((void**)&hp, g_hp);
    cudaGetSymbolAddress((void**)&comp, g_comp);
    cudaGetSymbolAddress((void**)&wT1, g_wT1);
    cudaGetSymbolAddress((void**)&w16b, g_w16);
    cudaGetSymbolAddress((void**)&q1, g_q1);
    cudaGetSymbolAddress((void**)&q2, g_q2);
    cudaGetSymbolAddress((void**)&q3, g_q3);

    const int cins[7]  = {3, 64, 64, 128, 128, 256, 256};
    const int couts[7] = {64, 64, 128, 128, 256, 256, 256};
    __half* w16[7];
    size_t ofs = 0;
    for (int i = 1; i < 7; i++) {
        w16[i] = w16b + ofs;
        ofs += (size_t)cins[i] * couts[i] * 9;
    }

    __half* Q1[3] = {q1, q1 + SZ1, q1 + 2 * (size_t)SZ1};
    __half* Q2[3] = {q2, q2 + SZ2, q2 + 2 * (size_t)SZ2};
    __half* Q3[3] = {q3, q3 + SZ3, q3 + 2 * (size_t)SZ3};

    // 1: weight prep (+ acc zero)
    wprep_k<<<256, 256>>>(w[0], w[1], w[2], w[3], w[4], w[5], w[6], wT1, w16b);
    // 2: comp + L1
    comp_l1_k<<<1024, 256>>>(igt, iout, mask);
    // 3: layer 1 (FFMA2): -> hA
    conv1_k<<<dim3(32, 32, 6 * 2), 256>>>(igt, iout, comp, wT1, bb[0],
                                          hA, 3, 64, 512, 512);
    // 4: layer 2: hA -> hB
    conv_mma64w_k<<<dim3(16, 64, 6), 256>>>(hA, w16[1], bb[1], hB, 64, 64, 512, 512);
    // 5: pool 1: hB -> hp
    pool16_k<<<8192, 256>>>(hB, hp, 6 * 256 * 256 * 8, 256, 256, 64);
    // 6: layer 3: hp -> hA   <- ncu -s 5 -c 1 captures this
    conv_mma64w_k<<<dim3(8, 32, 12), 256>>>(hp, w16[2], bb[2], hA, 64, 128, 256, 256);
    // 7: transpose pool-1 (hp still live) -> q1
    nhwc2nchw16_k<<<dim3(2048, 2, 6), dim3(32, 8)>>>(hp, q1, 65536, 64, SZ1);
    // 8: layer 4: hA -> hB
    conv_mma64w_k<<<dim3(8, 32, 12), 256>>>(hA, w16[3], bb[3], hB, 128, 128, 256, 256);
    // 9: pool 2: hB -> hp
    pool16_k<<<4096, 256>>>(hB, hp, 6 * 128 * 128 * 16, 128, 128, 128);
    // 10: layer 5: hp -> hA
    conv_mma64w_k<<<dim3(4, 16, 24), 256>>>(hp, w16[4], bb[4], hA, 128, 256, 128, 128);
    // 11: transpose pool-2 (hp still live) -> q2
    nhwc2nchw16_k<<<dim3(512, 4, 6), dim3(32, 8)>>>(hp, q2, 16384, 128, SZ2);
    // 12: layer 6: hA -> hB
    conv_mma64w_k<<<dim3(4, 16, 24), 256>>>(hA, w16[5], bb[5], hB, 256, 256, 128, 128);
    // 13: layer 7: hB -> hA
    conv_mma64w_k<<<dim3(4, 16, 24), 256>>>(hB, w16[6], bb[6], hA, 256, 256, 128, 128);
    // 14: pool 3: hA -> hp
    pool16_k<<<2048, 256>>>(hA, hp, 6 * 64 * 64 * 32, 64, 64, 256);
    // 15: transpose pool-3 -> q3
    nhwc2nchw16_k<<<dim3(128, 8, 6), dim3(32, 8)>>>(hp, q3, 4096, 256, SZ3);

    perc_sum16_k<<<2048, 256>>>(Q1[1], Q1[0], Q1[2], SZ1 / 8);
    perc_sum16_k<<<1024, 256>>>(Q2[1], Q2[0], Q2[2], SZ2 / 8);
    perc_sum16_k<<<512, 256>>>(Q3[1], Q3[0], Q3[2], SZ3 / 8);

    style_mma_k<<<dim3(8, 8, BN * 64), 256>>>(Q1[1], Q1[0], Q1[2], 256, 256,
                                              1.0 / (4194304.0 * 4096.0));
    style_mma_k<<<dim3(4, 4, BN * 128), 256>>>(Q2[1], Q2[0], Q2[2], 128, 128,
                                               1.0 / (2097152.0 * 16384.0));
    style_mma_k<<<dim3(2, 2, BN * 256), 256>>>(Q3[1], Q3[0], Q3[2], 64, 64,
                                               1.0 / (1048576.0 * 65536.0));

    finalize_k<<<1, 32>>>((float*)d_out);
}